// round 5
// baseline (speedup 1.0000x reference)
#include <cuda_runtime.h>
#include <cuda_bf16.h>
#include <math.h>

// Problem constants
#define B_   4
#define CIN  32
#define C_   64
#define H_   128
#define W_   128
#define HW   16384
#define DG_  8
#define CPG  8
#define KK_  9
#define OCM  216   // DG*3*K*K
#define C9   576   // C*9

// ---------------- scratch (device globals; no allocation allowed) ----------
__device__ float g_x1 [B_*C_ *HW];   // conv0 out
__device__ float g_om [B_*OCM*HW];   // offset/mask conv out
__device__ float g_dcn[B_*C_ *HW];   // lrelu(deform conv) == pre == x
__device__ float g_col[2*C9 *HW];    // im2col for a PAIR of batches (L2-resident)
__device__ float g_x0 [B_*C_ *HW];   // a0 conv out
__device__ float g_x1d[B_*C_ *HW];   // depthwise out (+eca folded in)
__device__ float g_out[B_*C_ *HW];   // dynamic-filter out (lrelu'd)
__device__ float g_s  [B_*C_];       // channel means of x0
__device__ float g_eca[B_*C_];       // eca values

// ---------------- 1: conv0 1x1, 32->64 : 4px x 16co tiling ------------------
__global__ void __launch_bounds__(256, 2) conv0_k(
        const float* __restrict__ x, const float* __restrict__ w,
        const float* __restrict__ bias) {
    __shared__ __align__(16) float ws[CIN*C_];   // [ci][co]
    int tid = threadIdx.x;
    int quad = tid & 63, cg = tid >> 6;
    for (int i = tid; i < C_*CIN; i += 256) {
        int ci = i >> 6, co = i & 63;
        ws[ci*C_ + co] = w[co*CIN + ci];
    }
    __syncthreads();
    int b = blockIdx.y;
    int p0 = blockIdx.x*256 + quad*4;
    const float* xb = x + (size_t)b*CIN*HW + p0;
    float acc[64];
#pragma unroll
    for (int c = 0; c < 16; c++) {
        float bv = __ldg(bias + cg*16 + c);
        acc[c*4+0] = bv; acc[c*4+1] = bv; acc[c*4+2] = bv; acc[c*4+3] = bv;
    }
    for (int ci = 0; ci < CIN; ci++) {
        float4 v = *(const float4*)(xb + (size_t)ci*HW);
        const float4* w4 = (const float4*)(ws + ci*C_ + cg*16);
#pragma unroll
        for (int q = 0; q < 4; q++) {
            float4 wv = w4[q];
            float wr[4] = {wv.x, wv.y, wv.z, wv.w};
#pragma unroll
            for (int r = 0; r < 4; r++) {
                float wc = wr[r];
                float* a = acc + (q*4+r)*4;
                a[0] += wc*v.x; a[1] += wc*v.y; a[2] += wc*v.z; a[3] += wc*v.w;
            }
        }
    }
    float* ob = g_x1 + (size_t)b*C_*HW + p0;
#pragma unroll
    for (int c = 0; c < 16; c++)
        *(float4*)(ob + (size_t)(cg*16+c)*HW) =
            make_float4(acc[c*4+0], acc[c*4+1], acc[c*4+2], acc[c*4+3]);
}

// ---------------- 2: offset/mask conv 3x3, 32->216 : 2px x 24co -------------
#define OMCH 24
__global__ void __launch_bounds__(256, 2) offm_k(
        const float* __restrict__ in, const float* __restrict__ w,
        const float* __restrict__ bias) {
    __shared__ __align__(16) float ws[CIN*KK_*OMCH];   // [ci][k][j]
    int tid = threadIdx.x;
    int b = blockIdx.y;
    int co0 = blockIdx.z*OMCH;
    int p0 = blockIdx.x*512 + tid*2;
    int h = p0 >> 7, wq = p0 & 127;
    for (int i = tid; i < OMCH*CIN*KK_; i += 256) {
        int ci = i/(KK_*OMCH);
        int k  = (i/OMCH)%KK_;
        int j  = i%OMCH;
        ws[i] = w[((co0+j)*CIN + ci)*KK_ + k];
    }
    __syncthreads();
    const float* ib = in + (size_t)b*CIN*HW;
    float acc[OMCH*2];
#pragma unroll
    for (int j = 0; j < OMCH; j++) {
        float bv = __ldg(bias + co0 + j);
        acc[j*2+0] = bv; acc[j*2+1] = bv;
    }
    for (int ci = 0; ci < CIN; ci++) {
        const float* ic = ib + (size_t)ci*HW;
        float v[12];   // [ky][xx] cols wq-1..wq+2
#pragma unroll
        for (int ky = 0; ky < 3; ky++) {
            int hy = h + ky - 1;
            bool oy = (hy >= 0 && hy < H_);
            const float* icr = ic + hy*W_;
#pragma unroll
            for (int xx = 0; xx < 4; xx++) {
                int wx = wq - 1 + xx;
                v[ky*4+xx] = (oy && wx >= 0 && wx < W_) ? __ldg(icr + wx) : 0.f;
            }
        }
#pragma unroll
        for (int k = 0; k < KK_; k++) {
            int ky = k/3, kx = k%3;
            float v0 = v[ky*4+kx], v1 = v[ky*4+kx+1];
            const float4* w4 = (const float4*)(ws + (ci*KK_ + k)*OMCH);
#pragma unroll
            for (int q = 0; q < 6; q++) {
                float4 wv = w4[q];
                float wr[4] = {wv.x, wv.y, wv.z, wv.w};
#pragma unroll
                for (int r = 0; r < 4; r++) {
                    float wc = wr[r];
                    acc[(q*4+r)*2+0] += wc*v0;
                    acc[(q*4+r)*2+1] += wc*v1;
                }
            }
        }
    }
    float* ob = g_om + (size_t)b*OCM*HW + p0;
#pragma unroll
    for (int j = 0; j < OMCH; j++)
        *(float2*)(ob + (size_t)(co0+j)*HW) = make_float2(acc[j*2+0], acc[j*2+1]);
}

// ---------------- 3: deform im2col (bilinear, modulated), batch pair -------
__global__ void __launch_bounds__(256, 2) col_k(int b0) {
    int tid = threadIdx.x;
    int p = blockIdx.x*256 + tid;
    int gk = blockIdx.y;                 // g*9+k, 0..71
    int g = gk/9, k = gk%9;
    int bl = blockIdx.z;                 // local batch 0/1
    int b = b0 + bl;
    int h = p >> 7, wq = p & 127;
    const float* omb = g_om + (size_t)b*OCM*HW;
    float dy = omb[(       g*9+k)*HW + p];
    float dx = omb[( 72 +  g*9+k)*HW + p];
    float mk = omb[(144 +  g*9+k)*HW + p];
    mk = 1.f/(1.f + expf(-mk));
    float py = dy + (float)(k/3) + (float)h - 1.f;
    float px = dx + (float)(k%3) + (float)wq - 1.f;
    float fy = floorf(py), fx = floorf(px);
    int y0 = (int)fy, x0 = (int)fx;
    float wy = py - fy, wx = px - fx;
    float w00 = (1.f-wy)*(1.f-wx)*mk;
    float w01 = (1.f-wy)*wx*mk;
    float w10 = wy*(1.f-wx)*mk;
    float w11 = wy*wx*mk;
    bool iy0 = (y0 >= 0 && y0 < H_);
    bool iy1 = (y0+1 >= 0 && y0+1 < H_);
    bool ix0 = (x0 >= 0 && x0 < W_);
    bool ix1 = (x0+1 >= 0 && x0+1 < W_);
    bool v00 = iy0 && ix0, v01 = iy0 && ix1, v10 = iy1 && ix0, v11 = iy1 && ix1;
    int i00 = y0*W_ + x0;
    const float* xb = g_x1 + (size_t)b*C_*HW + (size_t)g*CPG*HW;
    float* cb = g_col + (size_t)bl*C9*HW + (size_t)(g*CPG*KK_ + k)*HW + p;
#pragma unroll
    for (int c = 0; c < CPG; c++) {
        const float* xc = xb + c*HW;
        float s = 0.f;
        if (v00) s += w00*__ldg(xc + i00);
        if (v01) s += w01*__ldg(xc + i00 + 1);
        if (v10) s += w10*__ldg(xc + i00 + W_);
        if (v11) s += w11*__ldg(xc + i00 + W_ + 1);
        cb[(size_t)c*KK_*HW] = s;
    }
}

// ---------------- 4: dcn GEMM (64x576) + lrelu : 4px x 16co, batch pair ----
__global__ void __launch_bounds__(256, 2) dcngemm_k(
        const float* __restrict__ w, const float* __restrict__ bias, int b0) {
    __shared__ __align__(16) float ws[64*C_];     // [j][co]
    int tid = threadIdx.x;
    int quad = tid & 63, cg = tid >> 6;
    int bl = blockIdx.y;
    int b = b0 + bl;
    int p0 = blockIdx.x*256 + quad*4;
    const float* cb = g_col + (size_t)bl*C9*HW + p0;
    float acc[64];
#pragma unroll
    for (int c = 0; c < 16; c++) {
        float bv = __ldg(bias + cg*16 + c);
        acc[c*4+0] = bv; acc[c*4+1] = bv; acc[c*4+2] = bv; acc[c*4+3] = bv;
    }
    for (int jc = 0; jc < C9/64; jc++) {
        __syncthreads();
        for (int i = tid; i < C_*64; i += 256) {
            int j = i >> 6, co = i & 63;
            ws[i] = w[co*C9 + jc*64 + j];
        }
        __syncthreads();
#pragma unroll 4
        for (int j = 0; j < 64; j++) {
            float4 v = *(const float4*)(cb + (size_t)(jc*64+j)*HW);
            const float4* w4 = (const float4*)(ws + j*C_ + cg*16);
#pragma unroll
            for (int q = 0; q < 4; q++) {
                float4 wv = w4[q];
                float wr[4] = {wv.x, wv.y, wv.z, wv.w};
#pragma unroll
                for (int r = 0; r < 4; r++) {
                    float wc = wr[r];
                    float* a = acc + (q*4+r)*4;
                    a[0] += wc*v.x; a[1] += wc*v.y; a[2] += wc*v.z; a[3] += wc*v.w;
                }
            }
        }
    }
    float* ob = g_dcn + (size_t)b*C_*HW + p0;
#pragma unroll
    for (int c = 0; c < 16; c++) {
        float4 o;
        o.x = acc[c*4+0]; o.y = acc[c*4+1]; o.z = acc[c*4+2]; o.w = acc[c*4+3];
        o.x = (o.x >= 0.f) ? o.x : 0.2f*o.x;
        o.y = (o.y >= 0.f) ? o.y : 0.2f*o.y;
        o.z = (o.z >= 0.f) ? o.z : 0.2f*o.z;
        o.w = (o.w >= 0.f) ? o.w : 0.2f*o.w;
        *(float4*)(ob + (size_t)(cg*16+c)*HW) = o;
    }
}

// ---------------- shared body: conv3x3 64->64 : 4px x 16co -----------------
template <int FUSE>
__device__ __forceinline__ void conv3x3_v2(const float* __restrict__ ib,
                                           const float* __restrict__ w,
                                           const float* __restrict__ bias,
                                           const float* __restrict__ pre,
                                           float* __restrict__ outp,
                                           float* ws) {
    int tid = threadIdx.x;
    int quad = tid & 63, cq = tid >> 6;
    int p0 = blockIdx.x*256 + quad*4;
    int h = p0 >> 7, wq = p0 & 127;
    float acc[64];
#pragma unroll
    for (int c = 0; c < 16; c++) {
        float bv = __ldg(bias + cq*16 + c);
        acc[c*4+0] = bv; acc[c*4+1] = bv; acc[c*4+2] = bv; acc[c*4+3] = bv;
    }
    for (int cc = 0; cc < 8; cc++) {
        __syncthreads();
        for (int i = tid; i < 8*KK_*C_; i += 256) {
            int ci8 = i/(KK_*C_);
            int k   = (i/C_)%KK_;
            int co  = i & 63;
            ws[i] = w[((size_t)co*C_ + cc*8+ci8)*KK_ + k];
        }
        __syncthreads();
        for (int ci8 = 0; ci8 < 8; ci8++) {
            const float* ic = ib + (size_t)(cc*8+ci8)*HW;
            float v[18];   // [ky][xx] cols wq-1..wq+4
#pragma unroll
            for (int ky = 0; ky < 3; ky++) {
                int hy = h + ky - 1;
                bool oy = (hy >= 0 && hy < H_);
                const float* icr = ic + hy*W_;
#pragma unroll
                for (int xx = 0; xx < 6; xx++) {
                    int wx = wq - 1 + xx;
                    v[ky*6+xx] = (oy && wx >= 0 && wx < W_) ? __ldg(icr + wx) : 0.f;
                }
            }
#pragma unroll
            for (int k = 0; k < KK_; k++) {
                int ky = k/3, kx = k%3;
                const float4* w4 = (const float4*)(ws + (ci8*KK_+k)*C_ + cq*16);
                float v0 = v[ky*6+kx+0], v1 = v[ky*6+kx+1];
                float v2 = v[ky*6+kx+2], v3 = v[ky*6+kx+3];
#pragma unroll
                for (int q = 0; q < 4; q++) {
                    float4 wv = w4[q];
                    float wr[4] = {wv.x, wv.y, wv.z, wv.w};
#pragma unroll
                    for (int r = 0; r < 4; r++) {
                        float wc = wr[r];
                        float* a = acc + (q*4+r)*4;
                        a[0] += wc*v0; a[1] += wc*v1; a[2] += wc*v2; a[3] += wc*v3;
                    }
                }
            }
        }
    }
#pragma unroll
    for (int c = 0; c < 16; c++) {
        float4 o;
        o.x = acc[c*4+0]; o.y = acc[c*4+1]; o.z = acc[c*4+2]; o.w = acc[c*4+3];
        if (FUSE) {
            float4 pv = *(const float4*)(pre + (size_t)(cq*16+c)*HW + p0);
            o.x += 2.f*pv.x; o.y += 2.f*pv.y; o.z += 2.f*pv.z; o.w += 2.f*pv.w;
        }
        *(float4*)(outp + (size_t)(cq*16+c)*HW + p0) = o;
    }
}

// a0: g_dcn -> g_x0
__global__ void __launch_bounds__(256, 2) conv_a0_k(
        const float* __restrict__ w, const float* __restrict__ bias) {
    __shared__ __align__(16) float ws[8*KK_*C_];
    int b = blockIdx.y;
    conv3x3_v2<0>(g_dcn + (size_t)b*C_*HW, w, bias, nullptr,
                  g_x0 + (size_t)b*C_*HW, ws);
}

// fus: g_out -> d_out (+ 2*g_dcn)
__global__ void __launch_bounds__(256, 2) conv_fus_k(
        const float* __restrict__ w, const float* __restrict__ bias,
        float* __restrict__ out) {
    __shared__ __align__(16) float ws[8*KK_*C_];
    int b = blockIdx.y;
    conv3x3_v2<1>(g_out + (size_t)b*C_*HW, w, bias, g_dcn + (size_t)b*C_*HW,
                  out + (size_t)b*C_*HW, ws);
}

// ---------------- 6: depthwise 3x3 on g_x0 -> g_x1d (+eca) -----------------
__global__ void __launch_bounds__(256, 4) dw_k(
        const float* __restrict__ w, const float* __restrict__ bias) {
    int tid = threadIdx.x;
    int c = blockIdx.y, b = blockIdx.z;
    int p = blockIdx.x*256 + tid;
    int h = p >> 7, wq = p & 127;
    const float* ic = g_x0 + ((size_t)b*C_ + c)*HW;
    float acc = bias[c] + g_eca[b*C_ + c];
#pragma unroll
    for (int ky = 0; ky < 3; ky++) {
        int hy = h + ky - 1;
        bool oky = (hy >= 0 && hy < H_);
#pragma unroll
        for (int kx = 0; kx < 3; kx++) {
            int wx = wq + kx - 1;
            float v = (oky && wx >= 0 && wx < W_) ? __ldg(ic + hy*W_ + wx) : 0.f;
            acc += __ldg(w + c*KK_ + ky*3+kx)*v;
        }
    }
    g_x1d[((size_t)b*C_ + c)*HW + p] = acc;
}

// ---------------- 7: per-(b,c) mean of g_x0 --------------------------------
__global__ void mean_k() {
    __shared__ float sd[256];
    int bc = blockIdx.x;
    const float* ic = g_x0 + (size_t)bc*HW;
    float s = 0.f;
    for (int i = threadIdx.x; i < HW; i += 256) s += ic[i];
    sd[threadIdx.x] = s;
    __syncthreads();
    for (int st = 128; st > 0; st >>= 1) {
        if (threadIdx.x < st) sd[threadIdx.x] += sd[threadIdx.x+st];
        __syncthreads();
    }
    if (threadIdx.x == 0) g_s[bc] = sd[0]*(1.f/(float)HW);
}

// ---------------- 8: ECA 1D conv over channels -----------------------------
__global__ void eca_k(const float* __restrict__ w2, const float* __restrict__ b2) {
    int i = threadIdx.x;
    if (i >= B_*C_) return;
    int c = i & 63;
    float sm1 = (c > 0)  ? g_s[i-1] : 0.f;
    float s0  = g_s[i];
    float sp1 = (c < 63) ? g_s[i+1] : 0.f;
    g_eca[i] = w2[0]*sm1 + w2[1]*s0 + w2[2]*sp1 + b2[0];
}

// ---------------- 9: a3 1x1 (64->576) + dynamic filter + lrelu : 4px -------
__global__ void __launch_bounds__(256, 2) a3filt_k(
        const float* __restrict__ w, const float* __restrict__ bias) {
    __shared__ __align__(16) float ws[8*KK_*C_];   // [c8][k][ci]
    int tid = threadIdx.x;
    int b = blockIdx.y;
    int cc0 = blockIdx.z*2;
    int p0 = blockIdx.x*1024 + tid*4;
    int h = p0 >> 7, wq = p0 & 127;
    const float* xb  = g_x1d + (size_t)b*C_*HW + p0;
    const float* x0b = g_x0  + (size_t)b*C_*HW;
    float* ob = g_out + (size_t)b*C_*HW + p0;
    for (int cc = cc0; cc < cc0+2; cc++) {
        __syncthreads();
        for (int i = tid; i < 8*KK_*C_; i += 256) ws[i] = w[(size_t)cc*8*KK_*C_ + i];
        __syncthreads();
        for (int c8 = 0; c8 < 8; c8++) {
            int c = cc*8 + c8;
            float filt[36];   // [k][x]
#pragma unroll
            for (int k = 0; k < KK_; k++) {
                float bv = __ldg(bias + c*KK_ + k);
                filt[k*4+0] = bv; filt[k*4+1] = bv; filt[k*4+2] = bv; filt[k*4+3] = bv;
            }
#pragma unroll 4
            for (int q = 0; q < 16; q++) {
                float4 iv0 = *(const float4*)(xb + (size_t)(q*4+0)*HW);
                float4 iv1 = *(const float4*)(xb + (size_t)(q*4+1)*HW);
                float4 iv2 = *(const float4*)(xb + (size_t)(q*4+2)*HW);
                float4 iv3 = *(const float4*)(xb + (size_t)(q*4+3)*HW);
                const float4* w4 = (const float4*)(ws + (c8*KK_)*C_);
#pragma unroll
                for (int k = 0; k < KK_; k++) {
                    float4 wv = w4[k*16 + q];
                    float* f = filt + k*4;
                    f[0] += wv.x*iv0.x + wv.y*iv1.x + wv.z*iv2.x + wv.w*iv3.x;
                    f[1] += wv.x*iv0.y + wv.y*iv1.y + wv.z*iv2.y + wv.w*iv3.y;
                    f[2] += wv.x*iv0.z + wv.y*iv1.z + wv.z*iv2.z + wv.w*iv3.z;
                    f[3] += wv.x*iv0.w + wv.y*iv1.w + wv.z*iv2.w + wv.w*iv3.w;
                }
            }
            // apply 3x3 dynamic filter over x0[c]
            const float* ic = x0b + (size_t)c*HW;
            float v[18];
#pragma unroll
            for (int ky = 0; ky < 3; ky++) {
                int hy = h + ky - 1;
                bool oy = (hy >= 0 && hy < H_);
                const float* icr = ic + hy*W_;
#pragma unroll
                for (int xx = 0; xx < 6; xx++) {
                    int wx = wq - 1 + xx;
                    v[ky*6+xx] = (oy && wx >= 0 && wx < W_) ? __ldg(icr + wx) : 0.f;
                }
            }
            float o[4] = {0.f, 0.f, 0.f, 0.f};
#pragma unroll
            for (int k = 0; k < KK_; k++) {
                int ky = k/3, kx = k%3;
#pragma unroll
                for (int xx = 0; xx < 4; xx++)
                    o[xx] += filt[k*4+xx]*v[ky*6+kx+xx];
            }
            float4 r;
            r.x = (o[0] >= 0.f) ? o[0] : 0.2f*o[0];
            r.y = (o[1] >= 0.f) ? o[1] : 0.2f*o[1];
            r.z = (o[2] >= 0.f) ? o[2] : 0.2f*o[2];
            r.w = (o[3] >= 0.f) ? o[3] : 0.2f*o[3];
            *(float4*)(ob + (size_t)c*HW) = r;
        }
    }
}

// ---------------- launch ----------------------------------------------------
extern "C" void kernel_launch(void* const* d_in, const int* in_sizes, int n_in,
                              void* d_out, int out_size) {
    const float* x       = (const float*)d_in[0];
    const float* offset  = (const float*)d_in[1];
    const float* conv0_w = (const float*)d_in[2];
    const float* conv0_b = (const float*)d_in[3];
    const float* offm_w  = (const float*)d_in[4];
    const float* offm_b  = (const float*)d_in[5];
    const float* dcn_w   = (const float*)d_in[6];
    const float* dcn_b   = (const float*)d_in[7];
    const float* a0_w    = (const float*)d_in[8];
    const float* a0_b    = (const float*)d_in[9];
    const float* a1_w    = (const float*)d_in[10];
    const float* a1_b    = (const float*)d_in[11];
    const float* a2_w    = (const float*)d_in[12];
    const float* a2_b    = (const float*)d_in[13];
    const float* a3_w    = (const float*)d_in[14];
    const float* a3_b    = (const float*)d_in[15];
    const float* fus_w   = (const float*)d_in[16];
    const float* fus_b   = (const float*)d_in[17];
    float* out = (float*)d_out;

    dim3 gp(HW/256, B_);
    conv0_k  <<<gp, 256>>>(x, conv0_w, conv0_b);
    offm_k   <<<dim3(HW/512, B_, OCM/OMCH), 256>>>(offset, offm_w, offm_b);
    // deform conv in batch pairs so g_col (75MB) stays L2-resident
    for (int b0 = 0; b0 < B_; b0 += 2) {
        col_k    <<<dim3(HW/256, DG_*KK_, 2), 256>>>(b0);
        dcngemm_k<<<dim3(HW/256, 2), 256>>>(dcn_w, dcn_b, b0);
    }
    conv_a0_k<<<gp, 256>>>(a0_w, a0_b);
    mean_k   <<<B_*C_, 256>>>();
    eca_k    <<<1, 256>>>(a2_w, a2_b);
    dw_k     <<<dim3(HW/256, C_, B_), 256>>>(a1_w, a1_b);
    a3filt_k <<<dim3(HW/1024, B_, 4), 256>>>(a3_w, a3_b);
    conv_fus_k<<<gp, 256>>>(fus_w, fus_b, out);
}

// round 8
// speedup vs baseline: 1.2528x; 1.2528x over previous
#include <cuda_runtime.h>
#include <cuda_bf16.h>
#include <math.h>

// Problem constants
#define B_   4
#define CIN  32
#define C_   64
#define H_   128
#define W_   128
#define HW   16384
#define DG_  8
#define CPG  8
#define KK_  9
#define OCM  216   // DG*3*K*K
#define C9   576   // C*9

// ---------------- scratch (device globals; no allocation allowed) ----------
__device__ float g_x1 [B_*C_ *HW];   // conv0 out
__device__ float g_om [B_*OCM*HW];   // offset/mask conv out
__device__ float g_dcn[B_*C_ *HW];   // lrelu(deform conv) == pre == x
__device__ float g_col[B_*C9 *HW];   // deform im2col columns [b][j][p]
__device__ float g_wt [C9*C_];       // dcn weights transposed [j][co]
__device__ float g_x0 [B_*C_ *HW];   // a0 conv out
__device__ float g_x1d[B_*C_ *HW];   // depthwise out (+eca folded in)
__device__ float g_out[B_*C_ *HW];   // dynamic-filter out (lrelu'd)
__device__ float g_s  [B_*C_];       // channel means of x0
__device__ float g_eca[B_*C_];       // eca values

__device__ __forceinline__ unsigned f2tf32(float v) {
    unsigned t;
    asm("cvt.rna.tf32.f32 %0, %1;" : "=r"(t) : "f"(v));
    return t;
}

// ---------------- 1: conv0 1x1, 32->64 : 4px x 16co tiling ------------------
__global__ void __launch_bounds__(256, 2) conv0_k(
        const float* __restrict__ x, const float* __restrict__ w,
        const float* __restrict__ bias) {
    __shared__ __align__(16) float ws[CIN*C_];   // [ci][co]
    int tid = threadIdx.x;
    int quad = tid & 63, cg = tid >> 6;
    for (int i = tid; i < C_*CIN; i += 256) {
        int ci = i >> 6, co = i & 63;
        ws[ci*C_ + co] = w[co*CIN + ci];
    }
    __syncthreads();
    int b = blockIdx.y;
    int p0 = blockIdx.x*256 + quad*4;
    const float* xb = x + (size_t)b*CIN*HW + p0;
    float acc[64];
#pragma unroll
    for (int c = 0; c < 16; c++) {
        float bv = __ldg(bias + cg*16 + c);
        acc[c*4+0] = bv; acc[c*4+1] = bv; acc[c*4+2] = bv; acc[c*4+3] = bv;
    }
    for (int ci = 0; ci < CIN; ci++) {
        float4 v = *(const float4*)(xb + (size_t)ci*HW);
        const float4* w4 = (const float4*)(ws + ci*C_ + cg*16);
#pragma unroll
        for (int q = 0; q < 4; q++) {
            float4 wv = w4[q];
            float wr[4] = {wv.x, wv.y, wv.z, wv.w};
#pragma unroll
            for (int r = 0; r < 4; r++) {
                float wc = wr[r];
                float* a = acc + (q*4+r)*4;
                a[0] += wc*v.x; a[1] += wc*v.y; a[2] += wc*v.z; a[3] += wc*v.w;
            }
        }
    }
    float* ob = g_x1 + (size_t)b*C_*HW + p0;
#pragma unroll
    for (int c = 0; c < 16; c++)
        *(float4*)(ob + (size_t)(cg*16+c)*HW) =
            make_float4(acc[c*4+0], acc[c*4+1], acc[c*4+2], acc[c*4+3]);
}

// ---------------- 2: offset/mask conv 3x3, 32->216 : 2px x 24co -------------
#define OMCH 24
__global__ void __launch_bounds__(256, 2) offm_k(
        const float* __restrict__ in, const float* __restrict__ w,
        const float* __restrict__ bias) {
    __shared__ __align__(16) float ws[CIN*KK_*OMCH];   // [ci][k][j]
    int tid = threadIdx.x;
    int b = blockIdx.y;
    int co0 = blockIdx.z*OMCH;
    int p0 = blockIdx.x*512 + tid*2;
    int h = p0 >> 7, wq = p0 & 127;
    for (int i = tid; i < OMCH*CIN*KK_; i += 256) {
        int ci = i/(KK_*OMCH);
        int k  = (i/OMCH)%KK_;
        int j  = i%OMCH;
        ws[i] = w[((co0+j)*CIN + ci)*KK_ + k];
    }
    __syncthreads();
    const float* ib = in + (size_t)b*CIN*HW;
    float acc[OMCH*2];
#pragma unroll
    for (int j = 0; j < OMCH; j++) {
        float bv = __ldg(bias + co0 + j);
        acc[j*2+0] = bv; acc[j*2+1] = bv;
    }
    for (int ci = 0; ci < CIN; ci++) {
        const float* ic = ib + (size_t)ci*HW;
        float v[12];   // [ky][xx] cols wq-1..wq+2
#pragma unroll
        for (int ky = 0; ky < 3; ky++) {
            int hy = h + ky - 1;
            bool oy = (hy >= 0 && hy < H_);
            const float* icr = ic + hy*W_;
#pragma unroll
            for (int xx = 0; xx < 4; xx++) {
                int wx = wq - 1 + xx;
                v[ky*4+xx] = (oy && wx >= 0 && wx < W_) ? __ldg(icr + wx) : 0.f;
            }
        }
#pragma unroll
        for (int k = 0; k < KK_; k++) {
            int ky = k/3, kx = k%3;
            float v0 = v[ky*4+kx], v1 = v[ky*4+kx+1];
            const float4* w4 = (const float4*)(ws + (ci*KK_ + k)*OMCH);
#pragma unroll
            for (int q = 0; q < 6; q++) {
                float4 wv = w4[q];
                float wr[4] = {wv.x, wv.y, wv.z, wv.w};
#pragma unroll
                for (int r = 0; r < 4; r++) {
                    float wc = wr[r];
                    acc[(q*4+r)*2+0] += wc*v0;
                    acc[(q*4+r)*2+1] += wc*v1;
                }
            }
        }
    }
    float* ob = g_om + (size_t)b*OCM*HW + p0;
#pragma unroll
    for (int j = 0; j < OMCH; j++)
        *(float2*)(ob + (size_t)(co0+j)*HW) = make_float2(acc[j*2+0], acc[j*2+1]);
}

// ---------------- 3: transpose dcn weights -> [j][co] ----------------------
__global__ void wtr_k(const float* __restrict__ w) {
    int i = blockIdx.x*256 + threadIdx.x;   // i < C9*C_
    int co = i & 63, j = i >> 6;
    g_wt[i] = w[co*C9 + j];
}

// ---------------- 4: deform im2col (bilinear, modulated) -------------------
__global__ void __launch_bounds__(256, 2) col_k() {
    int tid = threadIdx.x;
    int p = blockIdx.x*256 + tid;
    int gk = blockIdx.y;                 // g*9+k, 0..71
    int g = gk/9, k = gk%9;
    int b = blockIdx.z;
    int h = p >> 7, wq = p & 127;
    const float* omb = g_om + (size_t)b*OCM*HW;
    float dy = omb[(       g*9+k)*HW + p];
    float dx = omb[( 72 +  g*9+k)*HW + p];
    float mk = omb[(144 +  g*9+k)*HW + p];
    mk = 1.f/(1.f + expf(-mk));
    float py = dy + (float)(k/3) + (float)h - 1.f;
    float px = dx + (float)(k%3) + (float)wq - 1.f;
    float fy = floorf(py), fx = floorf(px);
    int y0 = (int)fy, x0 = (int)fx;
    float wy = py - fy, wx = px - fx;
    float w00 = (1.f-wy)*(1.f-wx)*mk;
    float w01 = (1.f-wy)*wx*mk;
    float w10 = wy*(1.f-wx)*mk;
    float w11 = wy*wx*mk;
    bool iy0 = (y0 >= 0 && y0 < H_);
    bool iy1 = (y0+1 >= 0 && y0+1 < H_);
    bool ix0 = (x0 >= 0 && x0 < W_);
    bool ix1 = (x0+1 >= 0 && x0+1 < W_);
    bool v00 = iy0 && ix0, v01 = iy0 && ix1, v10 = iy1 && ix0, v11 = iy1 && ix1;
    int i00 = y0*W_ + x0;
    const float* xb = g_x1 + (size_t)b*C_*HW + (size_t)g*CPG*HW;
    float* cb = g_col + (size_t)b*C9*HW + (size_t)(g*CPG*KK_ + k)*HW + p;
#pragma unroll
    for (int c = 0; c < CPG; c++) {
        const float* xc = xb + c*HW;
        float s = 0.f;
        if (v00) s += w00*__ldg(xc + i00);
        if (v01) s += w01*__ldg(xc + i00 + 1);
        if (v10) s += w10*__ldg(xc + i00 + W_);
        if (v11) s += w11*__ldg(xc + i00 + W_ + 1);
        cb[(size_t)c*KK_*HW] = s;
    }
}

// ---------------- 5: dcn GEMM via tf32 mma.sync + lrelu --------------------
// CTA: 128 px (M) x 64 co (N), K=576 in 32-chunks. 8 warps: each M16 x N64.
#define APAD 136
#define BPAD 72
__global__ void __launch_bounds__(256, 2) dcntc_k(const float* __restrict__ bias) {
    __shared__ __align__(16) float As[32*APAD];   // [j][p] k-chunk x 128px
    __shared__ __align__(16) float Bs[32*BPAD];   // [j][co]
    int tid = threadIdx.x, lane = tid & 31, wid = tid >> 5;
    int b = blockIdx.y;
    int p0 = blockIdx.x*128;
    const float* cb = g_col + (size_t)b*C9*HW + p0;
    float d[8][4];
#pragma unroll
    for (int n = 0; n < 8; n++)
#pragma unroll
        for (int r = 0; r < 4; r++) d[n][r] = 0.f;

    for (int kc = 0; kc < C9/32; kc++) {
        // stage A: 32 rows x 128 px
        const float* src = cb + (size_t)kc*32*HW;
#pragma unroll
        for (int r = 0; r < 4; r++) {
            int i4 = tid + r*256;               // 0..1023
            int row = i4 >> 5, c4 = i4 & 31;
            float4 v = *(const float4*)(src + (size_t)row*HW + c4*4);
            *(float4*)(As + row*APAD + c4*4) = v;
        }
        // stage B: 32 rows x 64 co
#pragma unroll
        for (int r = 0; r < 2; r++) {
            int i4 = tid + r*256;               // 0..511
            int row = i4 >> 4, c4 = i4 & 15;
            float4 v = *(const float4*)(g_wt + (size_t)(kc*32+row)*C_ + c4*4);
            *(float4*)(Bs + row*BPAD + c4*4) = v;
        }
        __syncthreads();
#pragma unroll
        for (int ks = 0; ks < 4; ks++) {
            int j0 = ks*8 + (lane & 3);
            int pa = wid*16 + (lane >> 2);
            unsigned a0 = f2tf32(As[j0*APAD + pa]);
            unsigned a1 = f2tf32(As[j0*APAD + pa + 8]);
            unsigned a2 = f2tf32(As[(j0+4)*APAD + pa]);
            unsigned a3 = f2tf32(As[(j0+4)*APAD + pa + 8]);
#pragma unroll
            for (int n = 0; n < 8; n++) {
                unsigned b0 = f2tf32(Bs[j0*BPAD + n*8 + (lane >> 2)]);
                unsigned b1 = f2tf32(Bs[(j0+4)*BPAD + n*8 + (lane >> 2)]);
                asm volatile(
                    "mma.sync.aligned.m16n8k8.row.col.f32.tf32.tf32.f32 "
                    "{%0,%1,%2,%3}, {%4,%5,%6,%7}, {%8,%9}, {%0,%1,%2,%3};"
                    : "+f"(d[n][0]), "+f"(d[n][1]), "+f"(d[n][2]), "+f"(d[n][3])
                    : "r"(a0), "r"(a1), "r"(a2), "r"(a3), "r"(b0), "r"(b1));
            }
        }
        __syncthreads();
    }
    // epilogue: bias + lrelu, D[p][co] -> g_dcn[co][p]
    int prow = p0 + wid*16 + (lane >> 2);
    float* ob = g_dcn + (size_t)b*C_*HW;
#pragma unroll
    for (int n = 0; n < 8; n++) {
        int co = n*8 + (lane & 3)*2;
        float b0v = __ldg(bias + co), b1v = __ldg(bias + co + 1);
        float v0 = d[n][0] + b0v, v1 = d[n][1] + b1v;
        float v2 = d[n][2] + b0v, v3 = d[n][3] + b1v;
        v0 = (v0 >= 0.f) ? v0 : 0.2f*v0;
        v1 = (v1 >= 0.f) ? v1 : 0.2f*v1;
        v2 = (v2 >= 0.f) ? v2 : 0.2f*v2;
        v3 = (v3 >= 0.f) ? v3 : 0.2f*v3;
        ob[(size_t)co*HW     + prow]     = v0;
        ob[(size_t)(co+1)*HW + prow]     = v1;
        ob[(size_t)co*HW     + prow + 8] = v2;
        ob[(size_t)(co+1)*HW + prow + 8] = v3;
    }
}

// ---------------- shared body: conv3x3 64->64 : 4px x 16co -----------------
template <int FUSE>
__device__ __forceinline__ void conv3x3_v2(const float* __restrict__ ib,
                                           const float* __restrict__ w,
                                           const float* __restrict__ bias,
                                           const float* __restrict__ pre,
                                           float* __restrict__ outp,
                                           float* ws) {
    int tid = threadIdx.x;
    int quad = tid & 63, cq = tid >> 6;
    int p0 = blockIdx.x*256 + quad*4;
    int h = p0 >> 7, wq = p0 & 127;
    float acc[64];
#pragma unroll
    for (int c = 0; c < 16; c++) {
        float bv = __ldg(bias + cq*16 + c);
        acc[c*4+0] = bv; acc[c*4+1] = bv; acc[c*4+2] = bv; acc[c*4+3] = bv;
    }
    for (int cc = 0; cc < 8; cc++) {
        __syncthreads();
        for (int i = tid; i < 8*KK_*C_; i += 256) {
            int ci8 = i/(KK_*C_);
            int k   = (i/C_)%KK_;
            int co  = i & 63;
            ws[i] = w[((size_t)co*C_ + cc*8+ci8)*KK_ + k];
        }
        __syncthreads();
        for (int ci8 = 0; ci8 < 8; ci8++) {
            const float* ic = ib + (size_t)(cc*8+ci8)*HW;
            float v[18];   // [ky][xx] cols wq-1..wq+4
#pragma unroll
            for (int ky = 0; ky < 3; ky++) {
                int hy = h + ky - 1;
                bool oy = (hy >= 0 && hy < H_);
                const float* icr = ic + hy*W_;
#pragma unroll
                for (int xx = 0; xx < 6; xx++) {
                    int wx = wq - 1 + xx;
                    v[ky*6+xx] = (oy && wx >= 0 && wx < W_) ? __ldg(icr + wx) : 0.f;
                }
            }
#pragma unroll
            for (int k = 0; k < KK_; k++) {
                int ky = k/3, kx = k%3;
                const float4* w4 = (const float4*)(ws + (ci8*KK_+k)*C_ + cq*16);
                float v0 = v[ky*6+kx+0], v1 = v[ky*6+kx+1];
                float v2 = v[ky*6+kx+2], v3 = v[ky*6+kx+3];
#pragma unroll
                for (int q = 0; q < 4; q++) {
                    float4 wv = w4[q];
                    float wr[4] = {wv.x, wv.y, wv.z, wv.w};
#pragma unroll
                    for (int r = 0; r < 4; r++) {
                        float wc = wr[r];
                        float* a = acc + (q*4+r)*4;
                        a[0] += wc*v0; a[1] += wc*v1; a[2] += wc*v2; a[3] += wc*v3;
                    }
                }
            }
        }
    }
#pragma unroll
    for (int c = 0; c < 16; c++) {
        float4 o;
        o.x = acc[c*4+0]; o.y = acc[c*4+1]; o.z = acc[c*4+2]; o.w = acc[c*4+3];
        if (FUSE) {
            float4 pv = *(const float4*)(pre + (size_t)(cq*16+c)*HW + p0);
            o.x += 2.f*pv.x; o.y += 2.f*pv.y; o.z += 2.f*pv.z; o.w += 2.f*pv.w;
        }
        *(float4*)(outp + (size_t)(cq*16+c)*HW + p0) = o;
    }
}

// a0: g_dcn -> g_x0
__global__ void __launch_bounds__(256, 2) conv_a0_k(
        const float* __restrict__ w, const float* __restrict__ bias) {
    __shared__ __align__(16) float ws[8*KK_*C_];
    int b = blockIdx.y;
    conv3x3_v2<0>(g_dcn + (size_t)b*C_*HW, w, bias, nullptr,
                  g_x0 + (size_t)b*C_*HW, ws);
}

// fus: g_out -> d_out (+ 2*g_dcn)
__global__ void __launch_bounds__(256, 2) conv_fus_k(
        const float* __restrict__ w, const float* __restrict__ bias,
        float* __restrict__ out) {
    __shared__ __align__(16) float ws[8*KK_*C_];
    int b = blockIdx.y;
    conv3x3_v2<1>(g_out + (size_t)b*C_*HW, w, bias, g_dcn + (size_t)b*C_*HW,
                  out + (size_t)b*C_*HW, ws);
}

// ---------------- 6: depthwise 3x3 on g_x0 -> g_x1d (+eca) -----------------
__global__ void __launch_bounds__(256, 4) dw_k(
        const float* __restrict__ w, const float* __restrict__ bias) {
    int tid = threadIdx.x;
    int c = blockIdx.y, b = blockIdx.z;
    int p = blockIdx.x*256 + tid;
    int h = p >> 7, wq = p & 127;
    const float* ic = g_x0 + ((size_t)b*C_ + c)*HW;
    float acc = bias[c] + g_eca[b*C_ + c];
#pragma unroll
    for (int ky = 0; ky < 3; ky++) {
        int hy = h + ky - 1;
        bool oky = (hy >= 0 && hy < H_);
#pragma unroll
        for (int kx = 0; kx < 3; kx++) {
            int wx = wq + kx - 1;
            float v = (oky && wx >= 0 && wx < W_) ? __ldg(ic + hy*W_ + wx) : 0.f;
            acc += __ldg(w + c*KK_ + ky*3+kx)*v;
        }
    }
    g_x1d[((size_t)b*C_ + c)*HW + p] = acc;
}

// ---------------- 7: per-(b,c) mean of g_x0 --------------------------------
__global__ void mean_k() {
    __shared__ float sd[256];
    int bc = blockIdx.x;
    const float* ic = g_x0 + (size_t)bc*HW;
    float s = 0.f;
    for (int i = threadIdx.x; i < HW; i += 256) s += ic[i];
    sd[threadIdx.x] = s;
    __syncthreads();
    for (int st = 128; st > 0; st >>= 1) {
        if (threadIdx.x < st) sd[threadIdx.x] += sd[threadIdx.x+st];
        __syncthreads();
    }
    if (threadIdx.x == 0) g_s[bc] = sd[0]*(1.f/(float)HW);
}

// ---------------- 8: ECA 1D conv over channels -----------------------------
__global__ void eca_k(const float* __restrict__ w2, const float* __restrict__ b2) {
    int i = threadIdx.x;
    if (i >= B_*C_) return;
    int c = i & 63;
    float sm1 = (c > 0)  ? g_s[i-1] : 0.f;
    float s0  = g_s[i];
    float sp1 = (c < 63) ? g_s[i+1] : 0.f;
    g_eca[i] = w2[0]*sm1 + w2[1]*s0 + w2[2]*sp1 + b2[0];
}

// ---------------- 9: a3 1x1 (64->576) + dynamic filter + lrelu : 4px -------
__global__ void __launch_bounds__(256, 2) a3filt_k(
        const float* __restrict__ w, const float* __restrict__ bias) {
    __shared__ __align__(16) float ws[8*KK_*C_];   // [c8][k][ci]
    int tid = threadIdx.x;
    int b = blockIdx.y;
    int cc0 = blockIdx.z*2;
    int p0 = blockIdx.x*1024 + tid*4;
    int h = p0 >> 7, wq = p0 & 127;
    const float* xb  = g_x1d + (size_t)b*C_*HW + p0;
    const float* x0b = g_x0  + (size_t)b*C_*HW;
    float* ob = g_out + (size_t)b*C_*HW + p0;
    for (int cc = cc0; cc < cc0+2; cc++) {
        __syncthreads();
        for (int i = tid; i < 8*KK_*C_; i += 256) ws[i] = w[(size_t)cc*8*KK_*C_ + i];
        __syncthreads();
        for (int c8 = 0; c8 < 8; c8++) {
            int c = cc*8 + c8;
            float filt[36];   // [k][x]
#pragma unroll
            for (int k = 0; k < KK_; k++) {
                float bv = __ldg(bias + c*KK_ + k);
                filt[k*4+0] = bv; filt[k*4+1] = bv; filt[k*4+2] = bv; filt[k*4+3] = bv;
            }
#pragma unroll 4
            for (int q = 0; q < 16; q++) {
                float4 iv0 = *(const float4*)(xb + (size_t)(q*4+0)*HW);
                float4 iv1 = *(const float4*)(xb + (size_t)(q*4+1)*HW);
                float4 iv2 = *(const float4*)(xb + (size_t)(q*4+2)*HW);
                float4 iv3 = *(const float4*)(xb + (size_t)(q*4+3)*HW);
                const float4* w4 = (const float4*)(ws + (c8*KK_)*C_);
#pragma unroll
                for (int k = 0; k < KK_; k++) {
                    float4 wv = w4[k*16 + q];
                    float* f = filt + k*4;
                    f[0] += wv.x*iv0.x + wv.y*iv1.x + wv.z*iv2.x + wv.w*iv3.x;
                    f[1] += wv.x*iv0.y + wv.y*iv1.y + wv.z*iv2.y + wv.w*iv3.y;
                    f[2] += wv.x*iv0.z + wv.y*iv1.z + wv.z*iv2.z + wv.w*iv3.z;
                    f[3] += wv.x*iv0.w + wv.y*iv1.w + wv.z*iv2.w + wv.w*iv3.w;
                }
            }
            // apply 3x3 dynamic filter over x0[c]
            const float* ic = x0b + (size_t)c*HW;
            float v[18];
#pragma unroll
            for (int ky = 0; ky < 3; ky++) {
                int hy = h + ky - 1;
                bool oy = (hy >= 0 && hy < H_);
                const float* icr = ic + hy*W_;
#pragma unroll
                for (int xx = 0; xx < 6; xx++) {
                    int wx = wq - 1 + xx;
                    v[ky*6+xx] = (oy && wx >= 0 && wx < W_) ? __ldg(icr + wx) : 0.f;
                }
            }
            float o[4] = {0.f, 0.f, 0.f, 0.f};
#pragma unroll
            for (int k = 0; k < KK_; k++) {
                int ky = k/3, kx = k%3;
#pragma unroll
                for (int xx = 0; xx < 4; xx++)
                    o[xx] += filt[k*4+xx]*v[ky*6+kx+xx];
            }
            float4 r;
            r.x = (o[0] >= 0.f) ? o[0] : 0.2f*o[0];
            r.y = (o[1] >= 0.f) ? o[1] : 0.2f*o[1];
            r.z = (o[2] >= 0.f) ? o[2] : 0.2f*o[2];
            r.w = (o[3] >= 0.f) ? o[3] : 0.2f*o[3];
            *(float4*)(ob + (size_t)c*HW) = r;
        }
    }
}

// ---------------- launch ----------------------------------------------------
extern "C" void kernel_launch(void* const* d_in, const int* in_sizes, int n_in,
                              void* d_out, int out_size) {
    const float* x       = (const float*)d_in[0];
    const float* offset  = (const float*)d_in[1];
    const float* conv0_w = (const float*)d_in[2];
    const float* conv0_b = (const float*)d_in[3];
    const float* offm_w  = (const float*)d_in[4];
    const float* offm_b  = (const float*)d_in[5];
    const float* dcn_w   = (const float*)d_in[6];
    const float* dcn_b   = (const float*)d_in[7];
    const float* a0_w    = (const float*)d_in[8];
    const float* a0_b    = (const float*)d_in[9];
    const float* a1_w    = (const float*)d_in[10];
    const float* a1_b    = (const float*)d_in[11];
    const float* a2_w    = (const float*)d_in[12];
    const float* a2_b    = (const float*)d_in[13];
    const float* a3_w    = (const float*)d_in[14];
    const float* a3_b    = (const float*)d_in[15];
    const float* fus_w   = (const float*)d_in[16];
    const float* fus_b   = (const float*)d_in[17];
    float* out = (float*)d_out;

    dim3 gp(HW/256, B_);
    wtr_k    <<<C9*C_/256, 256>>>(dcn_w);
    conv0_k  <<<gp, 256>>>(x, conv0_w, conv0_b);
    offm_k   <<<dim3(HW/512, B_, OCM/OMCH), 256>>>(offset, offm_w, offm_b);
    col_k    <<<dim3(HW/256, DG_*KK_, B_), 256>>>();
    dcntc_k  <<<dim3(HW/128, B_), 256>>>(dcn_b);
    conv_a0_k<<<gp, 256>>>(a0_w, a0_b);
    mean_k   <<<B_*C_, 256>>>();
    eca_k    <<<1, 256>>>(a2_w, a2_b);
    dw_k     <<<dim3(HW/256, C_, B_), 256>>>(a1_w, a1_b);
    a3filt_k <<<dim3(HW/1024, B_, 4), 256>>>(a3_w, a3_b);
    conv_fus_k<<<gp, 256>>>(fus_w, fus_b, out);
}

// round 9
// speedup vs baseline: 1.4960x; 1.1941x over previous
#include <cuda_runtime.h>
#include <cuda_bf16.h>
#include <math.h>

// Problem constants
#define B_   4
#define CIN  32
#define C_   64
#define H_   128
#define W_   128
#define HW   16384
#define DG_  8
#define CPG  8
#define KK_  9
#define OCM  216   // DG*3*K*K
#define C9   576   // C*9

// ---------------- scratch (device globals; no allocation allowed) ----------
__device__ float g_x1 [B_*C_ *HW];   // conv0 out
__device__ float g_om [B_*OCM*HW];   // offset/mask conv out
__device__ float g_dcn[B_*C_ *HW];   // lrelu(deform conv) == pre == x
__device__ float g_col[B_*C9 *HW];   // deform im2col columns [b][j][p]
__device__ float g_wt [C9*C_];       // dcn weights transposed [j][co]
__device__ float g_wta[C9*C_];       // a0 weights transposed [ci*9+k][co]
__device__ float g_wtf[C9*C_];       // fus weights transposed [ci*9+k][co]
__device__ float g_x0 [B_*C_ *HW];   // a0 conv out
__device__ float g_x1d[B_*C_ *HW];   // depthwise out (+eca folded in)
__device__ float g_out[B_*C_ *HW];   // dynamic-filter out (lrelu'd)
__device__ float g_s  [B_*C_];       // channel means of x0
__device__ float g_eca[B_*C_];       // eca values

__device__ __forceinline__ unsigned f2tf32(float v) {
    unsigned t;
    asm("cvt.rna.tf32.f32 %0, %1;" : "=r"(t) : "f"(v));
    return t;
}

// ---------------- 1: conv0 1x1, 32->64 : 4px x 16co tiling ------------------
__global__ void __launch_bounds__(256, 2) conv0_k(
        const float* __restrict__ x, const float* __restrict__ w,
        const float* __restrict__ bias) {
    __shared__ __align__(16) float ws[CIN*C_];   // [ci][co]
    int tid = threadIdx.x;
    int quad = tid & 63, cg = tid >> 6;
    for (int i = tid; i < C_*CIN; i += 256) {
        int ci = i >> 6, co = i & 63;
        ws[ci*C_ + co] = w[co*CIN + ci];
    }
    __syncthreads();
    int b = blockIdx.y;
    int p0 = blockIdx.x*256 + quad*4;
    const float* xb = x + (size_t)b*CIN*HW + p0;
    float acc[64];
#pragma unroll
    for (int c = 0; c < 16; c++) {
        float bv = __ldg(bias + cg*16 + c);
        acc[c*4+0] = bv; acc[c*4+1] = bv; acc[c*4+2] = bv; acc[c*4+3] = bv;
    }
    for (int ci = 0; ci < CIN; ci++) {
        float4 v = *(const float4*)(xb + (size_t)ci*HW);
        const float4* w4 = (const float4*)(ws + ci*C_ + cg*16);
#pragma unroll
        for (int q = 0; q < 4; q++) {
            float4 wv = w4[q];
            float wr[4] = {wv.x, wv.y, wv.z, wv.w};
#pragma unroll
            for (int r = 0; r < 4; r++) {
                float wc = wr[r];
                float* a = acc + (q*4+r)*4;
                a[0] += wc*v.x; a[1] += wc*v.y; a[2] += wc*v.z; a[3] += wc*v.w;
            }
        }
    }
    float* ob = g_x1 + (size_t)b*C_*HW + p0;
#pragma unroll
    for (int c = 0; c < 16; c++)
        *(float4*)(ob + (size_t)(cg*16+c)*HW) =
            make_float4(acc[c*4+0], acc[c*4+1], acc[c*4+2], acc[c*4+3]);
}

// ---------------- 2: offset/mask conv 3x3, 32->216 : 2px x 24co -------------
#define OMCH 24
__global__ void __launch_bounds__(256, 2) offm_k(
        const float* __restrict__ in, const float* __restrict__ w,
        const float* __restrict__ bias) {
    __shared__ __align__(16) float ws[CIN*KK_*OMCH];   // [ci][k][j]
    int tid = threadIdx.x;
    int b = blockIdx.y;
    int co0 = blockIdx.z*OMCH;
    int p0 = blockIdx.x*512 + tid*2;
    int h = p0 >> 7, wq = p0 & 127;
    for (int i = tid; i < OMCH*CIN*KK_; i += 256) {
        int ci = i/(KK_*OMCH);
        int k  = (i/OMCH)%KK_;
        int j  = i%OMCH;
        ws[i] = w[((co0+j)*CIN + ci)*KK_ + k];
    }
    __syncthreads();
    const float* ib = in + (size_t)b*CIN*HW;
    float acc[OMCH*2];
#pragma unroll
    for (int j = 0; j < OMCH; j++) {
        float bv = __ldg(bias + co0 + j);
        acc[j*2+0] = bv; acc[j*2+1] = bv;
    }
    for (int ci = 0; ci < CIN; ci++) {
        const float* ic = ib + (size_t)ci*HW;
        float v[12];   // [ky][xx] cols wq-1..wq+2
#pragma unroll
        for (int ky = 0; ky < 3; ky++) {
            int hy = h + ky - 1;
            bool oy = (hy >= 0 && hy < H_);
            const float* icr = ic + hy*W_;
#pragma unroll
            for (int xx = 0; xx < 4; xx++) {
                int wx = wq - 1 + xx;
                v[ky*4+xx] = (oy && wx >= 0 && wx < W_) ? __ldg(icr + wx) : 0.f;
            }
        }
#pragma unroll
        for (int k = 0; k < KK_; k++) {
            int ky = k/3, kx = k%3;
            float v0 = v[ky*4+kx], v1 = v[ky*4+kx+1];
            const float4* w4 = (const float4*)(ws + (ci*KK_ + k)*OMCH);
#pragma unroll
            for (int q = 0; q < 6; q++) {
                float4 wv = w4[q];
                float wr[4] = {wv.x, wv.y, wv.z, wv.w};
#pragma unroll
                for (int r = 0; r < 4; r++) {
                    float wc = wr[r];
                    acc[(q*4+r)*2+0] += wc*v0;
                    acc[(q*4+r)*2+1] += wc*v1;
                }
            }
        }
    }
    float* ob = g_om + (size_t)b*OCM*HW + p0;
#pragma unroll
    for (int j = 0; j < OMCH; j++)
        *(float2*)(ob + (size_t)(co0+j)*HW) = make_float2(acc[j*2+0], acc[j*2+1]);
}

// ---------------- 3: transpose weights [co][j] -> [j][co] ------------------
__global__ void wtr_k(const float* __restrict__ w, int which) {
    int i = blockIdx.x*256 + threadIdx.x;   // i < C9*C_
    int co = i & 63, j = i >> 6;
    float v = w[co*C9 + j];
    if (which == 0)      g_wt [i] = v;
    else if (which == 1) g_wta[i] = v;
    else                 g_wtf[i] = v;
}

// ---------------- 4: deform im2col (bilinear, modulated) -------------------
__global__ void __launch_bounds__(256, 2) col_k() {
    int tid = threadIdx.x;
    int p = blockIdx.x*256 + tid;
    int gk = blockIdx.y;                 // g*9+k, 0..71
    int g = gk/9, k = gk%9;
    int b = blockIdx.z;
    int h = p >> 7, wq = p & 127;
    const float* omb = g_om + (size_t)b*OCM*HW;
    float dy = omb[(       g*9+k)*HW + p];
    float dx = omb[( 72 +  g*9+k)*HW + p];
    float mk = omb[(144 +  g*9+k)*HW + p];
    mk = 1.f/(1.f + expf(-mk));
    float py = dy + (float)(k/3) + (float)h - 1.f;
    float px = dx + (float)(k%3) + (float)wq - 1.f;
    float fy = floorf(py), fx = floorf(px);
    int y0 = (int)fy, x0 = (int)fx;
    float wy = py - fy, wx = px - fx;
    float w00 = (1.f-wy)*(1.f-wx)*mk;
    float w01 = (1.f-wy)*wx*mk;
    float w10 = wy*(1.f-wx)*mk;
    float w11 = wy*wx*mk;
    bool iy0 = (y0 >= 0 && y0 < H_);
    bool iy1 = (y0+1 >= 0 && y0+1 < H_);
    bool ix0 = (x0 >= 0 && x0 < W_);
    bool ix1 = (x0+1 >= 0 && x0+1 < W_);
    bool v00 = iy0 && ix0, v01 = iy0 && ix1, v10 = iy1 && ix0, v11 = iy1 && ix1;
    int i00 = y0*W_ + x0;
    const float* xb = g_x1 + (size_t)b*C_*HW + (size_t)g*CPG*HW;
    float* cb = g_col + (size_t)b*C9*HW + (size_t)(g*CPG*KK_ + k)*HW + p;
#pragma unroll
    for (int c = 0; c < CPG; c++) {
        const float* xc = xb + c*HW;
        float s = 0.f;
        if (v00) s += w00*__ldg(xc + i00);
        if (v01) s += w01*__ldg(xc + i00 + 1);
        if (v10) s += w10*__ldg(xc + i00 + W_);
        if (v11) s += w11*__ldg(xc + i00 + W_ + 1);
        cb[(size_t)c*KK_*HW] = s;
    }
}

// ---------------- 5: dcn GEMM via tf32 mma.sync + lrelu --------------------
// CTA: 128 px (M) x 64 co (N), K=576 in 32-chunks. 8 warps: each M16 x N64.
#define APAD 136
#define BPAD 72
__global__ void __launch_bounds__(256, 2) dcntc_k(const float* __restrict__ bias) {
    __shared__ __align__(16) float As[32*APAD];   // [j][p] k-chunk x 128px
    __shared__ __align__(16) float Bs[32*BPAD];   // [j][co]
    int tid = threadIdx.x, lane = tid & 31, wid = tid >> 5;
    int b = blockIdx.y;
    int p0 = blockIdx.x*128;
    const float* cb = g_col + (size_t)b*C9*HW + p0;
    float d[8][4];
#pragma unroll
    for (int n = 0; n < 8; n++)
#pragma unroll
        for (int r = 0; r < 4; r++) d[n][r] = 0.f;

    for (int kc = 0; kc < C9/32; kc++) {
        // stage A: 32 rows x 128 px
        const float* src = cb + (size_t)kc*32*HW;
#pragma unroll
        for (int r = 0; r < 4; r++) {
            int i4 = tid + r*256;               // 0..1023
            int row = i4 >> 5, c4 = i4 & 31;
            float4 v = *(const float4*)(src + (size_t)row*HW + c4*4);
            *(float4*)(As + row*APAD + c4*4) = v;
        }
        // stage B: 32 rows x 64 co
#pragma unroll
        for (int r = 0; r < 2; r++) {
            int i4 = tid + r*256;               // 0..511
            int row = i4 >> 4, c4 = i4 & 15;
            float4 v = *(const float4*)(g_wt + (size_t)(kc*32+row)*C_ + c4*4);
            *(float4*)(Bs + row*BPAD + c4*4) = v;
        }
        __syncthreads();
#pragma unroll
        for (int ks = 0; ks < 4; ks++) {
            int j0 = ks*8 + (lane & 3);
            int pa = wid*16 + (lane >> 2);
            unsigned a0 = f2tf32(As[j0*APAD + pa]);
            unsigned a1 = f2tf32(As[j0*APAD + pa + 8]);
            unsigned a2 = f2tf32(As[(j0+4)*APAD + pa]);
            unsigned a3 = f2tf32(As[(j0+4)*APAD + pa + 8]);
#pragma unroll
            for (int n = 0; n < 8; n++) {
                unsigned b0 = f2tf32(Bs[j0*BPAD + n*8 + (lane >> 2)]);
                unsigned b1 = f2tf32(Bs[(j0+4)*BPAD + n*8 + (lane >> 2)]);
                asm volatile(
                    "mma.sync.aligned.m16n8k8.row.col.f32.tf32.tf32.f32 "
                    "{%0,%1,%2,%3}, {%4,%5,%6,%7}, {%8,%9}, {%0,%1,%2,%3};"
                    : "+f"(d[n][0]), "+f"(d[n][1]), "+f"(d[n][2]), "+f"(d[n][3])
                    : "r"(a0), "r"(a1), "r"(a2), "r"(a3), "r"(b0), "r"(b1));
            }
        }
        __syncthreads();
    }
    // epilogue: bias + lrelu, D[p][co] -> g_dcn[co][p]
    int prow = p0 + wid*16 + (lane >> 2);
    float* ob = g_dcn + (size_t)b*C_*HW;
#pragma unroll
    for (int n = 0; n < 8; n++) {
        int co = n*8 + (lane & 3)*2;
        float b0v = __ldg(bias + co), b1v = __ldg(bias + co + 1);
        float v0 = d[n][0] + b0v, v1 = d[n][1] + b1v;
        float v2 = d[n][2] + b0v, v3 = d[n][3] + b1v;
        v0 = (v0 >= 0.f) ? v0 : 0.2f*v0;
        v1 = (v1 >= 0.f) ? v1 : 0.2f*v1;
        v2 = (v2 >= 0.f) ? v2 : 0.2f*v2;
        v3 = (v3 >= 0.f) ? v3 : 0.2f*v3;
        ob[(size_t)co*HW     + prow]     = v0;
        ob[(size_t)(co+1)*HW + prow]     = v1;
        ob[(size_t)co*HW     + prow + 8] = v2;
        ob[(size_t)(co+1)*HW + prow + 8] = v3;
    }
}

// ---------------- 6: conv3x3 64->64 via tf32 mma (implicit GEMM) -----------
// CTA: one image row (128 px M) x 64 co N. K = ci-chunks of 8, 9 shift passes.
#define TW 132
template <int FUSE>
__device__ __forceinline__ void conv3tc_body(
        const float* __restrict__ in, const float* __restrict__ wt,
        const float* __restrict__ bias, const float* __restrict__ pre,
        float* __restrict__ outp) {
    __shared__ __align__(16) float raw[8*3*TW];    // [ci8][row3][col132]
    __shared__ __align__(16) float Bs[9*8*BPAD];   // [k9][ci8][co72]
    int tid = threadIdx.x, lane = tid & 31, wid = tid >> 5;
    int h = blockIdx.x;
    float d[8][4];
#pragma unroll
    for (int n = 0; n < 8; n++)
#pragma unroll
        for (int r = 0; r < 4; r++) d[n][r] = 0.f;

    for (int cc = 0; cc < 8; cc++) {
        __syncthreads();
        // stage raw input tile: 8 ci x 3 rows x 130 cols (halo zero)
        for (int i = tid; i < 8*3*TW; i += 256) {
            int ci = i/(3*TW);
            int r  = (i/TW)%3;
            int t  = i%TW;
            int row = h + r - 1, col = t - 1;
            float v = 0.f;
            if (t < 130 && row >= 0 && row < H_ && col >= 0 && col < W_)
                v = __ldg(in + (size_t)(cc*8+ci)*HW + row*W_ + col);
            raw[i] = v;
        }
        // stage weights: Bs[k][ci][co]
        for (int i = tid; i < 9*8*C_; i += 256) {
            int ks = i/(8*C_);
            int ci = (i/C_)%8;
            int co = i & 63;
            Bs[(ks*8+ci)*BPAD + co] = __ldg(wt + (size_t)((cc*8+ci)*KK_ + ks)*C_ + co);
        }
        __syncthreads();
#pragma unroll
        for (int ks = 0; ks < KK_; ks++) {
            int ky = ks/3, kx = ks%3;
            int abase = ((lane&3)*3 + ky)*TW + wid*16 + (lane>>2) + kx;
            unsigned a0 = f2tf32(raw[abase]);
            unsigned a1 = f2tf32(raw[abase + 8]);
            unsigned a2 = f2tf32(raw[abase + 4*3*TW]);
            unsigned a3 = f2tf32(raw[abase + 4*3*TW + 8]);
#pragma unroll
            for (int n = 0; n < 8; n++) {
                unsigned b0 = f2tf32(Bs[(ks*8 + (lane&3))*BPAD + n*8 + (lane>>2)]);
                unsigned b1 = f2tf32(Bs[(ks*8 + (lane&3)+4)*BPAD + n*8 + (lane>>2)]);
                asm volatile(
                    "mma.sync.aligned.m16n8k8.row.col.f32.tf32.tf32.f32 "
                    "{%0,%1,%2,%3}, {%4,%5,%6,%7}, {%8,%9}, {%0,%1,%2,%3};"
                    : "+f"(d[n][0]), "+f"(d[n][1]), "+f"(d[n][2]), "+f"(d[n][3])
                    : "r"(a0), "r"(a1), "r"(a2), "r"(a3), "r"(b0), "r"(b1));
            }
        }
    }
    // epilogue: bias (+2*pre for FUSE), D[px][co] -> outp[co][h*W+px]
    int prow = h*W_ + wid*16 + (lane >> 2);
#pragma unroll
    for (int n = 0; n < 8; n++) {
        int co = n*8 + (lane & 3)*2;
        float b0v = __ldg(bias + co), b1v = __ldg(bias + co + 1);
        float v0 = d[n][0] + b0v, v1 = d[n][1] + b1v;
        float v2 = d[n][2] + b0v, v3 = d[n][3] + b1v;
        if (FUSE) {
            v0 += 2.f*__ldg(pre + (size_t)co*HW     + prow);
            v1 += 2.f*__ldg(pre + (size_t)(co+1)*HW + prow);
            v2 += 2.f*__ldg(pre + (size_t)co*HW     + prow + 8);
            v3 += 2.f*__ldg(pre + (size_t)(co+1)*HW + prow + 8);
        }
        outp[(size_t)co*HW     + prow]     = v0;
        outp[(size_t)(co+1)*HW + prow]     = v1;
        outp[(size_t)co*HW     + prow + 8] = v2;
        outp[(size_t)(co+1)*HW + prow + 8] = v3;
    }
}

__global__ void __launch_bounds__(256, 2) conv_a0tc_k(const float* __restrict__ bias) {
    int b = blockIdx.y;
    conv3tc_body<0>(g_dcn + (size_t)b*C_*HW, g_wta, bias, nullptr,
                    g_x0 + (size_t)b*C_*HW);
}

__global__ void __launch_bounds__(256, 2) conv_fustc_k(
        const float* __restrict__ bias, float* __restrict__ out) {
    int b = blockIdx.y;
    conv3tc_body<1>(g_out + (size_t)b*C_*HW, g_wtf, bias,
                    g_dcn + (size_t)b*C_*HW, out + (size_t)b*C_*HW);
}

// ---------------- 7: depthwise 3x3 on g_x0 -> g_x1d (+eca) -----------------
__global__ void __launch_bounds__(256, 4) dw_k(
        const float* __restrict__ w, const float* __restrict__ bias) {
    int tid = threadIdx.x;
    int c = blockIdx.y, b = blockIdx.z;
    int p = blockIdx.x*256 + tid;
    int h = p >> 7, wq = p & 127;
    const float* ic = g_x0 + ((size_t)b*C_ + c)*HW;
    float acc = bias[c] + g_eca[b*C_ + c];
#pragma unroll
    for (int ky = 0; ky < 3; ky++) {
        int hy = h + ky - 1;
        bool oky = (hy >= 0 && hy < H_);
#pragma unroll
        for (int kx = 0; kx < 3; kx++) {
            int wx = wq + kx - 1;
            float v = (oky && wx >= 0 && wx < W_) ? __ldg(ic + hy*W_ + wx) : 0.f;
            acc += __ldg(w + c*KK_ + ky*3+kx)*v;
        }
    }
    g_x1d[((size_t)b*C_ + c)*HW + p] = acc;
}

// ---------------- 8: per-(b,c) mean of g_x0 --------------------------------
__global__ void mean_k() {
    __shared__ float sd[256];
    int bc = blockIdx.x;
    const float* ic = g_x0 + (size_t)bc*HW;
    float s = 0.f;
    for (int i = threadIdx.x; i < HW; i += 256) s += ic[i];
    sd[threadIdx.x] = s;
    __syncthreads();
    for (int st = 128; st > 0; st >>= 1) {
        if (threadIdx.x < st) sd[threadIdx.x] += sd[threadIdx.x+st];
        __syncthreads();
    }
    if (threadIdx.x == 0) g_s[bc] = sd[0]*(1.f/(float)HW);
}

// ---------------- 9: ECA 1D conv over channels -----------------------------
__global__ void eca_k(const float* __restrict__ w2, const float* __restrict__ b2) {
    int i = threadIdx.x;
    if (i >= B_*C_) return;
    int c = i & 63;
    float sm1 = (c > 0)  ? g_s[i-1] : 0.f;
    float s0  = g_s[i];
    float sp1 = (c < 63) ? g_s[i+1] : 0.f;
    g_eca[i] = w2[0]*sm1 + w2[1]*s0 + w2[2]*sp1 + b2[0];
}

// ---------------- 10: a3 1x1 (64->576) + dynamic filter + lrelu : 4px ------
__global__ void __launch_bounds__(256, 2) a3filt_k(
        const float* __restrict__ w, const float* __restrict__ bias) {
    __shared__ __align__(16) float ws[8*KK_*C_];   // [c8][k][ci]
    int tid = threadIdx.x;
    int b = blockIdx.y;
    int cc0 = blockIdx.z*2;
    int p0 = blockIdx.x*1024 + tid*4;
    int h = p0 >> 7, wq = p0 & 127;
    const float* xb  = g_x1d + (size_t)b*C_*HW + p0;
    const float* x0b = g_x0  + (size_t)b*C_*HW;
    float* ob = g_out + (size_t)b*C_*HW + p0;
    for (int cc = cc0; cc < cc0+2; cc++) {
        __syncthreads();
        for (int i = tid; i < 8*KK_*C_; i += 256) ws[i] = w[(size_t)cc*8*KK_*C_ + i];
        __syncthreads();
        for (int c8 = 0; c8 < 8; c8++) {
            int c = cc*8 + c8;
            float filt[36];   // [k][x]
#pragma unroll
            for (int k = 0; k < KK_; k++) {
                float bv = __ldg(bias + c*KK_ + k);
                filt[k*4+0] = bv; filt[k*4+1] = bv; filt[k*4+2] = bv; filt[k*4+3] = bv;
            }
#pragma unroll 4
            for (int q = 0; q < 16; q++) {
                float4 iv0 = *(const float4*)(xb + (size_t)(q*4+0)*HW);
                float4 iv1 = *(const float4*)(xb + (size_t)(q*4+1)*HW);
                float4 iv2 = *(const float4*)(xb + (size_t)(q*4+2)*HW);
                float4 iv3 = *(const float4*)(xb + (size_t)(q*4+3)*HW);
                const float4* w4 = (const float4*)(ws + (c8*KK_)*C_);
#pragma unroll
                for (int k = 0; k < KK_; k++) {
                    float4 wv = w4[k*16 + q];
                    float* f = filt + k*4;
                    f[0] += wv.x*iv0.x + wv.y*iv1.x + wv.z*iv2.x + wv.w*iv3.x;
                    f[1] += wv.x*iv0.y + wv.y*iv1.y + wv.z*iv2.y + wv.w*iv3.y;
                    f[2] += wv.x*iv0.z + wv.y*iv1.z + wv.z*iv2.z + wv.w*iv3.z;
                    f[3] += wv.x*iv0.w + wv.y*iv1.w + wv.z*iv2.w + wv.w*iv3.w;
                }
            }
            // apply 3x3 dynamic filter over x0[c]
            const float* ic = x0b + (size_t)c*HW;
            float v[18];
#pragma unroll
            for (int ky = 0; ky < 3; ky++) {
                int hy = h + ky - 1;
                bool oy = (hy >= 0 && hy < H_);
                const float* icr = ic + hy*W_;
#pragma unroll
                for (int xx = 0; xx < 6; xx++) {
                    int wx = wq - 1 + xx;
                    v[ky*6+xx] = (oy && wx >= 0 && wx < W_) ? __ldg(icr + wx) : 0.f;
                }
            }
            float o[4] = {0.f, 0.f, 0.f, 0.f};
#pragma unroll
            for (int k = 0; k < KK_; k++) {
                int ky = k/3, kx = k%3;
#pragma unroll
                for (int xx = 0; xx < 4; xx++)
                    o[xx] += filt[k*4+xx]*v[ky*6+kx+xx];
            }
            float4 r;
            r.x = (o[0] >= 0.f) ? o[0] : 0.2f*o[0];
            r.y = (o[1] >= 0.f) ? o[1] : 0.2f*o[1];
            r.z = (o[2] >= 0.f) ? o[2] : 0.2f*o[2];
            r.w = (o[3] >= 0.f) ? o[3] : 0.2f*o[3];
            *(float4*)(ob + (size_t)c*HW) = r;
        }
    }
}

// ---------------- launch ----------------------------------------------------
extern "C" void kernel_launch(void* const* d_in, const int* in_sizes, int n_in,
                              void* d_out, int out_size) {
    const float* x       = (const float*)d_in[0];
    const float* offset  = (const float*)d_in[1];
    const float* conv0_w = (const float*)d_in[2];
    const float* conv0_b = (const float*)d_in[3];
    const float* offm_w  = (const float*)d_in[4];
    const float* offm_b  = (const float*)d_in[5];
    const float* dcn_w   = (const float*)d_in[6];
    const float* dcn_b   = (const float*)d_in[7];
    const float* a0_w    = (const float*)d_in[8];
    const float* a0_b    = (const float*)d_in[9];
    const float* a1_w    = (const float*)d_in[10];
    const float* a1_b    = (const float*)d_in[11];
    const float* a2_w    = (const float*)d_in[12];
    const float* a2_b    = (const float*)d_in[13];
    const float* a3_w    = (const float*)d_in[14];
    const float* a3_b    = (const float*)d_in[15];
    const float* fus_w   = (const float*)d_in[16];
    const float* fus_b   = (const float*)d_in[17];
    float* out = (float*)d_out;

    dim3 gp(HW/256, B_);
    wtr_k    <<<C9*C_/256, 256>>>(dcn_w, 0);
    wtr_k    <<<C9*C_/256, 256>>>(a0_w, 1);
    wtr_k    <<<C9*C_/256, 256>>>(fus_w, 2);
    conv0_k  <<<gp, 256>>>(x, conv0_w, conv0_b);
    offm_k   <<<dim3(HW/512, B_, OCM/OMCH), 256>>>(offset, offm_w, offm_b);
    col_k    <<<dim3(HW/256, DG_*KK_, B_), 256>>>();
    dcntc_k  <<<dim3(HW/128, B_), 256>>>(dcn_b);
    conv_a0tc_k<<<dim3(H_, B_), 256>>>(a0_b);
    mean_k   <<<B_*C_, 256>>>();
    eca_k    <<<1, 256>>>(a2_w, a2_b);
    dw_k     <<<dim3(HW/256, C_, B_), 256>>>(a1_w, a1_b);
    a3filt_k <<<dim3(HW/1024, B_, 4), 256>>>(a3_w, a3_b);
    conv_fustc_k<<<dim3(H_, B_), 256>>>(fus_b, out);
}

// round 10
// speedup vs baseline: 1.7797x; 1.1896x over previous
#include <cuda_runtime.h>
#include <cuda_bf16.h>
#include <math.h>

// Problem constants
#define B_   4
#define CIN  32
#define C_   64
#define H_   128
#define W_   128
#define HW   16384
#define DG_  8
#define CPG  8
#define KK_  9
#define OCM  216   // DG*3*K*K
#define C9   576   // C*9

// ---------------- scratch (device globals; no allocation allowed) ----------
__device__ float g_x1 [B_*C_ *HW];   // conv0 out
__device__ float g_om [B_*OCM*HW];   // offset/mask conv out
__device__ float g_dcn[B_*C_ *HW];   // lrelu(deform conv) == pre == x
__device__ float g_col[B_*C9 *HW];   // deform im2col columns [b][j][p]
__device__ float g_wt [C9*C_];       // dcn weights transposed [j][co]
__device__ float g_wta[C9*C_];       // a0 weights transposed [ci*9+k][co]
__device__ float g_wtf[C9*C_];       // fus weights transposed [ci*9+k][co]
__device__ float g_wt3[C_*C9];       // a3 weights transposed [ci][co576]
__device__ float g_wto[CIN*KK_*OCM]; // offm weights transposed [ci*9+k][co216]
__device__ float g_x0 [B_*C_ *HW];   // a0 conv out
__device__ float g_x1d[B_*C_ *HW];   // depthwise out (+eca folded in)
__device__ float g_out[B_*C_ *HW];   // dynamic-filter out (lrelu'd)
__device__ float g_s  [B_*C_];       // channel means of x0
__device__ float g_eca[B_*C_];       // eca values

__device__ __forceinline__ unsigned f2tf32(float v) {
    unsigned t;
    asm("cvt.rna.tf32.f32 %0, %1;" : "=r"(t) : "f"(v));
    return t;
}

#define APAD 136
#define BPAD 72
#define TW 132

// ---------------- 1: conv0 1x1, 32->64 : 4px x 16co tiling ------------------
__global__ void __launch_bounds__(256, 2) conv0_k(
        const float* __restrict__ x, const float* __restrict__ w,
        const float* __restrict__ bias) {
    __shared__ __align__(16) float ws[CIN*C_];   // [ci][co]
    int tid = threadIdx.x;
    int quad = tid & 63, cg = tid >> 6;
    for (int i = tid; i < C_*CIN; i += 256) {
        int ci = i >> 6, co = i & 63;
        ws[ci*C_ + co] = w[co*CIN + ci];
    }
    __syncthreads();
    int b = blockIdx.y;
    int p0 = blockIdx.x*256 + quad*4;
    const float* xb = x + (size_t)b*CIN*HW + p0;
    float acc[64];
#pragma unroll
    for (int c = 0; c < 16; c++) {
        float bv = __ldg(bias + cg*16 + c);
        acc[c*4+0] = bv; acc[c*4+1] = bv; acc[c*4+2] = bv; acc[c*4+3] = bv;
    }
    for (int ci = 0; ci < CIN; ci++) {
        float4 v = *(const float4*)(xb + (size_t)ci*HW);
        const float4* w4 = (const float4*)(ws + ci*C_ + cg*16);
#pragma unroll
        for (int q = 0; q < 4; q++) {
            float4 wv = w4[q];
            float wr[4] = {wv.x, wv.y, wv.z, wv.w};
#pragma unroll
            for (int r = 0; r < 4; r++) {
                float wc = wr[r];
                float* a = acc + (q*4+r)*4;
                a[0] += wc*v.x; a[1] += wc*v.y; a[2] += wc*v.z; a[3] += wc*v.w;
            }
        }
    }
    float* ob = g_x1 + (size_t)b*C_*HW + p0;
#pragma unroll
    for (int c = 0; c < 16; c++)
        *(float4*)(ob + (size_t)(cg*16+c)*HW) =
            make_float4(acc[c*4+0], acc[c*4+1], acc[c*4+2], acc[c*4+3]);
}

// ---------------- transposes ------------------------------------------------
__global__ void wtr_k(const float* __restrict__ w, int which) {
    int i = blockIdx.x*256 + threadIdx.x;   // i < C9*C_
    int co = i & 63, j = i >> 6;
    float v = w[co*C9 + j];
    if (which == 0)      g_wt [i] = v;
    else if (which == 1) g_wta[i] = v;
    else                 g_wtf[i] = v;
}
__global__ void wtr3_k(const float* __restrict__ w) {
    int i = blockIdx.x*256 + threadIdx.x;   // i < C_*C9: i = ci*C9+co
    int co = i % C9, ci = i / C9;
    g_wt3[i] = w[co*C_ + ci];
}
__global__ void wtro_k(const float* __restrict__ w) {
    int i = blockIdx.x*256 + threadIdx.x;   // i < CIN*KK*OCM
    if (i >= CIN*KK_*OCM) return;
    int co = i % OCM, cik = i / OCM;
    int ci = cik / KK_, k = cik % KK_;
    g_wto[i] = w[(co*CIN + ci)*KK_ + k];
}

// ---------------- 2: offm conv 3x3 32->216 via tf32 mma --------------------
// grid (H_, B_, 3): row h, co-chunk of 72. K = 4 ci-chunks of 8, 9 shifts.
__global__ void __launch_bounds__(256, 2) offmtc_k(
        const float* __restrict__ in, const float* __restrict__ bias) {
    __shared__ __align__(16) float raw[8*3*TW];    // [ci8][row3][col132]
    __shared__ __align__(16) float Bs[9*8*BPAD];   // [k9][ci8][co72]
    int tid = threadIdx.x, lane = tid & 31, wid = tid >> 5;
    int h = blockIdx.x, b = blockIdx.y;
    int co0 = blockIdx.z*72;
    const float* ib = in + (size_t)b*CIN*HW;
    float d[9][4];
#pragma unroll
    for (int n = 0; n < 9; n++)
#pragma unroll
        for (int r = 0; r < 4; r++) d[n][r] = 0.f;

    for (int cc = 0; cc < 4; cc++) {
        __syncthreads();
        for (int i = tid; i < 8*3*TW; i += 256) {
            int ci = i/(3*TW);
            int r  = (i/TW)%3;
            int t  = i%TW;
            int row = h + r - 1, col = t - 1;
            float v = 0.f;
            if (t < 130 && row >= 0 && row < H_ && col >= 0 && col < W_)
                v = __ldg(ib + (size_t)(cc*8+ci)*HW + row*W_ + col);
            raw[i] = v;
        }
        for (int i = tid; i < 9*8*72; i += 256) {
            int ks = i/(8*72);
            int ci = (i/72)%8;
            int co = i%72;
            Bs[(ks*8+ci)*BPAD + co] =
                __ldg(g_wto + (size_t)((cc*8+ci)*KK_ + ks)*OCM + co0 + co);
        }
        __syncthreads();
#pragma unroll
        for (int ks = 0; ks < KK_; ks++) {
            int ky = ks/3, kx = ks%3;
            int abase = ((lane&3)*3 + ky)*TW + wid*16 + (lane>>2) + kx;
            unsigned a0 = f2tf32(raw[abase]);
            unsigned a1 = f2tf32(raw[abase + 8]);
            unsigned a2 = f2tf32(raw[abase + 4*3*TW]);
            unsigned a3 = f2tf32(raw[abase + 4*3*TW + 8]);
#pragma unroll
            for (int n = 0; n < 9; n++) {
                unsigned b0 = f2tf32(Bs[(ks*8 + (lane&3))*BPAD + n*8 + (lane>>2)]);
                unsigned b1 = f2tf32(Bs[(ks*8 + (lane&3)+4)*BPAD + n*8 + (lane>>2)]);
                asm volatile(
                    "mma.sync.aligned.m16n8k8.row.col.f32.tf32.tf32.f32 "
                    "{%0,%1,%2,%3}, {%4,%5,%6,%7}, {%8,%9}, {%0,%1,%2,%3};"
                    : "+f"(d[n][0]), "+f"(d[n][1]), "+f"(d[n][2]), "+f"(d[n][3])
                    : "r"(a0), "r"(a1), "r"(a2), "r"(a3), "r"(b0), "r"(b1));
            }
        }
    }
    int prow = h*W_ + wid*16 + (lane >> 2);
    float* ob = g_om + (size_t)b*OCM*HW;
#pragma unroll
    for (int n = 0; n < 9; n++) {
        int co = co0 + n*8 + (lane & 3)*2;
        float b0v = __ldg(bias + co), b1v = __ldg(bias + co + 1);
        ob[(size_t)co*HW     + prow]     = d[n][0] + b0v;
        ob[(size_t)(co+1)*HW + prow]     = d[n][1] + b1v;
        ob[(size_t)co*HW     + prow + 8] = d[n][2] + b0v;
        ob[(size_t)(co+1)*HW + prow + 8] = d[n][3] + b1v;
    }
}

// ---------------- 3: deform im2col (bilinear, modulated) -------------------
__global__ void __launch_bounds__(256, 2) col_k() {
    int tid = threadIdx.x;
    int p = blockIdx.x*256 + tid;
    int gk = blockIdx.y;                 // g*9+k, 0..71
    int g = gk/9, k = gk%9;
    int b = blockIdx.z;
    int h = p >> 7, wq = p & 127;
    const float* omb = g_om + (size_t)b*OCM*HW;
    float dy = omb[(       g*9+k)*HW + p];
    float dx = omb[( 72 +  g*9+k)*HW + p];
    float mk = omb[(144 +  g*9+k)*HW + p];
    mk = 1.f/(1.f + expf(-mk));
    float py = dy + (float)(k/3) + (float)h - 1.f;
    float px = dx + (float)(k%3) + (float)wq - 1.f;
    float fy = floorf(py), fx = floorf(px);
    int y0 = (int)fy, x0 = (int)fx;
    float wy = py - fy, wx = px - fx;
    float w00 = (1.f-wy)*(1.f-wx)*mk;
    float w01 = (1.f-wy)*wx*mk;
    float w10 = wy*(1.f-wx)*mk;
    float w11 = wy*wx*mk;
    bool iy0 = (y0 >= 0 && y0 < H_);
    bool iy1 = (y0+1 >= 0 && y0+1 < H_);
    bool ix0 = (x0 >= 0 && x0 < W_);
    bool ix1 = (x0+1 >= 0 && x0+1 < W_);
    bool v00 = iy0 && ix0, v01 = iy0 && ix1, v10 = iy1 && ix0, v11 = iy1 && ix1;
    int i00 = y0*W_ + x0;
    const float* xb = g_x1 + (size_t)b*C_*HW + (size_t)g*CPG*HW;
    float* cb = g_col + (size_t)b*C9*HW + (size_t)(g*CPG*KK_ + k)*HW + p;
#pragma unroll
    for (int c = 0; c < CPG; c++) {
        const float* xc = xb + c*HW;
        float s = 0.f;
        if (v00) s += w00*__ldg(xc + i00);
        if (v01) s += w01*__ldg(xc + i00 + 1);
        if (v10) s += w10*__ldg(xc + i00 + W_);
        if (v11) s += w11*__ldg(xc + i00 + W_ + 1);
        cb[(size_t)c*KK_*HW] = s;
    }
}

// ---------------- 4: dcn GEMM via tf32 mma.sync + lrelu --------------------
__global__ void __launch_bounds__(256, 2) dcntc_k(const float* __restrict__ bias) {
    __shared__ __align__(16) float As[32*APAD];   // [j][p] k-chunk x 128px
    __shared__ __align__(16) float Bs[32*BPAD];   // [j][co]
    int tid = threadIdx.x, lane = tid & 31, wid = tid >> 5;
    int b = blockIdx.y;
    int p0 = blockIdx.x*128;
    const float* cb = g_col + (size_t)b*C9*HW + p0;
    float d[8][4];
#pragma unroll
    for (int n = 0; n < 8; n++)
#pragma unroll
        for (int r = 0; r < 4; r++) d[n][r] = 0.f;

    for (int kc = 0; kc < C9/32; kc++) {
        const float* src = cb + (size_t)kc*32*HW;
#pragma unroll
        for (int r = 0; r < 4; r++) {
            int i4 = tid + r*256;
            int row = i4 >> 5, c4 = i4 & 31;
            float4 v = *(const float4*)(src + (size_t)row*HW + c4*4);
            *(float4*)(As + row*APAD + c4*4) = v;
        }
#pragma unroll
        for (int r = 0; r < 2; r++) {
            int i4 = tid + r*256;
            int row = i4 >> 4, c4 = i4 & 15;
            float4 v = *(const float4*)(g_wt + (size_t)(kc*32+row)*C_ + c4*4);
            *(float4*)(Bs + row*BPAD + c4*4) = v;
        }
        __syncthreads();
#pragma unroll
        for (int ks = 0; ks < 4; ks++) {
            int j0 = ks*8 + (lane & 3);
            int pa = wid*16 + (lane >> 2);
            unsigned a0 = f2tf32(As[j0*APAD + pa]);
            unsigned a1 = f2tf32(As[j0*APAD + pa + 8]);
            unsigned a2 = f2tf32(As[(j0+4)*APAD + pa]);
            unsigned a3 = f2tf32(As[(j0+4)*APAD + pa + 8]);
#pragma unroll
            for (int n = 0; n < 8; n++) {
                unsigned b0 = f2tf32(Bs[j0*BPAD + n*8 + (lane >> 2)]);
                unsigned b1 = f2tf32(Bs[(j0+4)*BPAD + n*8 + (lane >> 2)]);
                asm volatile(
                    "mma.sync.aligned.m16n8k8.row.col.f32.tf32.tf32.f32 "
                    "{%0,%1,%2,%3}, {%4,%5,%6,%7}, {%8,%9}, {%0,%1,%2,%3};"
                    : "+f"(d[n][0]), "+f"(d[n][1]), "+f"(d[n][2]), "+f"(d[n][3])
                    : "r"(a0), "r"(a1), "r"(a2), "r"(a3), "r"(b0), "r"(b1));
            }
        }
        __syncthreads();
    }
    int prow = p0 + wid*16 + (lane >> 2);
    float* ob = g_dcn + (size_t)b*C_*HW;
#pragma unroll
    for (int n = 0; n < 8; n++) {
        int co = n*8 + (lane & 3)*2;
        float b0v = __ldg(bias + co), b1v = __ldg(bias + co + 1);
        float v0 = d[n][0] + b0v, v1 = d[n][1] + b1v;
        float v2 = d[n][2] + b0v, v3 = d[n][3] + b1v;
        v0 = (v0 >= 0.f) ? v0 : 0.2f*v0;
        v1 = (v1 >= 0.f) ? v1 : 0.2f*v1;
        v2 = (v2 >= 0.f) ? v2 : 0.2f*v2;
        v3 = (v3 >= 0.f) ? v3 : 0.2f*v3;
        ob[(size_t)co*HW     + prow]     = v0;
        ob[(size_t)(co+1)*HW + prow]     = v1;
        ob[(size_t)co*HW     + prow + 8] = v2;
        ob[(size_t)(co+1)*HW + prow + 8] = v3;
    }
}

// ---------------- 5: conv3x3 64->64 via tf32 mma (implicit GEMM) -----------
template <int FUSE>
__device__ __forceinline__ void conv3tc_body(
        const float* __restrict__ in, const float* __restrict__ wt,
        const float* __restrict__ bias, const float* __restrict__ pre,
        float* __restrict__ outp) {
    __shared__ __align__(16) float raw[8*3*TW];    // [ci8][row3][col132]
    __shared__ __align__(16) float Bs[9*8*BPAD];   // [k9][ci8][co72]
    int tid = threadIdx.x, lane = tid & 31, wid = tid >> 5;
    int h = blockIdx.x;
    float d[8][4];
#pragma unroll
    for (int n = 0; n < 8; n++)
#pragma unroll
        for (int r = 0; r < 4; r++) d[n][r] = 0.f;

    for (int cc = 0; cc < 8; cc++) {
        __syncthreads();
        for (int i = tid; i < 8*3*TW; i += 256) {
            int ci = i/(3*TW);
            int r  = (i/TW)%3;
            int t  = i%TW;
            int row = h + r - 1, col = t - 1;
            float v = 0.f;
            if (t < 130 && row >= 0 && row < H_ && col >= 0 && col < W_)
                v = __ldg(in + (size_t)(cc*8+ci)*HW + row*W_ + col);
            raw[i] = v;
        }
        for (int i = tid; i < 9*8*C_; i += 256) {
            int ks = i/(8*C_);
            int ci = (i/C_)%8;
            int co = i & 63;
            Bs[(ks*8+ci)*BPAD + co] = __ldg(wt + (size_t)((cc*8+ci)*KK_ + ks)*C_ + co);
        }
        __syncthreads();
#pragma unroll
        for (int ks = 0; ks < KK_; ks++) {
            int ky = ks/3, kx = ks%3;
            int abase = ((lane&3)*3 + ky)*TW + wid*16 + (lane>>2) + kx;
            unsigned a0 = f2tf32(raw[abase]);
            unsigned a1 = f2tf32(raw[abase + 8]);
            unsigned a2 = f2tf32(raw[abase + 4*3*TW]);
            unsigned a3 = f2tf32(raw[abase + 4*3*TW + 8]);
#pragma unroll
            for (int n = 0; n < 8; n++) {
                unsigned b0 = f2tf32(Bs[(ks*8 + (lane&3))*BPAD + n*8 + (lane>>2)]);
                unsigned b1 = f2tf32(Bs[(ks*8 + (lane&3)+4)*BPAD + n*8 + (lane>>2)]);
                asm volatile(
                    "mma.sync.aligned.m16n8k8.row.col.f32.tf32.tf32.f32 "
                    "{%0,%1,%2,%3}, {%4,%5,%6,%7}, {%8,%9}, {%0,%1,%2,%3};"
                    : "+f"(d[n][0]), "+f"(d[n][1]), "+f"(d[n][2]), "+f"(d[n][3])
                    : "r"(a0), "r"(a1), "r"(a2), "r"(a3), "r"(b0), "r"(b1));
            }
        }
    }
    int prow = h*W_ + wid*16 + (lane >> 2);
#pragma unroll
    for (int n = 0; n < 8; n++) {
        int co = n*8 + (lane & 3)*2;
        float b0v = __ldg(bias + co), b1v = __ldg(bias + co + 1);
        float v0 = d[n][0] + b0v, v1 = d[n][1] + b1v;
        float v2 = d[n][2] + b0v, v3 = d[n][3] + b1v;
        if (FUSE) {
            v0 += 2.f*__ldg(pre + (size_t)co*HW     + prow);
            v1 += 2.f*__ldg(pre + (size_t)(co+1)*HW + prow);
            v2 += 2.f*__ldg(pre + (size_t)co*HW     + prow + 8);
            v3 += 2.f*__ldg(pre + (size_t)(co+1)*HW + prow + 8);
        }
        outp[(size_t)co*HW     + prow]     = v0;
        outp[(size_t)(co+1)*HW + prow]     = v1;
        outp[(size_t)co*HW     + prow + 8] = v2;
        outp[(size_t)(co+1)*HW + prow + 8] = v3;
    }
}

__global__ void __launch_bounds__(256, 2) conv_a0tc_k(const float* __restrict__ bias) {
    int b = blockIdx.y;
    conv3tc_body<0>(g_dcn + (size_t)b*C_*HW, g_wta, bias, nullptr,
                    g_x0 + (size_t)b*C_*HW);
}

__global__ void __launch_bounds__(256, 2) conv_fustc_k(
        const float* __restrict__ bias, float* __restrict__ out) {
    int b = blockIdx.y;
    conv3tc_body<1>(g_out + (size_t)b*C_*HW, g_wtf, bias,
                    g_dcn + (size_t)b*C_*HW, out + (size_t)b*C_*HW);
}

// ---------------- 6: depthwise 3x3 on g_x0 -> g_x1d (+eca) -----------------
__global__ void __launch_bounds__(256, 4) dw_k(
        const float* __restrict__ w, const float* __restrict__ bias) {
    int tid = threadIdx.x;
    int c = blockIdx.y, b = blockIdx.z;
    int p = blockIdx.x*256 + tid;
    int h = p >> 7, wq = p & 127;
    const float* ic = g_x0 + ((size_t)b*C_ + c)*HW;
    float acc = bias[c] + g_eca[b*C_ + c];
#pragma unroll
    for (int ky = 0; ky < 3; ky++) {
        int hy = h + ky - 1;
        bool oky = (hy >= 0 && hy < H_);
#pragma unroll
        for (int kx = 0; kx < 3; kx++) {
            int wx = wq + kx - 1;
            float v = (oky && wx >= 0 && wx < W_) ? __ldg(ic + hy*W_ + wx) : 0.f;
            acc += __ldg(w + c*KK_ + ky*3+kx)*v;
        }
    }
    g_x1d[((size_t)b*C_ + c)*HW + p] = acc;
}

// ---------------- 7: per-(b,c) mean of g_x0 --------------------------------
__global__ void mean_k() {
    __shared__ float sd[256];
    int bc = blockIdx.x;
    const float* ic = g_x0 + (size_t)bc*HW;
    float s = 0.f;
    for (int i = threadIdx.x; i < HW; i += 256) s += ic[i];
    sd[threadIdx.x] = s;
    __syncthreads();
    for (int st = 128; st > 0; st >>= 1) {
        if (threadIdx.x < st) sd[threadIdx.x] += sd[threadIdx.x+st];
        __syncthreads();
    }
    if (threadIdx.x == 0) g_s[bc] = sd[0]*(1.f/(float)HW);
}

// ---------------- 8: ECA 1D conv over channels -----------------------------
__global__ void eca_k(const float* __restrict__ w2, const float* __restrict__ b2) {
    int i = threadIdx.x;
    if (i >= B_*C_) return;
    int c = i & 63;
    float sm1 = (c > 0)  ? g_s[i-1] : 0.f;
    float s0  = g_s[i];
    float sp1 = (c < 63) ? g_s[i+1] : 0.f;
    g_eca[i] = w2[0]*sm1 + w2[1]*s0 + w2[2]*sp1 + b2[0];
}

// ---------------- 9: a3 1x1 (64->576) via tf32 mma + dyn filter + lrelu ----
// grid (H_, B_, 8): row h, c-chunk cc (8 channels = 72 filt values).
__global__ void __launch_bounds__(256, 2) a3tc_k(const float* __restrict__ bias) {
    // buf carved: phase 1: As[32*APAD]=4352 + Bs[32*72]=2304 (6656 floats)
    //             phase 2/3: filt[72*TW]=9504 floats
    __shared__ __align__(16) float buf[72*TW];
    float* As = buf;
    float* Bs = buf + 32*APAD;
    int tid = threadIdx.x, lane = tid & 31, wid = tid >> 5;
    int h = blockIdx.x, b = blockIdx.y;
    int cc = blockIdx.z;
    int co0 = cc*72;
    const float* inb = g_x1d + (size_t)b*C_*HW + h*W_;
    float d[9][4];
#pragma unroll
    for (int n = 0; n < 9; n++)
#pragma unroll
        for (int r = 0; r < 4; r++) d[n][r] = 0.f;

    for (int kc = 0; kc < 2; kc++) {
        __syncthreads();
#pragma unroll
        for (int r = 0; r < 4; r++) {
            int i4 = tid + r*256;
            int row = i4 >> 5, c4 = i4 & 31;
            float4 v = *(const float4*)(inb + (size_t)(kc*32+row)*HW + c4*4);
            *(float4*)(As + row*APAD + c4*4) = v;
        }
        for (int i = tid; i < 32*72; i += 256) {
            int row = i/72, co = i%72;
            Bs[i] = __ldg(g_wt3 + (size_t)(kc*32+row)*C9 + co0 + co);
        }
        __syncthreads();
#pragma unroll
        for (int ks = 0; ks < 4; ks++) {
            int j0 = ks*8 + (lane & 3);
            int pa = wid*16 + (lane >> 2);
            unsigned a0 = f2tf32(As[j0*APAD + pa]);
            unsigned a1 = f2tf32(As[j0*APAD + pa + 8]);
            unsigned a2 = f2tf32(As[(j0+4)*APAD + pa]);
            unsigned a3 = f2tf32(As[(j0+4)*APAD + pa + 8]);
#pragma unroll
            for (int n = 0; n < 9; n++) {
                unsigned b0 = f2tf32(Bs[j0*72 + n*8 + (lane >> 2)]);
                unsigned b1 = f2tf32(Bs[(j0+4)*72 + n*8 + (lane >> 2)]);
                asm volatile(
                    "mma.sync.aligned.m16n8k8.row.col.f32.tf32.tf32.f32 "
                    "{%0,%1,%2,%3}, {%4,%5,%6,%7}, {%8,%9}, {%0,%1,%2,%3};"
                    : "+f"(d[n][0]), "+f"(d[n][1]), "+f"(d[n][2]), "+f"(d[n][3])
                    : "r"(a0), "r"(a1), "r"(a2), "r"(a3), "r"(b0), "r"(b1));
            }
        }
    }
    // write filt to smem (reuse buf): filt[co72][px TW]
    __syncthreads();
    float* filt = buf;
    int px = wid*16 + (lane >> 2);
#pragma unroll
    for (int n = 0; n < 9; n++) {
        int co = n*8 + (lane & 3)*2;
        float b0v = __ldg(bias + co0 + co), b1v = __ldg(bias + co0 + co + 1);
        filt[co*TW     + px]     = d[n][0] + b0v;
        filt[(co+1)*TW + px]     = d[n][1] + b1v;
        filt[co*TW     + px + 8] = d[n][2] + b0v;
        filt[(co+1)*TW + px + 8] = d[n][3] + b1v;
    }
    __syncthreads();
    // phase 3: apply 3x3 dynamic filter over x0 channels cc*8..cc*8+7
    int p  = tid & 127;
    int c80 = tid >> 7;                  // 0 or 1
    const float* x0b = g_x0 + (size_t)b*C_*HW;
    float* ob = g_out + (size_t)b*C_*HW + h*W_;
#pragma unroll
    for (int cq = 0; cq < 4; cq++) {
        int c8 = c80 + cq*2;
        int c = cc*8 + c8;
        const float* ic = x0b + (size_t)c*HW;
        float v[9];
#pragma unroll
        for (int ky = 0; ky < 3; ky++) {
            int hy = h + ky - 1;
            bool oy = (hy >= 0 && hy < H_);
            const float* icr = ic + hy*W_;
#pragma unroll
            for (int kx = 0; kx < 3; kx++) {
                int wx = p + kx - 1;
                v[ky*3+kx] = (oy && wx >= 0 && wx < W_) ? __ldg(icr + wx) : 0.f;
            }
        }
        float o = 0.f;
#pragma unroll
        for (int k = 0; k < KK_; k++)
            o += filt[(c8*KK_+k)*TW + p]*v[k];
        o = (o >= 0.f) ? o : 0.2f*o;
        ob[(size_t)c*HW + p] = o;
    }
}

// ---------------- launch ----------------------------------------------------
extern "C" void kernel_launch(void* const* d_in, const int* in_sizes, int n_in,
                              void* d_out, int out_size) {
    const float* x       = (const float*)d_in[0];
    const float* offset  = (const float*)d_in[1];
    const float* conv0_w = (const float*)d_in[2];
    const float* conv0_b = (const float*)d_in[3];
    const float* offm_w  = (const float*)d_in[4];
    const float* offm_b  = (const float*)d_in[5];
    const float* dcn_w   = (const float*)d_in[6];
    const float* dcn_b   = (const float*)d_in[7];
    const float* a0_w    = (const float*)d_in[8];
    const float* a0_b    = (const float*)d_in[9];
    const float* a1_w    = (const float*)d_in[10];
    const float* a1_b    = (const float*)d_in[11];
    const float* a2_w    = (const float*)d_in[12];
    const float* a2_b    = (const float*)d_in[13];
    const float* a3_w    = (const float*)d_in[14];
    const float* a3_b    = (const float*)d_in[15];
    const float* fus_w   = (const float*)d_in[16];
    const float* fus_b   = (const float*)d_in[17];
    float* out = (float*)d_out;

    dim3 gp(HW/256, B_);
    wtr_k    <<<C9*C_/256, 256>>>(dcn_w, 0);
    wtr_k    <<<C9*C_/256, 256>>>(a0_w, 1);
    wtr_k    <<<C9*C_/256, 256>>>(fus_w, 2);
    wtr3_k   <<<C_*C9/256, 256>>>(a3_w);
    wtro_k   <<<(CIN*KK_*OCM + 255)/256, 256>>>(offm_w);
    conv0_k  <<<gp, 256>>>(x, conv0_w, conv0_b);
    offmtc_k <<<dim3(H_, B_, 3), 256>>>(offset, offm_b);
    col_k    <<<dim3(HW/256, DG_*KK_, B_), 256>>>();
    dcntc_k  <<<dim3(HW/128, B_), 256>>>(dcn_b);
    conv_a0tc_k<<<dim3(H_, B_), 256>>>(a0_b);
    mean_k   <<<B_*C_, 256>>>();
    eca_k    <<<1, 256>>>(a2_w, a2_b);
    dw_k     <<<dim3(HW/256, C_, B_), 256>>>(a1_w, a1_b);
    a3tc_k   <<<dim3(H_, B_, 8), 256>>>(a3_b);
    conv_fustc_k<<<dim3(H_, B_), 256>>>(fus_b, out);
}

// round 11
// speedup vs baseline: 1.8945x; 1.0645x over previous
#include <cuda_runtime.h>
#include <cuda_bf16.h>
#include <cuda_fp16.h>
#include <math.h>

// Problem constants
#define B_   4
#define CIN  32
#define C_   64
#define H_   128
#define W_   128
#define HW   16384
#define DG_  8
#define CPG  8
#define KK_  9
#define OCM  216   // DG*3*K*K
#define C9   576   // C*9
#define C9P  288   // C9/2 packed rows

// ---------------- scratch (device globals; no allocation allowed) ----------
__device__ float g_x1 [B_*C_ *HW];    // conv0 out
__device__ float g_om [B_*OCM*HW];    // offset/mask conv out
__device__ float g_dcn[B_*C_ *HW];    // lrelu(deform conv) == pre == x
__device__ unsigned g_colp[B_*C9P*HW]; // packed half2 im2col [b][jp][p]
__device__ unsigned g_wtp[C9P*C_];    // dcn weights packed half2 [jp][co]
__device__ float g_wta[C9*C_];        // a0 weights transposed [ci*9+k][co]
__device__ float g_wtf[C9*C_];        // fus weights transposed [ci*9+k][co]
__device__ float g_wt3[C_*C9];        // a3 weights transposed [ci][co576]
__device__ float g_wto[CIN*KK_*OCM];  // offm weights transposed [ci*9+k][co216]
__device__ float g_x0 [B_*C_ *HW];    // a0 conv out
__device__ float g_x1d[B_*C_ *HW];    // depthwise out (+eca folded in)
__device__ float g_out[B_*C_ *HW];    // dynamic-filter out (lrelu'd)
__device__ float g_s  [B_*C_];        // channel means of x0
__device__ float g_eca[B_*C_];        // eca values

__device__ __forceinline__ unsigned f2tf32(float v) {
    unsigned t;
    asm("cvt.rna.tf32.f32 %0, %1;" : "=r"(t) : "f"(v));
    return t;
}
__device__ __forceinline__ unsigned packh2(float a, float b) {
    __half2 h = __floats2half2_rn(a, b);
    return *(unsigned*)&h;
}

#define APAD 136
#define BPAD 72
#define TW 132

// ---------------- 1: conv0 1x1, 32->64 : 4px x 16co tiling ------------------
__global__ void __launch_bounds__(256, 2) conv0_k(
        const float* __restrict__ x, const float* __restrict__ w,
        const float* __restrict__ bias) {
    __shared__ __align__(16) float ws[CIN*C_];   // [ci][co]
    int tid = threadIdx.x;
    int quad = tid & 63, cg = tid >> 6;
    for (int i = tid; i < C_*CIN; i += 256) {
        int ci = i >> 6, co = i & 63;
        ws[ci*C_ + co] = w[co*CIN + ci];
    }
    __syncthreads();
    int b = blockIdx.y;
    int p0 = blockIdx.x*256 + quad*4;
    const float* xb = x + (size_t)b*CIN*HW + p0;
    float acc[64];
#pragma unroll
    for (int c = 0; c < 16; c++) {
        float bv = __ldg(bias + cg*16 + c);
        acc[c*4+0] = bv; acc[c*4+1] = bv; acc[c*4+2] = bv; acc[c*4+3] = bv;
    }
    for (int ci = 0; ci < CIN; ci++) {
        float4 v = *(const float4*)(xb + (size_t)ci*HW);
        const float4* w4 = (const float4*)(ws + ci*C_ + cg*16);
#pragma unroll
        for (int q = 0; q < 4; q++) {
            float4 wv = w4[q];
            float wr[4] = {wv.x, wv.y, wv.z, wv.w};
#pragma unroll
            for (int r = 0; r < 4; r++) {
                float wc = wr[r];
                float* a = acc + (q*4+r)*4;
                a[0] += wc*v.x; a[1] += wc*v.y; a[2] += wc*v.z; a[3] += wc*v.w;
            }
        }
    }
    float* ob = g_x1 + (size_t)b*C_*HW + p0;
#pragma unroll
    for (int c = 0; c < 16; c++)
        *(float4*)(ob + (size_t)(cg*16+c)*HW) =
            make_float4(acc[c*4+0], acc[c*4+1], acc[c*4+2], acc[c*4+3]);
}

// ---------------- all weight transposes in ONE launch ----------------------
// [0,18432): g_wtp packed; [18432,55296): wta; [55296,92160): wtf;
// [92160,129024): wt3; [129024,191232): wto
__global__ void wtrall_k(const float* __restrict__ dcn_w,
                         const float* __restrict__ a0_w,
                         const float* __restrict__ fus_w,
                         const float* __restrict__ a3_w,
                         const float* __restrict__ offm_w) {
    int i = blockIdx.x*256 + threadIdx.x;
    if (i < 18432) {
        // g_wtp: jp = g*36 + k*4 + ip packs (c=2ip, 2ip+1) for (g,k), col co
        int jp = i >> 6, co = i & 63;
        int g = jp/36, r = jp%36, k = r/4, ip = r%4;
        int c0 = ip*2;
        float v0 = dcn_w[co*C9 + g*72 + c0*9 + k];
        float v1 = dcn_w[co*C9 + g*72 + (c0+1)*9 + k];
        g_wtp[i] = packh2(v0, v1);
    } else if (i < 55296) {
        int t = i - 18432;
        int co = t & 63, j = t >> 6;
        g_wta[t] = a0_w[co*C9 + j];
    } else if (i < 92160) {
        int t = i - 55296;
        int co = t & 63, j = t >> 6;
        g_wtf[t] = fus_w[co*C9 + j];
    } else if (i < 129024) {
        int t = i - 92160;
        int co = t % C9, ci = t / C9;
        g_wt3[t] = a3_w[co*C_ + ci];
    } else if (i < 191232) {
        int t = i - 129024;
        int co = t % OCM, cik = t / OCM;
        int ci = cik / KK_, k = cik % KK_;
        g_wto[t] = offm_w[(co*CIN + ci)*KK_ + k];
    }
}

// ---------------- 2: offm conv 3x3 32->216 via tf32 mma --------------------
__global__ void __launch_bounds__(256, 2) offmtc_k(
        const float* __restrict__ in, const float* __restrict__ bias) {
    __shared__ __align__(16) float raw[8*3*TW];    // [ci8][row3][col132]
    __shared__ __align__(16) float Bs[9*8*BPAD];   // [k9][ci8][co72]
    int tid = threadIdx.x, lane = tid & 31, wid = tid >> 5;
    int h = blockIdx.x, b = blockIdx.y;
    int co0 = blockIdx.z*72;
    const float* ib = in + (size_t)b*CIN*HW;
    float d[9][4];
#pragma unroll
    for (int n = 0; n < 9; n++)
#pragma unroll
        for (int r = 0; r < 4; r++) d[n][r] = 0.f;

    for (int cc = 0; cc < 4; cc++) {
        __syncthreads();
        for (int i = tid; i < 8*3*TW; i += 256) {
            int ci = i/(3*TW);
            int r  = (i/TW)%3;
            int t  = i%TW;
            int row = h + r - 1, col = t - 1;
            float v = 0.f;
            if (t < 130 && row >= 0 && row < H_ && col >= 0 && col < W_)
                v = __ldg(ib + (size_t)(cc*8+ci)*HW + row*W_ + col);
            raw[i] = v;
        }
        for (int i = tid; i < 9*8*72; i += 256) {
            int ks = i/(8*72);
            int ci = (i/72)%8;
            int co = i%72;
            Bs[(ks*8+ci)*BPAD + co] =
                __ldg(g_wto + (size_t)((cc*8+ci)*KK_ + ks)*OCM + co0 + co);
        }
        __syncthreads();
#pragma unroll
        for (int ks = 0; ks < KK_; ks++) {
            int ky = ks/3, kx = ks%3;
            int abase = ((lane&3)*3 + ky)*TW + wid*16 + (lane>>2) + kx;
            unsigned a0 = f2tf32(raw[abase]);
            unsigned a1 = f2tf32(raw[abase + 8]);
            unsigned a2 = f2tf32(raw[abase + 4*3*TW]);
            unsigned a3 = f2tf32(raw[abase + 4*3*TW + 8]);
#pragma unroll
            for (int n = 0; n < 9; n++) {
                unsigned b0 = f2tf32(Bs[(ks*8 + (lane&3))*BPAD + n*8 + (lane>>2)]);
                unsigned b1 = f2tf32(Bs[(ks*8 + (lane&3)+4)*BPAD + n*8 + (lane>>2)]);
                asm volatile(
                    "mma.sync.aligned.m16n8k8.row.col.f32.tf32.tf32.f32 "
                    "{%0,%1,%2,%3}, {%4,%5,%6,%7}, {%8,%9}, {%0,%1,%2,%3};"
                    : "+f"(d[n][0]), "+f"(d[n][1]), "+f"(d[n][2]), "+f"(d[n][3])
                    : "r"(a0), "r"(a1), "r"(a2), "r"(a3), "r"(b0), "r"(b1));
            }
        }
    }
    int prow = h*W_ + wid*16 + (lane >> 2);
    float* ob = g_om + (size_t)b*OCM*HW;
#pragma unroll
    for (int n = 0; n < 9; n++) {
        int co = co0 + n*8 + (lane & 3)*2;
        float b0v = __ldg(bias + co), b1v = __ldg(bias + co + 1);
        ob[(size_t)co*HW     + prow]     = d[n][0] + b0v;
        ob[(size_t)(co+1)*HW + prow]     = d[n][1] + b1v;
        ob[(size_t)co*HW     + prow + 8] = d[n][2] + b0v;
        ob[(size_t)(co+1)*HW + prow + 8] = d[n][3] + b1v;
    }
}

// ---------------- 3: deform im2col -> packed half2, k-major c-pairs --------
__global__ void __launch_bounds__(256, 2) col_k() {
    int tid = threadIdx.x;
    int p = blockIdx.x*256 + tid;
    int gk = blockIdx.y;                 // g*9+k, 0..71
    int g = gk/9, k = gk%9;
    int b = blockIdx.z;
    int h = p >> 7, wq = p & 127;
    const float* omb = g_om + (size_t)b*OCM*HW;
    float dy = omb[(       g*9+k)*HW + p];
    float dx = omb[( 72 +  g*9+k)*HW + p];
    float mk = omb[(144 +  g*9+k)*HW + p];
    mk = 1.f/(1.f + expf(-mk));
    float py = dy + (float)(k/3) + (float)h - 1.f;
    float px = dx + (float)(k%3) + (float)wq - 1.f;
    float fy = floorf(py), fx = floorf(px);
    int y0 = (int)fy, x0 = (int)fx;
    float wy = py - fy, wx = px - fx;
    float w00 = (1.f-wy)*(1.f-wx)*mk;
    float w01 = (1.f-wy)*wx*mk;
    float w10 = wy*(1.f-wx)*mk;
    float w11 = wy*wx*mk;
    bool iy0 = (y0 >= 0 && y0 < H_);
    bool iy1 = (y0+1 >= 0 && y0+1 < H_);
    bool ix0 = (x0 >= 0 && x0 < W_);
    bool ix1 = (x0+1 >= 0 && x0+1 < W_);
    bool v00 = iy0 && ix0, v01 = iy0 && ix1, v10 = iy1 && ix0, v11 = iy1 && ix1;
    int i00 = y0*W_ + x0;
    const float* xb = g_x1 + (size_t)b*C_*HW + (size_t)g*CPG*HW;
    float s[CPG];
#pragma unroll
    for (int c = 0; c < CPG; c++) {
        const float* xc = xb + c*HW;
        float sv = 0.f;
        if (v00) sv += w00*__ldg(xc + i00);
        if (v01) sv += w01*__ldg(xc + i00 + 1);
        if (v10) sv += w10*__ldg(xc + i00 + W_);
        if (v11) sv += w11*__ldg(xc + i00 + W_ + 1);
        s[c] = sv;
    }
    // jp = g*36 + k*4 + i packs channels (2i, 2i+1)
    unsigned* cb = g_colp + (size_t)b*C9P*HW + (size_t)(g*36 + k*4)*HW + p;
#pragma unroll
    for (int i = 0; i < 4; i++)
        cb[(size_t)i*HW] = packh2(s[2*i], s[2*i+1]);
}

// ---------------- 4: dcn GEMM via fp16 m16n8k16 mma + lrelu ----------------
// CTA: 128 px (M) x 64 co (N). K=576 as 18 chunks of 16 packed rows.
#define A2PAD 136
__global__ void __launch_bounds__(256, 2) dcntc_k(const float* __restrict__ bias) {
    __shared__ __align__(16) unsigned As2[16*A2PAD];  // [jp][px]
    __shared__ __align__(16) unsigned Bs2[16*BPAD];   // [jp][co]
    int tid = threadIdx.x, lane = tid & 31, wid = tid >> 5;
    int b = blockIdx.y;
    int p0 = blockIdx.x*128;
    const unsigned* cb = g_colp + (size_t)b*C9P*HW + p0;
    float d[8][4];
#pragma unroll
    for (int n = 0; n < 8; n++)
#pragma unroll
        for (int r = 0; r < 4; r++) d[n][r] = 0.f;

    for (int kc = 0; kc < 18; kc++) {
        __syncthreads();
        // stage A: 16 jp-rows x 128 px (uint32 each)
#pragma unroll
        for (int r = 0; r < 2; r++) {
            int i4 = tid + r*256;               // 0..511
            int row = i4 >> 5, c4 = i4 & 31;
            uint4 v = *(const uint4*)(cb + (size_t)(kc*16+row)*HW + c4*4);
            *(uint4*)(As2 + row*A2PAD + c4*4) = v;
        }
        // stage B: 16 jp-rows x 64 co
        {
            int row = tid >> 4, c4 = tid & 15;
            uint4 v = *(const uint4*)(g_wtp + (size_t)(kc*16+row)*C_ + c4*4);
            *(uint4*)(Bs2 + row*BPAD + c4*4) = v;
        }
        __syncthreads();
#pragma unroll
        for (int ks = 0; ks < 2; ks++) {
            int jp0 = ks*8 + (lane & 3);
            int pa = wid*16 + (lane >> 2);
            unsigned a0 = As2[jp0*A2PAD + pa];
            unsigned a1 = As2[jp0*A2PAD + pa + 8];
            unsigned a2 = As2[(jp0+4)*A2PAD + pa];
            unsigned a3 = As2[(jp0+4)*A2PAD + pa + 8];
#pragma unroll
            for (int n = 0; n < 8; n++) {
                unsigned b0 = Bs2[jp0*BPAD + n*8 + (lane >> 2)];
                unsigned b1 = Bs2[(jp0+4)*BPAD + n*8 + (lane >> 2)];
                asm volatile(
                    "mma.sync.aligned.m16n8k16.row.col.f32.f16.f16.f32 "
                    "{%0,%1,%2,%3}, {%4,%5,%6,%7}, {%8,%9}, {%0,%1,%2,%3};"
                    : "+f"(d[n][0]), "+f"(d[n][1]), "+f"(d[n][2]), "+f"(d[n][3])
                    : "r"(a0), "r"(a1), "r"(a2), "r"(a3), "r"(b0), "r"(b1));
            }
        }
    }
    int prow = p0 + wid*16 + (lane >> 2);
    float* ob = g_dcn + (size_t)b*C_*HW;
#pragma unroll
    for (int n = 0; n < 8; n++) {
        int co = n*8 + (lane & 3)*2;
        float b0v = __ldg(bias + co), b1v = __ldg(bias + co + 1);
        float v0 = d[n][0] + b0v, v1 = d[n][1] + b1v;
        float v2 = d[n][2] + b0v, v3 = d[n][3] + b1v;
        v0 = (v0 >= 0.f) ? v0 : 0.2f*v0;
        v1 = (v1 >= 0.f) ? v1 : 0.2f*v1;
        v2 = (v2 >= 0.f) ? v2 : 0.2f*v2;
        v3 = (v3 >= 0.f) ? v3 : 0.2f*v3;
        ob[(size_t)co*HW     + prow]     = v0;
        ob[(size_t)(co+1)*HW + prow]     = v1;
        ob[(size_t)co*HW     + prow + 8] = v2;
        ob[(size_t)(co+1)*HW + prow + 8] = v3;
    }
}

// ---------------- 5: conv3x3 64->64 via tf32 mma (implicit GEMM) -----------
template <int FUSE>
__device__ __forceinline__ void conv3tc_body(
        const float* __restrict__ in, const float* __restrict__ wt,
        const float* __restrict__ bias, const float* __restrict__ pre,
        float* __restrict__ outp) {
    __shared__ __align__(16) float raw[8*3*TW];    // [ci8][row3][col132]
    __shared__ __align__(16) float Bs[9*8*BPAD];   // [k9][ci8][co72]
    int tid = threadIdx.x, lane = tid & 31, wid = tid >> 5;
    int h = blockIdx.x;
    float d[8][4];
#pragma unroll
    for (int n = 0; n < 8; n++)
#pragma unroll
        for (int r = 0; r < 4; r++) d[n][r] = 0.f;

    for (int cc = 0; cc < 8; cc++) {
        __syncthreads();
        for (int i = tid; i < 8*3*TW; i += 256) {
            int ci = i/(3*TW);
            int r  = (i/TW)%3;
            int t  = i%TW;
            int row = h + r - 1, col = t - 1;
            float v = 0.f;
            if (t < 130 && row >= 0 && row < H_ && col >= 0 && col < W_)
                v = __ldg(in + (size_t)(cc*8+ci)*HW + row*W_ + col);
            raw[i] = v;
        }
        for (int i = tid; i < 9*8*C_; i += 256) {
            int ks = i/(8*C_);
            int ci = (i/C_)%8;
            int co = i & 63;
            Bs[(ks*8+ci)*BPAD + co] = __ldg(wt + (size_t)((cc*8+ci)*KK_ + ks)*C_ + co);
        }
        __syncthreads();
#pragma unroll
        for (int ks = 0; ks < KK_; ks++) {
            int ky = ks/3, kx = ks%3;
            int abase = ((lane&3)*3 + ky)*TW + wid*16 + (lane>>2) + kx;
            unsigned a0 = f2tf32(raw[abase]);
            unsigned a1 = f2tf32(raw[abase + 8]);
            unsigned a2 = f2tf32(raw[abase + 4*3*TW]);
            unsigned a3 = f2tf32(raw[abase + 4*3*TW + 8]);
#pragma unroll
            for (int n = 0; n < 8; n++) {
                unsigned b0 = f2tf32(Bs[(ks*8 + (lane&3))*BPAD + n*8 + (lane>>2)]);
                unsigned b1 = f2tf32(Bs[(ks*8 + (lane&3)+4)*BPAD + n*8 + (lane>>2)]);
                asm volatile(
                    "mma.sync.aligned.m16n8k8.row.col.f32.tf32.tf32.f32 "
                    "{%0,%1,%2,%3}, {%4,%5,%6,%7}, {%8,%9}, {%0,%1,%2,%3};"
                    : "+f"(d[n][0]), "+f"(d[n][1]), "+f"(d[n][2]), "+f"(d[n][3])
                    : "r"(a0), "r"(a1), "r"(a2), "r"(a3), "r"(b0), "r"(b1));
            }
        }
    }
    int prow = h*W_ + wid*16 + (lane >> 2);
#pragma unroll
    for (int n = 0; n < 8; n++) {
        int co = n*8 + (lane & 3)*2;
        float b0v = __ldg(bias + co), b1v = __ldg(bias + co + 1);
        float v0 = d[n][0] + b0v, v1 = d[n][1] + b1v;
        float v2 = d[n][2] + b0v, v3 = d[n][3] + b1v;
        if (FUSE) {
            v0 += 2.f*__ldg(pre + (size_t)co*HW     + prow);
            v1 += 2.f*__ldg(pre + (size_t)(co+1)*HW + prow);
            v2 += 2.f*__ldg(pre + (size_t)co*HW     + prow + 8);
            v3 += 2.f*__ldg(pre + (size_t)(co+1)*HW + prow + 8);
        }
        outp[(size_t)co*HW     + prow]     = v0;
        outp[(size_t)(co+1)*HW + prow]     = v1;
        outp[(size_t)co*HW     + prow + 8] = v2;
        outp[(size_t)(co+1)*HW + prow + 8] = v3;
    }
}

__global__ void __launch_bounds__(256, 2) conv_a0tc_k(const float* __restrict__ bias) {
    int b = blockIdx.y;
    conv3tc_body<0>(g_dcn + (size_t)b*C_*HW, g_wta, bias, nullptr,
                    g_x0 + (size_t)b*C_*HW);
}

__global__ void __launch_bounds__(256, 2) conv_fustc_k(
        const float* __restrict__ bias, float* __restrict__ out) {
    int b = blockIdx.y;
    conv3tc_body<1>(g_out + (size_t)b*C_*HW, g_wtf, bias,
                    g_dcn + (size_t)b*C_*HW, out + (size_t)b*C_*HW);
}

// ---------------- 6: depthwise 3x3 on g_x0 -> g_x1d (+eca) -----------------
__global__ void __launch_bounds__(256, 4) dw_k(
        const float* __restrict__ w, const float* __restrict__ bias) {
    int tid = threadIdx.x;
    int c = blockIdx.y, b = blockIdx.z;
    int p = blockIdx.x*256 + tid;
    int h = p >> 7, wq = p & 127;
    const float* ic = g_x0 + ((size_t)b*C_ + c)*HW;
    float acc = bias[c] + g_eca[b*C_ + c];
#pragma unroll
    for (int ky = 0; ky < 3; ky++) {
        int hy = h + ky - 1;
        bool oky = (hy >= 0 && hy < H_);
#pragma unroll
        for (int kx = 0; kx < 3; kx++) {
            int wx = wq + kx - 1;
            float v = (oky && wx >= 0 && wx < W_) ? __ldg(ic + hy*W_ + wx) : 0.f;
            acc += __ldg(w + c*KK_ + ky*3+kx)*v;
        }
    }
    g_x1d[((size_t)b*C_ + c)*HW + p] = acc;
}

// ---------------- 7: per-(b,c) mean of g_x0 --------------------------------
__global__ void mean_k() {
    __shared__ float sd[256];
    int bc = blockIdx.x;
    const float* ic = g_x0 + (size_t)bc*HW;
    float s = 0.f;
    for (int i = threadIdx.x; i < HW; i += 256) s += ic[i];
    sd[threadIdx.x] = s;
    __syncthreads();
    for (int st = 128; st > 0; st >>= 1) {
        if (threadIdx.x < st) sd[threadIdx.x] += sd[threadIdx.x+st];
        __syncthreads();
    }
    if (threadIdx.x == 0) g_s[bc] = sd[0]*(1.f/(float)HW);
}

// ---------------- 8: ECA 1D conv over channels -----------------------------
__global__ void eca_k(const float* __restrict__ w2, const float* __restrict__ b2) {
    int i = threadIdx.x;
    if (i >= B_*C_) return;
    int c = i & 63;
    float sm1 = (c > 0)  ? g_s[i-1] : 0.f;
    float s0  = g_s[i];
    float sp1 = (c < 63) ? g_s[i+1] : 0.f;
    g_eca[i] = w2[0]*sm1 + w2[1]*s0 + w2[2]*sp1 + b2[0];
}

// ---------------- 9: a3 1x1 (64->576) via tf32 mma + dyn filter + lrelu ----
__global__ void __launch_bounds__(256, 2) a3tc_k(const float* __restrict__ bias) {
    __shared__ __align__(16) float buf[72*TW];
    float* As = buf;
    float* Bs = buf + 32*APAD;
    int tid = threadIdx.x, lane = tid & 31, wid = tid >> 5;
    int h = blockIdx.x, b = blockIdx.y;
    int cc = blockIdx.z;
    int co0 = cc*72;
    const float* inb = g_x1d + (size_t)b*C_*HW + h*W_;
    float d[9][4];
#pragma unroll
    for (int n = 0; n < 9; n++)
#pragma unroll
        for (int r = 0; r < 4; r++) d[n][r] = 0.f;

    for (int kc = 0; kc < 2; kc++) {
        __syncthreads();
#pragma unroll
        for (int r = 0; r < 4; r++) {
            int i4 = tid + r*256;
            int row = i4 >> 5, c4 = i4 & 31;
            float4 v = *(const float4*)(inb + (size_t)(kc*32+row)*HW + c4*4);
            *(float4*)(As + row*APAD + c4*4) = v;
        }
        for (int i = tid; i < 32*72; i += 256) {
            int row = i/72, co = i%72;
            Bs[i] = __ldg(g_wt3 + (size_t)(kc*32+row)*C9 + co0 + co);
        }
        __syncthreads();
#pragma unroll
        for (int ks = 0; ks < 4; ks++) {
            int j0 = ks*8 + (lane & 3);
            int pa = wid*16 + (lane >> 2);
            unsigned a0 = f2tf32(As[j0*APAD + pa]);
            unsigned a1 = f2tf32(As[j0*APAD + pa + 8]);
            unsigned a2 = f2tf32(As[(j0+4)*APAD + pa]);
            unsigned a3 = f2tf32(As[(j0+4)*APAD + pa + 8]);
#pragma unroll
            for (int n = 0; n < 9; n++) {
                unsigned b0 = f2tf32(Bs[j0*72 + n*8 + (lane >> 2)]);
                unsigned b1 = f2tf32(Bs[(j0+4)*72 + n*8 + (lane >> 2)]);
                asm volatile(
                    "mma.sync.aligned.m16n8k8.row.col.f32.tf32.tf32.f32 "
                    "{%0,%1,%2,%3}, {%4,%5,%6,%7}, {%8,%9}, {%0,%1,%2,%3};"
                    : "+f"(d[n][0]), "+f"(d[n][1]), "+f"(d[n][2]), "+f"(d[n][3])
                    : "r"(a0), "r"(a1), "r"(a2), "r"(a3), "r"(b0), "r"(b1));
            }
        }
    }
    __syncthreads();
    float* filt = buf;
    int px = wid*16 + (lane >> 2);
#pragma unroll
    for (int n = 0; n < 9; n++) {
        int co = n*8 + (lane & 3)*2;
        float b0v = __ldg(bias + co0 + co), b1v = __ldg(bias + co0 + co + 1);
        filt[co*TW     + px]     = d[n][0] + b0v;
        filt[(co+1)*TW + px]     = d[n][1] + b1v;
        filt[co*TW     + px + 8] = d[n][2] + b0v;
        filt[(co+1)*TW + px + 8] = d[n][3] + b1v;
    }
    __syncthreads();
    int p  = tid & 127;
    int c80 = tid >> 7;
    const float* x0b = g_x0 + (size_t)b*C_*HW;
    float* ob = g_out + (size_t)b*C_*HW + h*W_;
#pragma unroll
    for (int cq = 0; cq < 4; cq++) {
        int c8 = c80 + cq*2;
        int c = cc*8 + c8;
        const float* ic = x0b + (size_t)c*HW;
        float v[9];
#pragma unroll
        for (int ky = 0; ky < 3; ky++) {
            int hy = h + ky - 1;
            bool oy = (hy >= 0 && hy < H_);
            const float* icr = ic + hy*W_;
#pragma unroll
            for (int kx = 0; kx < 3; kx++) {
                int wx = p + kx - 1;
                v[ky*3+kx] = (oy && wx >= 0 && wx < W_) ? __ldg(icr + wx) : 0.f;
            }
        }
        float o = 0.f;
#pragma unroll
        for (int k = 0; k < KK_; k++)
            o += filt[(c8*KK_+k)*TW + p]*v[k];
        o = (o >= 0.f) ? o : 0.2f*o;
        ob[(size_t)c*HW + p] = o;
    }
}

// ---------------- launch ----------------------------------------------------
extern "C" void kernel_launch(void* const* d_in, const int* in_sizes, int n_in,
                              void* d_out, int out_size) {
    const float* x       = (const float*)d_in[0];
    const float* offset  = (const float*)d_in[1];
    const float* conv0_w = (const float*)d_in[2];
    const float* conv0_b = (const float*)d_in[3];
    const float* offm_w  = (const float*)d_in[4];
    const float* offm_b  = (const float*)d_in[5];
    const float* dcn_w   = (const float*)d_in[6];
    const float* dcn_b   = (const float*)d_in[7];
    const float* a0_w    = (const float*)d_in[8];
    const float* a0_b    = (const float*)d_in[9];
    const float* a1_w    = (const float*)d_in[10];
    const float* a1_b    = (const float*)d_in[11];
    const float* a2_w    = (const float*)d_in[12];
    const float* a2_b    = (const float*)d_in[13];
    const float* a3_w    = (const float*)d_in[14];
    const float* a3_b    = (const float*)d_in[15];
    const float* fus_w   = (const float*)d_in[16];
    const float* fus_b   = (const float*)d_in[17];
    float* out = (float*)d_out;

    dim3 gp(HW/256, B_);
    wtrall_k <<<(191232 + 255)/256, 256>>>(dcn_w, a0_w, fus_w, a3_w, offm_w);
    conv0_k  <<<gp, 256>>>(x, conv0_w, conv0_b);
    offmtc_k <<<dim3(H_, B_, 3), 256>>>(offset, offm_b);
    col_k    <<<dim3(HW/256, DG_*KK_, B_), 256>>>();
    dcntc_k  <<<dim3(HW/128, B_), 256>>>(dcn_b);
    conv_a0tc_k<<<dim3(H_, B_), 256>>>(a0_b);
    mean_k   <<<B_*C_, 256>>>();
    eca_k    <<<1, 256>>>(a2_w, a2_b);
    dw_k     <<<dim3(HW/256, C_, B_), 256>>>(a1_w, a1_b);
    a3tc_k   <<<dim3(H_, B_, 8), 256>>>(a3_b);
    conv_fustc_k<<<dim3(H_, B_), 256>>>(fus_b, out);
}

// round 12
// speedup vs baseline: 2.2845x; 1.2059x over previous
#include <cuda_runtime.h>
#include <cuda_bf16.h>
#include <cuda_fp16.h>
#include <math.h>

// Problem constants
#define B_   4
#define CIN  32
#define C_   64
#define H_   128
#define W_   128
#define HW   16384
#define DG_  8
#define CPG  8
#define KK_  9
#define OCM  216   // DG*3*K*K
#define C9   576   // C*9
#define C9P  288   // C9/2 packed rows

// ---------------- scratch (device globals; no allocation allowed) ----------
__device__ float g_x1 [B_*C_ *HW];     // conv0 out
__device__ float g_om [B_*OCM*HW];     // offset/mask conv out
__device__ float g_dcn[B_*C_ *HW];     // lrelu(deform conv) fp32 (residual use)
__device__ unsigned g_dch[B_*32*HW];   // same, packed half2 channel pairs
__device__ unsigned g_outh[B_*32*HW];  // dynamic-filter out, packed half2 pairs
__device__ unsigned g_colp[B_*C9P*HW]; // packed half2 im2col [b][jp][p]
__device__ unsigned g_wtp [C9P*C_];    // dcn weights packed half2 [jp][co]
__device__ unsigned g_wtah[32*KK_*C_]; // a0 weights packed [cipair*9+k][co]
__device__ unsigned g_wtfh[32*KK_*C_]; // fus weights packed [cipair*9+k][co]
__device__ float g_wt3[C_*C9];         // a3 weights transposed [ci][co576]
__device__ float g_wto[CIN*KK_*OCM];   // offm weights transposed [ci*9+k][co216]
__device__ float g_x0 [B_*C_ *HW];     // a0 conv out
__device__ float g_x1d[B_*C_ *HW];     // depthwise out (+eca folded in)
__device__ float g_s  [B_*C_];         // channel means of x0
__device__ float g_eca[B_*C_];         // eca values

__device__ __forceinline__ unsigned f2tf32(float v) {
    unsigned t;
    asm("cvt.rna.tf32.f32 %0, %1;" : "=r"(t) : "f"(v));
    return t;
}
__device__ __forceinline__ unsigned packh2(float a, float b) {
    __half2 h = __floats2half2_rn(a, b);
    return *(unsigned*)&h;
}

#define APAD 136
#define BPAD 72
#define TW 132

// ---------------- 1: conv0 1x1, 32->64 : 4px x 16co tiling ------------------
__global__ void __launch_bounds__(256, 2) conv0_k(
        const float* __restrict__ x, const float* __restrict__ w,
        const float* __restrict__ bias) {
    __shared__ __align__(16) float ws[CIN*C_];   // [ci][co]
    int tid = threadIdx.x;
    int quad = tid & 63, cg = tid >> 6;
    for (int i = tid; i < C_*CIN; i += 256) {
        int ci = i >> 6, co = i & 63;
        ws[ci*C_ + co] = w[co*CIN + ci];
    }
    __syncthreads();
    int b = blockIdx.y;
    int p0 = blockIdx.x*256 + quad*4;
    const float* xb = x + (size_t)b*CIN*HW + p0;
    float acc[64];
#pragma unroll
    for (int c = 0; c < 16; c++) {
        float bv = __ldg(bias + cg*16 + c);
        acc[c*4+0] = bv; acc[c*4+1] = bv; acc[c*4+2] = bv; acc[c*4+3] = bv;
    }
    for (int ci = 0; ci < CIN; ci++) {
        float4 v = *(const float4*)(xb + (size_t)ci*HW);
        const float4* w4 = (const float4*)(ws + ci*C_ + cg*16);
#pragma unroll
        for (int q = 0; q < 4; q++) {
            float4 wv = w4[q];
            float wr[4] = {wv.x, wv.y, wv.z, wv.w};
#pragma unroll
            for (int r = 0; r < 4; r++) {
                float wc = wr[r];
                float* a = acc + (q*4+r)*4;
                a[0] += wc*v.x; a[1] += wc*v.y; a[2] += wc*v.z; a[3] += wc*v.w;
            }
        }
    }
    float* ob = g_x1 + (size_t)b*C_*HW + p0;
#pragma unroll
    for (int c = 0; c < 16; c++)
        *(float4*)(ob + (size_t)(cg*16+c)*HW) =
            make_float4(acc[c*4+0], acc[c*4+1], acc[c*4+2], acc[c*4+3]);
}

// ---------------- all weight transposes/packs in ONE launch ----------------
// [0,18432): wtp; [18432,36864): wtah; [36864,55296): wtfh;
// [55296,92160): wt3; [92160,154368): wto
__global__ void wtrall_k(const float* __restrict__ dcn_w,
                         const float* __restrict__ a0_w,
                         const float* __restrict__ fus_w,
                         const float* __restrict__ a3_w,
                         const float* __restrict__ offm_w) {
    int i = blockIdx.x*256 + threadIdx.x;
    if (i < 18432) {
        // wtp: jp = g*36 + k*4 + ip packs (c=2ip, 2ip+1) within group g
        int jp = i >> 6, co = i & 63;
        int g = jp/36, r = jp%36, k = r/4, ip = r%4;
        int c0 = ip*2;
        g_wtp[i] = packh2(dcn_w[co*C9 + g*72 + c0*9 + k],
                          dcn_w[co*C9 + g*72 + (c0+1)*9 + k]);
    } else if (i < 36864) {
        int t = i - 18432;              // [cp*9+k][co]
        int co = t & 63, j = t >> 6;
        int cp = j/9, k = j%9;
        g_wtah[t] = packh2(a0_w[co*C9 + (2*cp)*KK_ + k],
                           a0_w[co*C9 + (2*cp+1)*KK_ + k]);
    } else if (i < 55296) {
        int t = i - 36864;
        int co = t & 63, j = t >> 6;
        int cp = j/9, k = j%9;
        g_wtfh[t] = packh2(fus_w[co*C9 + (2*cp)*KK_ + k],
                           fus_w[co*C9 + (2*cp+1)*KK_ + k]);
    } else if (i < 92160) {
        int t = i - 55296;
        int co = t % C9, ci = t / C9;
        g_wt3[t] = a3_w[co*C_ + ci];
    } else if (i < 154368) {
        int t = i - 92160;
        int co = t % OCM, cik = t / OCM;
        int ci = cik / KK_, k = cik % KK_;
        g_wto[t] = offm_w[(co*CIN + ci)*KK_ + k];
    }
}

// ---------------- 2: offm conv 3x3 32->216 via tf32 mma --------------------
__global__ void __launch_bounds__(256, 2) offmtc_k(
        const float* __restrict__ in, const float* __restrict__ bias) {
    __shared__ __align__(16) float raw[8*3*TW];    // [ci8][row3][col132]
    __shared__ __align__(16) float Bs[9*8*BPAD];   // [k9][ci8][co72]
    int tid = threadIdx.x, lane = tid & 31, wid = tid >> 5;
    int h = blockIdx.x, b = blockIdx.y;
    int co0 = blockIdx.z*72;
    const float* ib = in + (size_t)b*CIN*HW;
    float d[9][4];
#pragma unroll
    for (int n = 0; n < 9; n++)
#pragma unroll
        for (int r = 0; r < 4; r++) d[n][r] = 0.f;

    for (int cc = 0; cc < 4; cc++) {
        __syncthreads();
        for (int i = tid; i < 8*3*TW; i += 256) {
            int ci = i/(3*TW);
            int r  = (i/TW)%3;
            int t  = i%TW;
            int row = h + r - 1, col = t - 1;
            float v = 0.f;
            if (t < 130 && row >= 0 && row < H_ && col >= 0 && col < W_)
                v = __ldg(ib + (size_t)(cc*8+ci)*HW + row*W_ + col);
            raw[i] = v;
        }
        for (int i = tid; i < 9*8*72; i += 256) {
            int ks = i/(8*72);
            int ci = (i/72)%8;
            int co = i%72;
            Bs[(ks*8+ci)*BPAD + co] =
                __ldg(g_wto + (size_t)((cc*8+ci)*KK_ + ks)*OCM + co0 + co);
        }
        __syncthreads();
#pragma unroll
        for (int ks = 0; ks < KK_; ks++) {
            int ky = ks/3, kx = ks%3;
            int abase = ((lane&3)*3 + ky)*TW + wid*16 + (lane>>2) + kx;
            unsigned a0 = f2tf32(raw[abase]);
            unsigned a1 = f2tf32(raw[abase + 8]);
            unsigned a2 = f2tf32(raw[abase + 4*3*TW]);
            unsigned a3 = f2tf32(raw[abase + 4*3*TW + 8]);
#pragma unroll
            for (int n = 0; n < 9; n++) {
                unsigned b0 = f2tf32(Bs[(ks*8 + (lane&3))*BPAD + n*8 + (lane>>2)]);
                unsigned b1 = f2tf32(Bs[(ks*8 + (lane&3)+4)*BPAD + n*8 + (lane>>2)]);
                asm volatile(
                    "mma.sync.aligned.m16n8k8.row.col.f32.tf32.tf32.f32 "
                    "{%0,%1,%2,%3}, {%4,%5,%6,%7}, {%8,%9}, {%0,%1,%2,%3};"
                    : "+f"(d[n][0]), "+f"(d[n][1]), "+f"(d[n][2]), "+f"(d[n][3])
                    : "r"(a0), "r"(a1), "r"(a2), "r"(a3), "r"(b0), "r"(b1));
            }
        }
    }
    int prow = h*W_ + wid*16 + (lane >> 2);
    float* ob = g_om + (size_t)b*OCM*HW;
#pragma unroll
    for (int n = 0; n < 9; n++) {
        int co = co0 + n*8 + (lane & 3)*2;
        float b0v = __ldg(bias + co), b1v = __ldg(bias + co + 1);
        ob[(size_t)co*HW     + prow]     = d[n][0] + b0v;
        ob[(size_t)(co+1)*HW + prow]     = d[n][1] + b1v;
        ob[(size_t)co*HW     + prow + 8] = d[n][2] + b0v;
        ob[(size_t)(co+1)*HW + prow + 8] = d[n][3] + b1v;
    }
}

// ---------------- 3: deform im2col -> packed half2, k-major c-pairs --------
__global__ void __launch_bounds__(256, 2) col_k() {
    int tid = threadIdx.x;
    int p = blockIdx.x*256 + tid;
    int gk = blockIdx.y;                 // g*9+k, 0..71
    int g = gk/9, k = gk%9;
    int b = blockIdx.z;
    int h = p >> 7, wq = p & 127;
    const float* omb = g_om + (size_t)b*OCM*HW;
    float dy = omb[(       g*9+k)*HW + p];
    float dx = omb[( 72 +  g*9+k)*HW + p];
    float mk = omb[(144 +  g*9+k)*HW + p];
    mk = 1.f/(1.f + expf(-mk));
    float py = dy + (float)(k/3) + (float)h - 1.f;
    float px = dx + (float)(k%3) + (float)wq - 1.f;
    float fy = floorf(py), fx = floorf(px);
    int y0 = (int)fy, x0 = (int)fx;
    float wy = py - fy, wx = px - fx;
    float w00 = (1.f-wy)*(1.f-wx)*mk;
    float w01 = (1.f-wy)*wx*mk;
    float w10 = wy*(1.f-wx)*mk;
    float w11 = wy*wx*mk;
    bool iy0 = (y0 >= 0 && y0 < H_);
    bool iy1 = (y0+1 >= 0 && y0+1 < H_);
    bool ix0 = (x0 >= 0 && x0 < W_);
    bool ix1 = (x0+1 >= 0 && x0+1 < W_);
    bool v00 = iy0 && ix0, v01 = iy0 && ix1, v10 = iy1 && ix0, v11 = iy1 && ix1;
    int i00 = y0*W_ + x0;
    const float* xb = g_x1 + (size_t)b*C_*HW + (size_t)g*CPG*HW;
    float s[CPG];
#pragma unroll
    for (int c = 0; c < CPG; c++) {
        const float* xc = xb + c*HW;
        float sv = 0.f;
        if (v00) sv += w00*__ldg(xc + i00);
        if (v01) sv += w01*__ldg(xc + i00 + 1);
        if (v10) sv += w10*__ldg(xc + i00 + W_);
        if (v11) sv += w11*__ldg(xc + i00 + W_ + 1);
        s[c] = sv;
    }
    unsigned* cb = g_colp + (size_t)b*C9P*HW + (size_t)(g*36 + k*4)*HW + p;
#pragma unroll
    for (int i = 0; i < 4; i++)
        cb[(size_t)i*HW] = packh2(s[2*i], s[2*i+1]);
}

// ---------------- 4: dcn GEMM via fp16 m16n8k16 mma + lrelu ----------------
#define A2PAD 136
__global__ void __launch_bounds__(256, 2) dcntc_k(const float* __restrict__ bias) {
    __shared__ __align__(16) unsigned As2[16*A2PAD];  // [jp][px]
    __shared__ __align__(16) unsigned Bs2[16*BPAD];   // [jp][co]
    int tid = threadIdx.x, lane = tid & 31, wid = tid >> 5;
    int b = blockIdx.y;
    int p0 = blockIdx.x*128;
    const unsigned* cb = g_colp + (size_t)b*C9P*HW + p0;
    float d[8][4];
#pragma unroll
    for (int n = 0; n < 8; n++)
#pragma unroll
        for (int r = 0; r < 4; r++) d[n][r] = 0.f;

    for (int kc = 0; kc < 18; kc++) {
        __syncthreads();
#pragma unroll
        for (int r = 0; r < 2; r++) {
            int i4 = tid + r*256;
            int row = i4 >> 5, c4 = i4 & 31;
            uint4 v = *(const uint4*)(cb + (size_t)(kc*16+row)*HW + c4*4);
            *(uint4*)(As2 + row*A2PAD + c4*4) = v;
        }
        {
            int row = tid >> 4, c4 = tid & 15;
            uint4 v = *(const uint4*)(g_wtp + (size_t)(kc*16+row)*C_ + c4*4);
            *(uint4*)(Bs2 + row*BPAD + c4*4) = v;
        }
        __syncthreads();
#pragma unroll
        for (int ks = 0; ks < 2; ks++) {
            int jp0 = ks*8 + (lane & 3);
            int pa = wid*16 + (lane >> 2);
            unsigned a0 = As2[jp0*A2PAD + pa];
            unsigned a1 = As2[jp0*A2PAD + pa + 8];
            unsigned a2 = As2[(jp0+4)*A2PAD + pa];
            unsigned a3 = As2[(jp0+4)*A2PAD + pa + 8];
#pragma unroll
            for (int n = 0; n < 8; n++) {
                unsigned b0 = Bs2[jp0*BPAD + n*8 + (lane >> 2)];
                unsigned b1 = Bs2[(jp0+4)*BPAD + n*8 + (lane >> 2)];
                asm volatile(
                    "mma.sync.aligned.m16n8k16.row.col.f32.f16.f16.f32 "
                    "{%0,%1,%2,%3}, {%4,%5,%6,%7}, {%8,%9}, {%0,%1,%2,%3};"
                    : "+f"(d[n][0]), "+f"(d[n][1]), "+f"(d[n][2]), "+f"(d[n][3])
                    : "r"(a0), "r"(a1), "r"(a2), "r"(a3), "r"(b0), "r"(b1));
            }
        }
    }
    int prow = p0 + wid*16 + (lane >> 2);
    float* ob = g_dcn + (size_t)b*C_*HW;
    unsigned* oh = g_dch + (size_t)b*32*HW;
#pragma unroll
    for (int n = 0; n < 8; n++) {
        int co = n*8 + (lane & 3)*2;
        int cp = n*4 + (lane & 3);
        float b0v = __ldg(bias + co), b1v = __ldg(bias + co + 1);
        float v0 = d[n][0] + b0v, v1 = d[n][1] + b1v;
        float v2 = d[n][2] + b0v, v3 = d[n][3] + b1v;
        v0 = (v0 >= 0.f) ? v0 : 0.2f*v0;
        v1 = (v1 >= 0.f) ? v1 : 0.2f*v1;
        v2 = (v2 >= 0.f) ? v2 : 0.2f*v2;
        v3 = (v3 >= 0.f) ? v3 : 0.2f*v3;
        ob[(size_t)co*HW     + prow]     = v0;
        ob[(size_t)(co+1)*HW + prow]     = v1;
        ob[(size_t)co*HW     + prow + 8] = v2;
        ob[(size_t)(co+1)*HW + prow + 8] = v3;
        oh[(size_t)cp*HW + prow]     = packh2(v0, v1);
        oh[(size_t)cp*HW + prow + 8] = packh2(v2, v3);
    }
}

// ---------------- 5: conv3x3 64->64 via fp16 m16n8k16 (implicit GEMM) ------
// Input: packed half2 channel pairs [32][HW]. K = 16 ci per chunk, 4 chunks.
template <int FUSE>
__device__ __forceinline__ void conv3tc_f16(
        const unsigned* __restrict__ inh, const unsigned* __restrict__ wth,
        const float* __restrict__ bias, const float* __restrict__ pre,
        float* __restrict__ outp) {
    __shared__ __align__(16) unsigned raw2[8*3*TW];   // [cipair8][row3][col132]
    __shared__ __align__(16) unsigned Bs2[9*8*BPAD];  // [k9][cipair8][co]
    int tid = threadIdx.x, lane = tid & 31, wid = tid >> 5;
    int h = blockIdx.x;
    float d[8][4];
#pragma unroll
    for (int n = 0; n < 8; n++)
#pragma unroll
        for (int r = 0; r < 4; r++) d[n][r] = 0.f;

    for (int cc = 0; cc < 4; cc++) {
        __syncthreads();
        for (int i = tid; i < 8*3*TW; i += 256) {
            int ip = i/(3*TW);
            int r  = (i/TW)%3;
            int t  = i%TW;
            int row = h + r - 1, col = t - 1;
            unsigned v = 0u;
            if (t < 130 && row >= 0 && row < H_ && col >= 0 && col < W_)
                v = __ldg(inh + (size_t)(cc*8+ip)*HW + row*W_ + col);
            raw2[i] = v;
        }
        for (int i = tid; i < 9*8*C_; i += 256) {
            int ks = i/(8*C_);
            int ip = (i/C_)%8;
            int co = i & 63;
            Bs2[(ks*8+ip)*BPAD + co] =
                __ldg(wth + (size_t)((cc*8+ip)*KK_ + ks)*C_ + co);
        }
        __syncthreads();
#pragma unroll
        for (int ks = 0; ks < KK_; ks++) {
            int ky = ks/3, kx = ks%3;
            int abase = ((lane&3)*3 + ky)*TW + wid*16 + (lane>>2) + kx;
            unsigned a0 = raw2[abase];
            unsigned a1 = raw2[abase + 8];
            unsigned a2 = raw2[abase + 4*3*TW];
            unsigned a3 = raw2[abase + 4*3*TW + 8];
#pragma unroll
            for (int n = 0; n < 8; n++) {
                unsigned b0 = Bs2[(ks*8 + (lane&3))*BPAD + n*8 + (lane>>2)];
                unsigned b1 = Bs2[(ks*8 + (lane&3)+4)*BPAD + n*8 + (lane>>2)];
                asm volatile(
                    "mma.sync.aligned.m16n8k16.row.col.f32.f16.f16.f32 "
                    "{%0,%1,%2,%3}, {%4,%5,%6,%7}, {%8,%9}, {%0,%1,%2,%3};"
                    : "+f"(d[n][0]), "+f"(d[n][1]), "+f"(d[n][2]), "+f"(d[n][3])
                    : "r"(a0), "r"(a1), "r"(a2), "r"(a3), "r"(b0), "r"(b1));
            }
        }
    }
    int prow = h*W_ + wid*16 + (lane >> 2);
#pragma unroll
    for (int n = 0; n < 8; n++) {
        int co = n*8 + (lane & 3)*2;
        float b0v = __ldg(bias + co), b1v = __ldg(bias + co + 1);
        float v0 = d[n][0] + b0v, v1 = d[n][1] + b1v;
        float v2 = d[n][2] + b0v, v3 = d[n][3] + b1v;
        if (FUSE) {
            v0 += 2.f*__ldg(pre + (size_t)co*HW     + prow);
            v1 += 2.f*__ldg(pre + (size_t)(co+1)*HW + prow);
            v2 += 2.f*__ldg(pre + (size_t)co*HW     + prow + 8);
            v3 += 2.f*__ldg(pre + (size_t)(co+1)*HW + prow + 8);
        }
        outp[(size_t)co*HW     + prow]     = v0;
        outp[(size_t)(co+1)*HW + prow]     = v1;
        outp[(size_t)co*HW     + prow + 8] = v2;
        outp[(size_t)(co+1)*HW + prow + 8] = v3;
    }
}

__global__ void __launch_bounds__(256, 2) conv_a0tc_k(const float* __restrict__ bias) {
    int b = blockIdx.y;
    conv3tc_f16<0>(g_dch + (size_t)b*32*HW, g_wtah, bias, nullptr,
                   g_x0 + (size_t)b*C_*HW);
}

__global__ void __launch_bounds__(256, 2) conv_fustc_k(
        const float* __restrict__ bias, float* __restrict__ out) {
    int b = blockIdx.y;
    conv3tc_f16<1>(g_outh + (size_t)b*32*HW, g_wtfh, bias,
                   g_dcn + (size_t)b*C_*HW, out + (size_t)b*C_*HW);
}

// ---------------- 6: depthwise 3x3 on g_x0 -> g_x1d (+eca) -----------------
__global__ void __launch_bounds__(256, 4) dw_k(
        const float* __restrict__ w, const float* __restrict__ bias) {
    int tid = threadIdx.x;
    int c = blockIdx.y, b = blockIdx.z;
    int p = blockIdx.x*256 + tid;
    int h = p >> 7, wq = p & 127;
    const float* ic = g_x0 + ((size_t)b*C_ + c)*HW;
    float acc = bias[c] + g_eca[b*C_ + c];
#pragma unroll
    for (int ky = 0; ky < 3; ky++) {
        int hy = h + ky - 1;
        bool oky = (hy >= 0 && hy < H_);
#pragma unroll
        for (int kx = 0; kx < 3; kx++) {
            int wx = wq + kx - 1;
            float v = (oky && wx >= 0 && wx < W_) ? __ldg(ic + hy*W_ + wx) : 0.f;
            acc += __ldg(w + c*KK_ + ky*3+kx)*v;
        }
    }
    g_x1d[((size_t)b*C_ + c)*HW + p] = acc;
}

// ---------------- 7: per-(b,c) mean of g_x0 --------------------------------
__global__ void mean_k() {
    __shared__ float sd[256];
    int bc = blockIdx.x;
    const float* ic = g_x0 + (size_t)bc*HW;
    float s = 0.f;
    for (int i = threadIdx.x; i < HW; i += 256) s += ic[i];
    sd[threadIdx.x] = s;
    __syncthreads();
    for (int st = 128; st > 0; st >>= 1) {
        if (threadIdx.x < st) sd[threadIdx.x] += sd[threadIdx.x+st];
        __syncthreads();
    }
    if (threadIdx.x == 0) g_s[bc] = sd[0]*(1.f/(float)HW);
}

// ---------------- 8: ECA 1D conv over channels -----------------------------
__global__ void eca_k(const float* __restrict__ w2, const float* __restrict__ b2) {
    int i = threadIdx.x;
    if (i >= B_*C_) return;
    int c = i & 63;
    float sm1 = (c > 0)  ? g_s[i-1] : 0.f;
    float s0  = g_s[i];
    float sp1 = (c < 63) ? g_s[i+1] : 0.f;
    g_eca[i] = w2[0]*sm1 + w2[1]*s0 + w2[2]*sp1 + b2[0];
}

// ---------------- 9: a3 1x1 (64->576) via tf32 mma + dyn filter + lrelu ----
__global__ void __launch_bounds__(256, 2) a3tc_k(const float* __restrict__ bias) {
    __shared__ __align__(16) float buf[72*TW];
    float* As = buf;
    float* Bs = buf + 32*APAD;
    int tid = threadIdx.x, lane = tid & 31, wid = tid >> 5;
    int h = blockIdx.x, b = blockIdx.y;
    int cc = blockIdx.z;
    int co0 = cc*72;
    const float* inb = g_x1d + (size_t)b*C_*HW + h*W_;
    float d[9][4];
#pragma unroll
    for (int n = 0; n < 9; n++)
#pragma unroll
        for (int r = 0; r < 4; r++) d[n][r] = 0.f;

    for (int kc = 0; kc < 2; kc++) {
        __syncthreads();
#pragma unroll
        for (int r = 0; r < 4; r++) {
            int i4 = tid + r*256;
            int row = i4 >> 5, c4 = i4 & 31;
            float4 v = *(const float4*)(inb + (size_t)(kc*32+row)*HW + c4*4);
            *(float4*)(As + row*APAD + c4*4) = v;
        }
        for (int i = tid; i < 32*72; i += 256) {
            int row = i/72, co = i%72;
            Bs[i] = __ldg(g_wt3 + (size_t)(kc*32+row)*C9 + co0 + co);
        }
        __syncthreads();
#pragma unroll
        for (int ks = 0; ks < 4; ks++) {
            int j0 = ks*8 + (lane & 3);
            int pa = wid*16 + (lane >> 2);
            unsigned a0 = f2tf32(As[j0*APAD + pa]);
            unsigned a1 = f2tf32(As[j0*APAD + pa + 8]);
            unsigned a2 = f2tf32(As[(j0+4)*APAD + pa]);
            unsigned a3 = f2tf32(As[(j0+4)*APAD + pa + 8]);
#pragma unroll
            for (int n = 0; n < 9; n++) {
                unsigned b0 = f2tf32(Bs[j0*72 + n*8 + (lane >> 2)]);
                unsigned b1 = f2tf32(Bs[(j0+4)*72 + n*8 + (lane >> 2)]);
                asm volatile(
                    "mma.sync.aligned.m16n8k8.row.col.f32.tf32.tf32.f32 "
                    "{%0,%1,%2,%3}, {%4,%5,%6,%7}, {%8,%9}, {%0,%1,%2,%3};"
                    : "+f"(d[n][0]), "+f"(d[n][1]), "+f"(d[n][2]), "+f"(d[n][3])
                    : "r"(a0), "r"(a1), "r"(a2), "r"(a3), "r"(b0), "r"(b1));
            }
        }
    }
    __syncthreads();
    float* filt = buf;
    int px = wid*16 + (lane >> 2);
#pragma unroll
    for (int n = 0; n < 9; n++) {
        int co = n*8 + (lane & 3)*2;
        float b0v = __ldg(bias + co0 + co), b1v = __ldg(bias + co0 + co + 1);
        filt[co*TW     + px]     = d[n][0] + b0v;
        filt[(co+1)*TW + px]     = d[n][1] + b1v;
        filt[co*TW     + px + 8] = d[n][2] + b0v;
        filt[(co+1)*TW + px + 8] = d[n][3] + b1v;
    }
    __syncthreads();
    // phase 3: apply dyn filter; each thread handles 2 channel PAIRS
    int p  = tid & 127;
    int half = tid >> 7;                 // 0/1 -> pairs {0,1} / {2,3}
    const float* x0b = g_x0 + (size_t)b*C_*HW;
    unsigned* oh = g_outh + (size_t)b*32*HW + h*W_;
#pragma unroll
    for (int cq = 0; cq < 2; cq++) {
        int q = half*2 + cq;             // pair 0..3
        float o2[2];
#pragma unroll
        for (int e = 0; e < 2; e++) {
            int c8 = q*2 + e;
            int c = cc*8 + c8;
            const float* ic = x0b + (size_t)c*HW;
            float o = 0.f;
#pragma unroll
            for (int ky = 0; ky < 3; ky++) {
                int hy = h + ky - 1;
                bool oy = (hy >= 0 && hy < H_);
                const float* icr = ic + hy*W_;
#pragma unroll
                for (int kx = 0; kx < 3; kx++) {
                    int wx = p + kx - 1;
                    float v = (oy && wx >= 0 && wx < W_) ? __ldg(icr + wx) : 0.f;
                    o += filt[(c8*KK_ + ky*3+kx)*TW + p]*v;
                }
            }
            o2[e] = (o >= 0.f) ? o : 0.2f*o;
        }
        oh[(size_t)(cc*4 + q)*HW + p] = packh2(o2[0], o2[1]);
    }
}

// ---------------- launch ----------------------------------------------------
extern "C" void kernel_launch(void* const* d_in, const int* in_sizes, int n_in,
                              void* d_out, int out_size) {
    const float* x       = (const float*)d_in[0];
    const float* offset  = (const float*)d_in[1];
    const float* conv0_w = (const float*)d_in[2];
    const float* conv0_b = (const float*)d_in[3];
    const float* offm_w  = (const float*)d_in[4];
    const float* offm_b  = (const float*)d_in[5];
    const float* dcn_w   = (const float*)d_in[6];
    const float* dcn_b   = (const float*)d_in[7];
    const float* a0_w    = (const float*)d_in[8];
    const float* a0_b    = (const float*)d_in[9];
    const float* a1_w    = (const float*)d_in[10];
    const float* a1_b    = (const float*)d_in[11];
    const float* a2_w    = (const float*)d_in[12];
    const float* a2_b    = (const float*)d_in[13];
    const float* a3_w    = (const float*)d_in[14];
    const float* a3_b    = (const float*)d_in[15];
    const float* fus_w   = (const float*)d_in[16];
    const float* fus_b   = (const float*)d_in[17];
    float* out = (float*)d_out;

    dim3 gp(HW/256, B_);
    wtrall_k <<<(154368 + 255)/256, 256>>>(dcn_w, a0_w, fus_w, a3_w, offm_w);
    conv0_k  <<<gp, 256>>>(x, conv0_w, conv0_b);
    offmtc_k <<<dim3(H_, B_, 3), 256>>>(offset, offm_b);
    col_k    <<<dim3(HW/256, DG_*KK_, B_), 256>>>();
    dcntc_k  <<<dim3(HW/128, B_), 256>>>(dcn_b);
    conv_a0tc_k<<<dim3(H_, B_), 256>>>(a0_b);
    mean_k   <<<B_*C_, 256>>>();
    eca_k    <<<1, 256>>>(a2_w, a2_b);
    dw_k     <<<dim3(HW/256, C_, B_), 256>>>(a1_w, a1_b);
    a3tc_k   <<<dim3(H_, B_, 8), 256>>>(a3_b);
    conv_fustc_k<<<dim3(H_, B_), 256>>>(fus_b, out);
}

// round 13
// speedup vs baseline: 2.5585x; 1.1199x over previous
#include <cuda_runtime.h>
#include <cuda_bf16.h>
#include <cuda_fp16.h>
#include <math.h>

// Problem constants
#define B_   4
#define CIN  32
#define C_   64
#define H_   128
#define W_   128
#define HW   16384
#define DG_  8
#define CPG  8
#define KK_  9
#define OCM  216   // DG*3*K*K
#define C9   576   // C*9
#define C9P  288   // C9/2 packed rows

// ---------------- scratch (device globals; no allocation allowed) ----------
__device__ float g_x1 [B_*C_ *HW];     // conv0 out
__device__ float g_om [B_*OCM*HW];     // offset/mask conv out
__device__ float g_dcn[B_*C_ *HW];     // lrelu(deform conv) fp32 (residual use)
__device__ unsigned g_dch[B_*32*HW];   // same, packed half2 channel pairs
__device__ unsigned g_outh[B_*32*HW];  // dynamic-filter out, packed half2 pairs
__device__ unsigned g_colp[B_*C9P*HW]; // packed half2 im2col [b][jp][p]
__device__ unsigned g_x1dh[B_*32*HW];  // depthwise out, packed half2 pairs
__device__ unsigned g_wtp [C9P*C_];    // dcn weights packed half2 [jp][co]
__device__ unsigned g_wtah[32*KK_*C_]; // a0 weights packed [cipair*9+k][co]
__device__ unsigned g_wtfh[32*KK_*C_]; // fus weights packed [cipair*9+k][co]
__device__ unsigned g_wt3p[32*C9];     // a3 weights packed [cipair][co576]
__device__ unsigned g_wtoh[16*KK_*OCM];// offm weights packed [cipair*9+k][co216]
__device__ float g_beff[B_*C9];        // a3 bias + a3_w . eca
__device__ float g_x0 [B_*C_ *HW];     // a0 conv out
__device__ float g_s  [B_*C_];         // channel means of x0
__device__ float g_eca[B_*C_];         // eca values

__device__ __forceinline__ unsigned f2tf32(float v) {
    unsigned t;
    asm("cvt.rna.tf32.f32 %0, %1;" : "=r"(t) : "f"(v));
    return t;
}
__device__ __forceinline__ unsigned packh2(float a, float b) {
    __half2 h = __floats2half2_rn(a, b);
    return *(unsigned*)&h;
}

#define APAD 136
#define BPAD 72
#define TW 132
#define A2PAD 136

// ---------------- 1: conv0 1x1, 32->64 : 4px x 16co tiling ------------------
__global__ void __launch_bounds__(256, 2) conv0_k(
        const float* __restrict__ x, const float* __restrict__ w,
        const float* __restrict__ bias) {
    __shared__ __align__(16) float ws[CIN*C_];   // [ci][co]
    int tid = threadIdx.x;
    int quad = tid & 63, cg = tid >> 6;
    for (int i = tid; i < C_*CIN; i += 256) {
        int ci = i >> 6, co = i & 63;
        ws[ci*C_ + co] = w[co*CIN + ci];
    }
    __syncthreads();
    int b = blockIdx.y;
    int p0 = blockIdx.x*256 + quad*4;
    const float* xb = x + (size_t)b*CIN*HW + p0;
    float acc[64];
#pragma unroll
    for (int c = 0; c < 16; c++) {
        float bv = __ldg(bias + cg*16 + c);
        acc[c*4+0] = bv; acc[c*4+1] = bv; acc[c*4+2] = bv; acc[c*4+3] = bv;
    }
    for (int ci = 0; ci < CIN; ci++) {
        float4 v = *(const float4*)(xb + (size_t)ci*HW);
        const float4* w4 = (const float4*)(ws + ci*C_ + cg*16);
#pragma unroll
        for (int q = 0; q < 4; q++) {
            float4 wv = w4[q];
            float wr[4] = {wv.x, wv.y, wv.z, wv.w};
#pragma unroll
            for (int r = 0; r < 4; r++) {
                float wc = wr[r];
                float* a = acc + (q*4+r)*4;
                a[0] += wc*v.x; a[1] += wc*v.y; a[2] += wc*v.z; a[3] += wc*v.w;
            }
        }
    }
    float* ob = g_x1 + (size_t)b*C_*HW + p0;
#pragma unroll
    for (int c = 0; c < 16; c++)
        *(float4*)(ob + (size_t)(cg*16+c)*HW) =
            make_float4(acc[c*4+0], acc[c*4+1], acc[c*4+2], acc[c*4+3]);
}

// ---------------- all weight transposes/packs in ONE launch ----------------
// [0,18432): wtp; [18432,36864): wtah; [36864,55296): wtfh;
// [55296,73728): wt3p; [73728,104832): wtoh
__global__ void wtrall_k(const float* __restrict__ dcn_w,
                         const float* __restrict__ a0_w,
                         const float* __restrict__ fus_w,
                         const float* __restrict__ a3_w,
                         const float* __restrict__ offm_w) {
    int i = blockIdx.x*256 + threadIdx.x;
    if (i < 18432) {
        int jp = i >> 6, co = i & 63;
        int g = jp/36, r = jp%36, k = r/4, ip = r%4;
        int c0 = ip*2;
        g_wtp[i] = packh2(dcn_w[co*C9 + g*72 + c0*9 + k],
                          dcn_w[co*C9 + g*72 + (c0+1)*9 + k]);
    } else if (i < 36864) {
        int t = i - 18432;              // [cp*9+k][co]
        int co = t & 63, j = t >> 6;
        int cp = j/9, k = j%9;
        g_wtah[t] = packh2(a0_w[co*C9 + (2*cp)*KK_ + k],
                           a0_w[co*C9 + (2*cp+1)*KK_ + k]);
    } else if (i < 55296) {
        int t = i - 36864;
        int co = t & 63, j = t >> 6;
        int cp = j/9, k = j%9;
        g_wtfh[t] = packh2(fus_w[co*C9 + (2*cp)*KK_ + k],
                           fus_w[co*C9 + (2*cp+1)*KK_ + k]);
    } else if (i < 73728) {
        int t = i - 55296;              // [cp][co576]
        int co = t % C9, cp = t / C9;
        g_wt3p[t] = packh2(a3_w[co*C_ + 2*cp], a3_w[co*C_ + 2*cp+1]);
    } else if (i < 104832) {
        int t = i - 73728;              // [cp*9+k][co216]
        int co = t % OCM, j = t / OCM;
        int cp = j/9, k = j%9;
        g_wtoh[t] = packh2(offm_w[(co*CIN + 2*cp)*KK_ + k],
                           offm_w[(co*CIN + 2*cp+1)*KK_ + k]);
    }
}

// ---------------- 2: offm conv 3x3 32->216 via fp16 m16n8k16 ---------------
// grid (H_, B_, 3). K = 2 chunks of 8 channel-pairs, 9 shift passes.
__global__ void __launch_bounds__(256, 2) offmtc_k(
        const float* __restrict__ in, const float* __restrict__ bias) {
    __shared__ __align__(16) unsigned raw2[8*3*TW];   // [cipair8][row3][col132]
    __shared__ __align__(16) unsigned Bs2[9*8*BPAD];  // [k9][cipair8][co72]
    int tid = threadIdx.x, lane = tid & 31, wid = tid >> 5;
    int h = blockIdx.x, b = blockIdx.y;
    int co0 = blockIdx.z*72;
    const float* ib = in + (size_t)b*CIN*HW;
    float d[9][4];
#pragma unroll
    for (int n = 0; n < 9; n++)
#pragma unroll
        for (int r = 0; r < 4; r++) d[n][r] = 0.f;

    for (int cc = 0; cc < 2; cc++) {
        __syncthreads();
        for (int i = tid; i < 8*3*TW; i += 256) {
            int ip = i/(3*TW);
            int r  = (i/TW)%3;
            int t  = i%TW;
            int row = h + r - 1, col = t - 1;
            unsigned v = 0u;
            if (t < 130 && row >= 0 && row < H_ && col >= 0 && col < W_) {
                const float* p0 = ib + (size_t)(2*(cc*8+ip))*HW + row*W_ + col;
                v = packh2(__ldg(p0), __ldg(p0 + HW));
            }
            raw2[i] = v;
        }
        for (int i = tid; i < 9*8*72; i += 256) {
            int ks = i/(8*72);
            int ip = (i/72)%8;
            int co = i%72;
            Bs2[(ks*8+ip)*BPAD + co] =
                __ldg(g_wtoh + (size_t)((cc*8+ip)*KK_ + ks)*OCM + co0 + co);
        }
        __syncthreads();
#pragma unroll
        for (int ks = 0; ks < KK_; ks++) {
            int ky = ks/3, kx = ks%3;
            int abase = ((lane&3)*3 + ky)*TW + wid*16 + (lane>>2) + kx;
            unsigned a0 = raw2[abase];
            unsigned a1 = raw2[abase + 8];
            unsigned a2 = raw2[abase + 4*3*TW];
            unsigned a3 = raw2[abase + 4*3*TW + 8];
#pragma unroll
            for (int n = 0; n < 9; n++) {
                unsigned b0 = Bs2[(ks*8 + (lane&3))*BPAD + n*8 + (lane>>2)];
                unsigned b1 = Bs2[(ks*8 + (lane&3)+4)*BPAD + n*8 + (lane>>2)];
                asm volatile(
                    "mma.sync.aligned.m16n8k16.row.col.f32.f16.f16.f32 "
                    "{%0,%1,%2,%3}, {%4,%5,%6,%7}, {%8,%9}, {%0,%1,%2,%3};"
                    : "+f"(d[n][0]), "+f"(d[n][1]), "+f"(d[n][2]), "+f"(d[n][3])
                    : "r"(a0), "r"(a1), "r"(a2), "r"(a3), "r"(b0), "r"(b1));
            }
        }
    }
    int prow = h*W_ + wid*16 + (lane >> 2);
    float* ob = g_om + (size_t)b*OCM*HW;
#pragma unroll
    for (int n = 0; n < 9; n++) {
        int co = co0 + n*8 + (lane & 3)*2;
        float b0v = __ldg(bias + co), b1v = __ldg(bias + co + 1);
        ob[(size_t)co*HW     + prow]     = d[n][0] + b0v;
        ob[(size_t)(co+1)*HW + prow]     = d[n][1] + b1v;
        ob[(size_t)co*HW     + prow + 8] = d[n][2] + b0v;
        ob[(size_t)(co+1)*HW + prow + 8] = d[n][3] + b1v;
    }
}

// ---------------- 3: deform im2col -> packed half2, k-major c-pairs --------
__global__ void __launch_bounds__(256, 2) col_k() {
    int tid = threadIdx.x;
    int p = blockIdx.x*256 + tid;
    int gk = blockIdx.y;                 // g*9+k, 0..71
    int g = gk/9, k = gk%9;
    int b = blockIdx.z;
    int h = p >> 7, wq = p & 127;
    const float* omb = g_om + (size_t)b*OCM*HW;
    float dy = omb[(       g*9+k)*HW + p];
    float dx = omb[( 72 +  g*9+k)*HW + p];
    float mk = omb[(144 +  g*9+k)*HW + p];
    mk = 1.f/(1.f + expf(-mk));
    float py = dy + (float)(k/3) + (float)h - 1.f;
    float px = dx + (float)(k%3) + (float)wq - 1.f;
    float fy = floorf(py), fx = floorf(px);
    int y0 = (int)fy, x0 = (int)fx;
    float wy = py - fy, wx = px - fx;
    float w00 = (1.f-wy)*(1.f-wx)*mk;
    float w01 = (1.f-wy)*wx*mk;
    float w10 = wy*(1.f-wx)*mk;
    float w11 = wy*wx*mk;
    bool iy0 = (y0 >= 0 && y0 < H_);
    bool iy1 = (y0+1 >= 0 && y0+1 < H_);
    bool ix0 = (x0 >= 0 && x0 < W_);
    bool ix1 = (x0+1 >= 0 && x0+1 < W_);
    bool v00 = iy0 && ix0, v01 = iy0 && ix1, v10 = iy1 && ix0, v11 = iy1 && ix1;
    int i00 = y0*W_ + x0;
    const float* xb = g_x1 + (size_t)b*C_*HW + (size_t)g*CPG*HW;
    float s[CPG];
#pragma unroll
    for (int c = 0; c < CPG; c++) {
        const float* xc = xb + c*HW;
        float sv = 0.f;
        if (v00) sv += w00*__ldg(xc + i00);
        if (v01) sv += w01*__ldg(xc + i00 + 1);
        if (v10) sv += w10*__ldg(xc + i00 + W_);
        if (v11) sv += w11*__ldg(xc + i00 + W_ + 1);
        s[c] = sv;
    }
    unsigned* cb = g_colp + (size_t)b*C9P*HW + (size_t)(g*36 + k*4)*HW + p;
#pragma unroll
    for (int i = 0; i < 4; i++)
        cb[(size_t)i*HW] = packh2(s[2*i], s[2*i+1]);
}

// ---------------- 4: dcn GEMM via fp16 m16n8k16 mma + lrelu ----------------
__global__ void __launch_bounds__(256, 2) dcntc_k(const float* __restrict__ bias) {
    __shared__ __align__(16) unsigned As2[16*A2PAD];  // [jp][px]
    __shared__ __align__(16) unsigned Bs2[16*BPAD];   // [jp][co]
    int tid = threadIdx.x, lane = tid & 31, wid = tid >> 5;
    int b = blockIdx.y;
    int p0 = blockIdx.x*128;
    const unsigned* cb = g_colp + (size_t)b*C9P*HW + p0;
    float d[8][4];
#pragma unroll
    for (int n = 0; n < 8; n++)
#pragma unroll
        for (int r = 0; r < 4; r++) d[n][r] = 0.f;

    for (int kc = 0; kc < 18; kc++) {
        __syncthreads();
#pragma unroll
        for (int r = 0; r < 2; r++) {
            int i4 = tid + r*256;
            int row = i4 >> 5, c4 = i4 & 31;
            uint4 v = *(const uint4*)(cb + (size_t)(kc*16+row)*HW + c4*4);
            *(uint4*)(As2 + row*A2PAD + c4*4) = v;
        }
        {
            int row = tid >> 4, c4 = tid & 15;
            uint4 v = *(const uint4*)(g_wtp + (size_t)(kc*16+row)*C_ + c4*4);
            *(uint4*)(Bs2 + row*BPAD + c4*4) = v;
        }
        __syncthreads();
#pragma unroll
        for (int ks = 0; ks < 2; ks++) {
            int jp0 = ks*8 + (lane & 3);
            int pa = wid*16 + (lane >> 2);
            unsigned a0 = As2[jp0*A2PAD + pa];
            unsigned a1 = As2[jp0*A2PAD + pa + 8];
            unsigned a2 = As2[(jp0+4)*A2PAD + pa];
            unsigned a3 = As2[(jp0+4)*A2PAD + pa + 8];
#pragma unroll
            for (int n = 0; n < 8; n++) {
                unsigned b0 = Bs2[jp0*BPAD + n*8 + (lane >> 2)];
                unsigned b1 = Bs2[(jp0+4)*BPAD + n*8 + (lane >> 2)];
                asm volatile(
                    "mma.sync.aligned.m16n8k16.row.col.f32.f16.f16.f32 "
                    "{%0,%1,%2,%3}, {%4,%5,%6,%7}, {%8,%9}, {%0,%1,%2,%3};"
                    : "+f"(d[n][0]), "+f"(d[n][1]), "+f"(d[n][2]), "+f"(d[n][3])
                    : "r"(a0), "r"(a1), "r"(a2), "r"(a3), "r"(b0), "r"(b1));
            }
        }
    }
    int prow = p0 + wid*16 + (lane >> 2);
    float* ob = g_dcn + (size_t)b*C_*HW;
    unsigned* oh = g_dch + (size_t)b*32*HW;
#pragma unroll
    for (int n = 0; n < 8; n++) {
        int co = n*8 + (lane & 3)*2;
        int cp = n*4 + (lane & 3);
        float b0v = __ldg(bias + co), b1v = __ldg(bias + co + 1);
        float v0 = d[n][0] + b0v, v1 = d[n][1] + b1v;
        float v2 = d[n][2] + b0v, v3 = d[n][3] + b1v;
        v0 = (v0 >= 0.f) ? v0 : 0.2f*v0;
        v1 = (v1 >= 0.f) ? v1 : 0.2f*v1;
        v2 = (v2 >= 0.f) ? v2 : 0.2f*v2;
        v3 = (v3 >= 0.f) ? v3 : 0.2f*v3;
        ob[(size_t)co*HW     + prow]     = v0;
        ob[(size_t)(co+1)*HW + prow]     = v1;
        ob[(size_t)co*HW     + prow + 8] = v2;
        ob[(size_t)(co+1)*HW + prow + 8] = v3;
        oh[(size_t)cp*HW + prow]     = packh2(v0, v1);
        oh[(size_t)cp*HW + prow + 8] = packh2(v2, v3);
    }
}

// ---------------- 5: conv3x3 64->64 via fp16 m16n8k16 (implicit GEMM) ------
template <int FUSE>
__device__ __forceinline__ void conv3tc_f16(
        const unsigned* __restrict__ inh, const unsigned* __restrict__ wth,
        const float* __restrict__ bias, const float* __restrict__ pre,
        float* __restrict__ outp) {
    __shared__ __align__(16) unsigned raw2[8*3*TW];   // [cipair8][row3][col132]
    __shared__ __align__(16) unsigned Bs2[9*8*BPAD];  // [k9][cipair8][co]
    int tid = threadIdx.x, lane = tid & 31, wid = tid >> 5;
    int h = blockIdx.x;
    float d[8][4];
#pragma unroll
    for (int n = 0; n < 8; n++)
#pragma unroll
        for (int r = 0; r < 4; r++) d[n][r] = 0.f;

    for (int cc = 0; cc < 4; cc++) {
        __syncthreads();
        for (int i = tid; i < 8*3*TW; i += 256) {
            int ip = i/(3*TW);
            int r  = (i/TW)%3;
            int t  = i%TW;
            int row = h + r - 1, col = t - 1;
            unsigned v = 0u;
            if (t < 130 && row >= 0 && row < H_ && col >= 0 && col < W_)
                v = __ldg(inh + (size_t)(cc*8+ip)*HW + row*W_ + col);
            raw2[i] = v;
        }
        for (int i = tid; i < 9*8*C_; i += 256) {
            int ks = i/(8*C_);
            int ip = (i/C_)%8;
            int co = i & 63;
            Bs2[(ks*8+ip)*BPAD + co] =
                __ldg(wth + (size_t)((cc*8+ip)*KK_ + ks)*C_ + co);
        }
        __syncthreads();
#pragma unroll
        for (int ks = 0; ks < KK_; ks++) {
            int ky = ks/3, kx = ks%3;
            int abase = ((lane&3)*3 + ky)*TW + wid*16 + (lane>>2) + kx;
            unsigned a0 = raw2[abase];
            unsigned a1 = raw2[abase + 8];
            unsigned a2 = raw2[abase + 4*3*TW];
            unsigned a3 = raw2[abase + 4*3*TW + 8];
#pragma unroll
            for (int n = 0; n < 8; n++) {
                unsigned b0 = Bs2[(ks*8 + (lane&3))*BPAD + n*8 + (lane>>2)];
                unsigned b1 = Bs2[(ks*8 + (lane&3)+4)*BPAD + n*8 + (lane>>2)];
                asm volatile(
                    "mma.sync.aligned.m16n8k16.row.col.f32.f16.f16.f32 "
                    "{%0,%1,%2,%3}, {%4,%5,%6,%7}, {%8,%9}, {%0,%1,%2,%3};"
                    : "+f"(d[n][0]), "+f"(d[n][1]), "+f"(d[n][2]), "+f"(d[n][3])
                    : "r"(a0), "r"(a1), "r"(a2), "r"(a3), "r"(b0), "r"(b1));
            }
        }
    }
    int prow = h*W_ + wid*16 + (lane >> 2);
#pragma unroll
    for (int n = 0; n < 8; n++) {
        int co = n*8 + (lane & 3)*2;
        float b0v = __ldg(bias + co), b1v = __ldg(bias + co + 1);
        float v0 = d[n][0] + b0v, v1 = d[n][1] + b1v;
        float v2 = d[n][2] + b0v, v3 = d[n][3] + b1v;
        if (FUSE) {
            v0 += 2.f*__ldg(pre + (size_t)co*HW     + prow);
            v1 += 2.f*__ldg(pre + (size_t)(co+1)*HW + prow);
            v2 += 2.f*__ldg(pre + (size_t)co*HW     + prow + 8);
            v3 += 2.f*__ldg(pre + (size_t)(co+1)*HW + prow + 8);
        }
        outp[(size_t)co*HW     + prow]     = v0;
        outp[(size_t)(co+1)*HW + prow]     = v1;
        outp[(size_t)co*HW     + prow + 8] = v2;
        outp[(size_t)(co+1)*HW + prow + 8] = v3;
    }
}

__global__ void __launch_bounds__(256, 2) conv_a0tc_k(const float* __restrict__ bias) {
    int b = blockIdx.y;
    conv3tc_f16<0>(g_dch + (size_t)b*32*HW, g_wtah, bias, nullptr,
                   g_x0 + (size_t)b*C_*HW);
}

__global__ void __launch_bounds__(256, 2) conv_fustc_k(
        const float* __restrict__ bias, float* __restrict__ out) {
    int b = blockIdx.y;
    conv3tc_f16<1>(g_outh + (size_t)b*32*HW, g_wtfh, bias,
                   g_dcn + (size_t)b*C_*HW, out + (size_t)b*C_*HW);
}

// ---------------- 6: depthwise 3x3 on g_x0 -> packed g_x1dh (no eca) -------
__global__ void __launch_bounds__(256, 4) dw_k(
        const float* __restrict__ w, const float* __restrict__ bias) {
    int tid = threadIdx.x;
    int cp = blockIdx.y, b = blockIdx.z;
    int p = blockIdx.x*256 + tid;
    int h = p >> 7, wq = p & 127;
    int c0 = 2*cp;
    const float* ic0 = g_x0 + ((size_t)b*C_ + c0)*HW;
    const float* ic1 = ic0 + HW;
    float a0v = __ldg(bias + c0), a1v = __ldg(bias + c0 + 1);
#pragma unroll
    for (int ky = 0; ky < 3; ky++) {
        int hy = h + ky - 1;
        bool oky = (hy >= 0 && hy < H_);
#pragma unroll
        for (int kx = 0; kx < 3; kx++) {
            int wx = wq + kx - 1;
            bool ok = (oky && wx >= 0 && wx < W_);
            float v0 = ok ? __ldg(ic0 + hy*W_ + wx) : 0.f;
            float v1 = ok ? __ldg(ic1 + hy*W_ + wx) : 0.f;
            a0v += __ldg(w + c0*KK_ + ky*3+kx)*v0;
            a1v += __ldg(w + (c0+1)*KK_ + ky*3+kx)*v1;
        }
    }
    g_x1dh[((size_t)b*32 + cp)*HW + p] = packh2(a0v, a1v);
}

// ---------------- 7: per-(b,c) mean of g_x0 --------------------------------
__global__ void mean_k() {
    __shared__ float sd[256];
    int bc = blockIdx.x;
    const float* ic = g_x0 + (size_t)bc*HW;
    float s = 0.f;
    for (int i = threadIdx.x; i < HW; i += 256) s += ic[i];
    sd[threadIdx.x] = s;
    __syncthreads();
    for (int st = 128; st > 0; st >>= 1) {
        if (threadIdx.x < st) sd[threadIdx.x] += sd[threadIdx.x+st];
        __syncthreads();
    }
    if (threadIdx.x == 0) g_s[bc] = sd[0]*(1.f/(float)HW);
}

// ---------------- 8: ECA 1D conv over channels -----------------------------
__global__ void eca_k(const float* __restrict__ w2, const float* __restrict__ b2) {
    int i = threadIdx.x;
    if (i >= B_*C_) return;
    int c = i & 63;
    float sm1 = (c > 0)  ? g_s[i-1] : 0.f;
    float s0  = g_s[i];
    float sp1 = (c < 63) ? g_s[i+1] : 0.f;
    g_eca[i] = w2[0]*sm1 + w2[1]*s0 + w2[2]*sp1 + b2[0];
}

// ---------------- 8b: fold eca into a3 effective bias ----------------------
__global__ void ecabias_k(const float* __restrict__ a3w,
                          const float* __restrict__ a3b) {
    int b = blockIdx.x;
    int co = threadIdx.x;                // 0..575
    if (co >= C9) return;
    float s = __ldg(a3b + co);
    const float* wr = a3w + (size_t)co*C_;
#pragma unroll 8
    for (int ci = 0; ci < C_; ci++)
        s += __ldg(wr + ci)*g_eca[b*C_ + ci];
    g_beff[b*C9 + co] = s;
}

// ---------------- 9: a3 1x1 (64->576) via fp16 mma + dyn filter + lrelu ----
__global__ void __launch_bounds__(256, 2) a3tc_k() {
    __shared__ __align__(16) float buf[72*TW];   // phase2/3 filt [co72][pxTW]
    unsigned* As2 = (unsigned*)buf;              // phase1: [16][A2PAD]
    unsigned* Bs2 = (unsigned*)buf + 16*A2PAD;   //         [16][BPAD]
    int tid = threadIdx.x, lane = tid & 31, wid = tid >> 5;
    int h = blockIdx.x, b = blockIdx.y;
    int cc = blockIdx.z;
    int co0 = cc*72;
    const unsigned* inb = g_x1dh + (size_t)b*32*HW + h*W_;
    float d[9][4];
#pragma unroll
    for (int n = 0; n < 9; n++)
#pragma unroll
        for (int r = 0; r < 4; r++) d[n][r] = 0.f;

    for (int kc = 0; kc < 2; kc++) {
        __syncthreads();
#pragma unroll
        for (int r = 0; r < 2; r++) {
            int i4 = tid + r*256;                // 0..511
            int row = i4 >> 5, c4 = i4 & 31;
            uint4 v = *(const uint4*)(inb + (size_t)(kc*16+row)*HW + c4*4);
            *(uint4*)(As2 + row*A2PAD + c4*4) = v;
        }
        for (int i = tid; i < 16*72; i += 256) {
            int row = i/72, co = i%72;
            Bs2[row*BPAD + co] = __ldg(g_wt3p + (size_t)(kc*16+row)*C9 + co0 + co);
        }
        __syncthreads();
#pragma unroll
        for (int ks = 0; ks < 2; ks++) {
            int jp0 = ks*8 + (lane & 3);
            int pa = wid*16 + (lane >> 2);
            unsigned a0 = As2[jp0*A2PAD + pa];
            unsigned a1 = As2[jp0*A2PAD + pa + 8];
            unsigned a2 = As2[(jp0+4)*A2PAD + pa];
            unsigned a3 = As2[(jp0+4)*A2PAD + pa + 8];
#pragma unroll
            for (int n = 0; n < 9; n++) {
                unsigned b0 = Bs2[jp0*BPAD + n*8 + (lane >> 2)];
                unsigned b1 = Bs2[(jp0+4)*BPAD + n*8 + (lane >> 2)];
                asm volatile(
                    "mma.sync.aligned.m16n8k16.row.col.f32.f16.f16.f32 "
                    "{%0,%1,%2,%3}, {%4,%5,%6,%7}, {%8,%9}, {%0,%1,%2,%3};"
                    : "+f"(d[n][0]), "+f"(d[n][1]), "+f"(d[n][2]), "+f"(d[n][3])
                    : "r"(a0), "r"(a1), "r"(a2), "r"(a3), "r"(b0), "r"(b1));
            }
        }
    }
    __syncthreads();
    float* filt = buf;
    int px = wid*16 + (lane >> 2);
#pragma unroll
    for (int n = 0; n < 9; n++) {
        int co = n*8 + (lane & 3)*2;
        float b0v = __ldg(g_beff + b*C9 + co0 + co);
        float b1v = __ldg(g_beff + b*C9 + co0 + co + 1);
        filt[co*TW     + px]     = d[n][0] + b0v;
        filt[(co+1)*TW + px]     = d[n][1] + b1v;
        filt[co*TW     + px + 8] = d[n][2] + b0v;
        filt[(co+1)*TW + px + 8] = d[n][3] + b1v;
    }
    __syncthreads();
    // phase 3: apply dyn filter; each thread handles 2 channel PAIRS
    int p  = tid & 127;
    int half = tid >> 7;
    const float* x0b = g_x0 + (size_t)b*C_*HW;
    unsigned* oh = g_outh + (size_t)b*32*HW + h*W_;
#pragma unroll
    for (int cq = 0; cq < 2; cq++) {
        int q = half*2 + cq;
        float o2[2];
#pragma unroll
        for (int e = 0; e < 2; e++) {
            int c8 = q*2 + e;
            int c = cc*8 + c8;
            const float* ic = x0b + (size_t)c*HW;
            float o = 0.f;
#pragma unroll
            for (int ky = 0; ky < 3; ky++) {
                int hy = h + ky - 1;
                bool oy = (hy >= 0 && hy < H_);
                const float* icr = ic + hy*W_;
#pragma unroll
                for (int kx = 0; kx < 3; kx++) {
                    int wx = p + kx - 1;
                    float v = (oy && wx >= 0 && wx < W_) ? __ldg(icr + wx) : 0.f;
                    o += filt[(c8*KK_ + ky*3+kx)*TW + p]*v;
                }
            }
            o2[e] = (o >= 0.f) ? o : 0.2f*o;
        }
        oh[(size_t)(cc*4 + q)*HW + p] = packh2(o2[0], o2[1]);
    }
}

// ---------------- launch ----------------------------------------------------
extern "C" void kernel_launch(void* const* d_in, const int* in_sizes, int n_in,
                              void* d_out, int out_size) {
    const float* x       = (const float*)d_in[0];
    const float* offset  = (const float*)d_in[1];
    const float* conv0_w = (const float*)d_in[2];
    const float* conv0_b = (const float*)d_in[3];
    const float* offm_w  = (const float*)d_in[4];
    const float* offm_b  = (const float*)d_in[5];
    const float* dcn_w   = (const float*)d_in[6];
    const float* dcn_b   = (const float*)d_in[7];
    const float* a0_w    = (const float*)d_in[8];
    const float* a0_b    = (const float*)d_in[9];
    const float* a1_w    = (const float*)d_in[10];
    const float* a1_b    = (const float*)d_in[11];
    const float* a2_w    = (const float*)d_in[12];
    const float* a2_b    = (const float*)d_in[13];
    const float* a3_w    = (const float*)d_in[14];
    const float* a3_b    = (const float*)d_in[15];
    const float* fus_w   = (const float*)d_in[16];
    const float* fus_b   = (const float*)d_in[17];
    float* out = (float*)d_out;

    dim3 gp(HW/256, B_);
    wtrall_k <<<(104832 + 255)/256, 256>>>(dcn_w, a0_w, fus_w, a3_w, offm_w);
    conv0_k  <<<gp, 256>>>(x, conv0_w, conv0_b);
    offmtc_k <<<dim3(H_, B_, 3), 256>>>(offset, offm_b);
    col_k    <<<dim3(HW/256, DG_*KK_, B_), 256>>>();
    dcntc_k  <<<dim3(HW/128, B_), 256>>>(dcn_b);
    conv_a0tc_k<<<dim3(H_, B_), 256>>>(a0_b);
    dw_k     <<<dim3(HW/256, 32, B_), 256>>>(a1_w, a1_b);
    mean_k   <<<B_*C_, 256>>>();
    eca_k    <<<1, 256>>>(a2_w, a2_b);
    ecabias_k<<<B_, C9>>>(a3_w, a3_b);
    a3tc_k   <<<dim3(H_, B_, 8), 256>>>();
    conv_fustc_k<<<dim3(H_, B_), 256>>>(fus_b, out);
}

// round 15
// speedup vs baseline: 2.8016x; 1.0950x over previous
#include <cuda_runtime.h>
#include <cuda_bf16.h>
#include <cuda_fp16.h>
#include <math.h>

// Problem constants
#define B_   4
#define CIN  32
#define C_   64
#define H_   128
#define W_   128
#define HW   16384
#define DG_  8
#define CPG  8
#define KK_  9
#define OCM  216   // DG*3*K*K
#define C9   576   // C*9
#define C9P  288   // C9/2 packed rows

// ---------------- scratch (device globals; no allocation allowed) ----------
__device__ float g_x1i[B_*DG_*HW*8];   // conv0 out, interleaved [b][g][p][c8]
__device__ float g_om [B_*OCM*HW];     // offset/mask conv out
__device__ float g_dcn[B_*C_ *HW];     // lrelu(deform conv) fp32 (residual use)
__device__ unsigned g_dch[B_*32*HW];   // same, packed half2 channel pairs
__device__ unsigned g_outh[B_*32*HW];  // dynamic-filter out, packed half2 pairs
__device__ unsigned g_colp[B_*C9P*HW]; // packed half2 im2col [b][jp][p]
__device__ unsigned g_x1dh[B_*32*HW];  // depthwise out, packed half2 pairs
__device__ unsigned g_wtp [C9P*C_];    // dcn weights packed half2 [jp][co]
__device__ unsigned g_wtah[32*KK_*C_]; // a0 weights packed [cipair*9+k][co]
__device__ unsigned g_wtfh[32*KK_*C_]; // fus weights packed [cipair*9+k][co]
__device__ unsigned g_wt3p[32*C9];     // a3 weights packed [cipair][co576]
__device__ unsigned g_wtoh[16*KK_*OCM];// offm weights packed [cipair*9+k][co216]
__device__ float g_beff[B_*C9];        // a3 bias + a3_w . eca
__device__ float g_x0 [B_*C_ *HW];     // a0 conv out
__device__ float g_s  [B_*C_];         // channel means of x0

__device__ __forceinline__ unsigned packh2(float a, float b) {
    __half2 h = __floats2half2_rn(a, b);
    return *(unsigned*)&h;
}

#define APAD 136
#define BPAD 72
#define TW 132
#define A2PAD 136

// ---------------- 1: conv0 1x1, 32->64 : 4px x 16co, interleaved out -------
__global__ void __launch_bounds__(256, 2) conv0_k(
        const float* __restrict__ x, const float* __restrict__ w,
        const float* __restrict__ bias) {
    __shared__ __align__(16) float ws[CIN*C_];   // [ci][co]
    int tid = threadIdx.x;
    int quad = tid & 63, cg = tid >> 6;
    for (int i = tid; i < C_*CIN; i += 256) {
        int ci = i >> 6, co = i & 63;
        ws[ci*C_ + co] = w[co*CIN + ci];
    }
    __syncthreads();
    int b = blockIdx.y;
    int p0 = blockIdx.x*256 + quad*4;
    const float* xb = x + (size_t)b*CIN*HW + p0;
    float acc[64];
#pragma unroll
    for (int c = 0; c < 16; c++) {
        float bv = __ldg(bias + cg*16 + c);
        acc[c*4+0] = bv; acc[c*4+1] = bv; acc[c*4+2] = bv; acc[c*4+3] = bv;
    }
    for (int ci = 0; ci < CIN; ci++) {
        float4 v = *(const float4*)(xb + (size_t)ci*HW);
        const float4* w4 = (const float4*)(ws + ci*C_ + cg*16);
#pragma unroll
        for (int q = 0; q < 4; q++) {
            float4 wv = w4[q];
            float wr[4] = {wv.x, wv.y, wv.z, wv.w};
#pragma unroll
            for (int r = 0; r < 4; r++) {
                float wc = wr[r];
                float* a = acc + (q*4+r)*4;
                a[0] += wc*v.x; a[1] += wc*v.y; a[2] += wc*v.z; a[3] += wc*v.w;
            }
        }
    }
    // write interleaved: [b][g][p][c8]; this thread covers groups 2cg, 2cg+1
#pragma unroll
    for (int gg = 0; gg < 2; gg++) {
        int g = 2*cg + gg;
        float* og = g_x1i + ((size_t)(b*DG_+g)*HW + p0)*8;
#pragma unroll
        for (int px = 0; px < 4; px++) {
            float4 lo, hi;
            lo.x = acc[(gg*8+0)*4+px]; lo.y = acc[(gg*8+1)*4+px];
            lo.z = acc[(gg*8+2)*4+px]; lo.w = acc[(gg*8+3)*4+px];
            hi.x = acc[(gg*8+4)*4+px]; hi.y = acc[(gg*8+5)*4+px];
            hi.z = acc[(gg*8+6)*4+px]; hi.w = acc[(gg*8+7)*4+px];
            *(float4*)(og + px*8)     = lo;
            *(float4*)(og + px*8 + 4) = hi;
        }
    }
}

// ---------------- all weight transposes/packs in ONE launch ----------------
__global__ void wtrall_k(const float* __restrict__ dcn_w,
                         const float* __restrict__ a0_w,
                         const float* __restrict__ fus_w,
                         const float* __restrict__ a3_w,
                         const float* __restrict__ offm_w) {
    int i = blockIdx.x*256 + threadIdx.x;
    if (i < 18432) {
        int jp = i >> 6, co = i & 63;
        int g = jp/36, r = jp%36, k = r/4, ip = r%4;
        int c0 = ip*2;
        g_wtp[i] = packh2(dcn_w[co*C9 + g*72 + c0*9 + k],
                          dcn_w[co*C9 + g*72 + (c0+1)*9 + k]);
    } else if (i < 36864) {
        int t = i - 18432;              // [cp*9+k][co]
        int co = t & 63, j = t >> 6;
        int cp = j/9, k = j%9;
        g_wtah[t] = packh2(a0_w[co*C9 + (2*cp)*KK_ + k],
                           a0_w[co*C9 + (2*cp+1)*KK_ + k]);
    } else if (i < 55296) {
        int t = i - 36864;
        int co = t & 63, j = t >> 6;
        int cp = j/9, k = j%9;
        g_wtfh[t] = packh2(fus_w[co*C9 + (2*cp)*KK_ + k],
                           fus_w[co*C9 + (2*cp+1)*KK_ + k]);
    } else if (i < 73728) {
        int t = i - 55296;              // [cp][co576]
        int co = t % C9, cp = t / C9;
        g_wt3p[t] = packh2(a3_w[co*C_ + 2*cp], a3_w[co*C_ + 2*cp+1]);
    } else if (i < 104832) {
        int t = i - 73728;              // [cp*9+k][co216]
        int co = t % OCM, j = t / OCM;
        int cp = j/9, k = j%9;
        g_wtoh[t] = packh2(offm_w[(co*CIN + 2*cp)*KK_ + k],
                           offm_w[(co*CIN + 2*cp+1)*KK_ + k]);
    }
}

// ---------------- 2: offm conv 3x3 32->216 via fp16 m16n8k16 ---------------
__global__ void __launch_bounds__(256, 2) offmtc_k(
        const float* __restrict__ in, const float* __restrict__ bias) {
    __shared__ __align__(16) unsigned raw2[8*3*TW];   // [cipair8][row3][col132]
    __shared__ __align__(16) unsigned Bs2[9*8*BPAD];  // [k9][cipair8][co72]
    int tid = threadIdx.x, lane = tid & 31, wid = tid >> 5;
    int h = blockIdx.x, b = blockIdx.y;
    int co0 = blockIdx.z*72;
    const float* ib = in + (size_t)b*CIN*HW;
    float d[9][4];
#pragma unroll
    for (int n = 0; n < 9; n++)
#pragma unroll
        for (int r = 0; r < 4; r++) d[n][r] = 0.f;

    for (int cc = 0; cc < 2; cc++) {
        __syncthreads();
        for (int i = tid; i < 8*3*TW; i += 256) {
            int ip = i/(3*TW);
            int r  = (i/TW)%3;
            int t  = i%TW;
            int row = h + r - 1, col = t - 1;
            unsigned v = 0u;
            if (t < 130 && row >= 0 && row < H_ && col >= 0 && col < W_) {
                const float* p0 = ib + (size_t)(2*(cc*8+ip))*HW + row*W_ + col;
                v = packh2(__ldg(p0), __ldg(p0 + HW));
            }
            raw2[i] = v;
        }
        for (int i = tid; i < 9*8*72; i += 256) {
            int ks = i/(8*72);
            int ip = (i/72)%8;
            int co = i%72;
            Bs2[(ks*8+ip)*BPAD + co] =
                __ldg(g_wtoh + (size_t)((cc*8+ip)*KK_ + ks)*OCM + co0 + co);
        }
        __syncthreads();
#pragma unroll
        for (int ks = 0; ks < KK_; ks++) {
            int ky = ks/3, kx = ks%3;
            int abase = ((lane&3)*3 + ky)*TW + wid*16 + (lane>>2) + kx;
            unsigned a0 = raw2[abase];
            unsigned a1 = raw2[abase + 8];
            unsigned a2 = raw2[abase + 4*3*TW];
            unsigned a3 = raw2[abase + 4*3*TW + 8];
#pragma unroll
            for (int n = 0; n < 9; n++) {
                unsigned b0 = Bs2[(ks*8 + (lane&3))*BPAD + n*8 + (lane>>2)];
                unsigned b1 = Bs2[(ks*8 + (lane&3)+4)*BPAD + n*8 + (lane>>2)];
                asm volatile(
                    "mma.sync.aligned.m16n8k16.row.col.f32.f16.f16.f32 "
                    "{%0,%1,%2,%3}, {%4,%5,%6,%7}, {%8,%9}, {%0,%1,%2,%3};"
                    : "+f"(d[n][0]), "+f"(d[n][1]), "+f"(d[n][2]), "+f"(d[n][3])
                    : "r"(a0), "r"(a1), "r"(a2), "r"(a3), "r"(b0), "r"(b1));
            }
        }
    }
    int prow = h*W_ + wid*16 + (lane >> 2);
    float* ob = g_om + (size_t)b*OCM*HW;
#pragma unroll
    for (int n = 0; n < 9; n++) {
        int co = co0 + n*8 + (lane & 3)*2;
        float b0v = __ldg(bias + co), b1v = __ldg(bias + co + 1);
        ob[(size_t)co*HW     + prow]     = d[n][0] + b0v;
        ob[(size_t)(co+1)*HW + prow]     = d[n][1] + b1v;
        ob[(size_t)co*HW     + prow + 8] = d[n][2] + b0v;
        ob[(size_t)(co+1)*HW + prow + 8] = d[n][3] + b1v;
    }
}

// ---------------- 3: deform im2col (interleaved gather) -> packed half2 ----
__global__ void __launch_bounds__(256, 2) col_k() {
    int tid = threadIdx.x;
    int p = blockIdx.x*256 + tid;
    int gk = blockIdx.y;                 // g*9+k, 0..71
    int g = gk/9, k = gk%9;
    int b = blockIdx.z;
    int h = p >> 7, wq = p & 127;
    const float* omb = g_om + (size_t)b*OCM*HW;
    float dy = omb[(       g*9+k)*HW + p];
    float dx = omb[( 72 +  g*9+k)*HW + p];
    float mk = omb[(144 +  g*9+k)*HW + p];
    mk = 1.f/(1.f + expf(-mk));
    float py = dy + (float)(k/3) + (float)h - 1.f;
    float px = dx + (float)(k%3) + (float)wq - 1.f;
    float fy = floorf(py), fx = floorf(px);
    int y0 = (int)fy, x0 = (int)fx;
    float wy = py - fy, wx = px - fx;
    float w00 = (1.f-wy)*(1.f-wx)*mk;
    float w01 = (1.f-wy)*wx*mk;
    float w10 = wy*(1.f-wx)*mk;
    float w11 = wy*wx*mk;
    bool iy0 = (y0 >= 0 && y0 < H_);
    bool iy1 = (y0+1 >= 0 && y0+1 < H_);
    bool ix0 = (x0 >= 0 && x0 < W_);
    bool ix1 = (x0+1 >= 0 && x0+1 < W_);
    int i00 = y0*W_ + x0;
    const float* xg = g_x1i + (size_t)(b*DG_+g)*HW*8;
    float s[8] = {0.f,0.f,0.f,0.f,0.f,0.f,0.f,0.f};
#define GATHER(idx, wgt) { \
        const float4* q4 = (const float4*)(xg + (size_t)(idx)*8); \
        float4 lo = __ldg(q4), hi = __ldg(q4 + 1); \
        s[0] += (wgt)*lo.x; s[1] += (wgt)*lo.y; s[2] += (wgt)*lo.z; s[3] += (wgt)*lo.w; \
        s[4] += (wgt)*hi.x; s[5] += (wgt)*hi.y; s[6] += (wgt)*hi.z; s[7] += (wgt)*hi.w; }
    if (iy0 && ix0) GATHER(i00,        w00);
    if (iy0 && ix1) GATHER(i00+1,      w01);
    if (iy1 && ix0) GATHER(i00+W_,     w10);
    if (iy1 && ix1) GATHER(i00+W_+1,   w11);
#undef GATHER
    unsigned* cb = g_colp + (size_t)b*C9P*HW + (size_t)(g*36 + k*4)*HW + p;
#pragma unroll
    for (int i = 0; i < 4; i++)
        cb[(size_t)i*HW] = packh2(s[2*i], s[2*i+1]);
}

// ---------------- 4: dcn GEMM via fp16 m16n8k16 mma + lrelu ----------------
__global__ void __launch_bounds__(256, 2) dcntc_k(const float* __restrict__ bias) {
    __shared__ __align__(16) unsigned As2[16*A2PAD];  // [jp][px]
    __shared__ __align__(16) unsigned Bs2[16*BPAD];   // [jp][co]
    int tid = threadIdx.x, lane = tid & 31, wid = tid >> 5;
    int b = blockIdx.y;
    int p0 = blockIdx.x*128;
    const unsigned* cb = g_colp + (size_t)b*C9P*HW + p0;
    float d[8][4];
#pragma unroll
    for (int n = 0; n < 8; n++)
#pragma unroll
        for (int r = 0; r < 4; r++) d[n][r] = 0.f;

    for (int kc = 0; kc < 18; kc++) {
        __syncthreads();
#pragma unroll
        for (int r = 0; r < 2; r++) {
            int i4 = tid + r*256;
            int row = i4 >> 5, c4 = i4 & 31;
            uint4 v = *(const uint4*)(cb + (size_t)(kc*16+row)*HW + c4*4);
            *(uint4*)(As2 + row*A2PAD + c4*4) = v;
        }
        {
            int row = tid >> 4, c4 = tid & 15;
            uint4 v = *(const uint4*)(g_wtp + (size_t)(kc*16+row)*C_ + c4*4);
            *(uint4*)(Bs2 + row*BPAD + c4*4) = v;
        }
        __syncthreads();
#pragma unroll
        for (int ks = 0; ks < 2; ks++) {
            int jp0 = ks*8 + (lane & 3);
            int pa = wid*16 + (lane >> 2);
            unsigned a0 = As2[jp0*A2PAD + pa];
            unsigned a1 = As2[jp0*A2PAD + pa + 8];
            unsigned a2 = As2[(jp0+4)*A2PAD + pa];
            unsigned a3 = As2[(jp0+4)*A2PAD + pa + 8];
#pragma unroll
            for (int n = 0; n < 8; n++) {
                unsigned b0 = Bs2[jp0*BPAD + n*8 + (lane >> 2)];
                unsigned b1 = Bs2[(jp0+4)*BPAD + n*8 + (lane >> 2)];
                asm volatile(
                    "mma.sync.aligned.m16n8k16.row.col.f32.f16.f16.f32 "
                    "{%0,%1,%2,%3}, {%4,%5,%6,%7}, {%8,%9}, {%0,%1,%2,%3};"
                    : "+f"(d[n][0]), "+f"(d[n][1]), "+f"(d[n][2]), "+f"(d[n][3])
                    : "r"(a0), "r"(a1), "r"(a2), "r"(a3), "r"(b0), "r"(b1));
            }
        }
    }
    int prow = p0 + wid*16 + (lane >> 2);
    float* ob = g_dcn + (size_t)b*C_*HW;
    unsigned* oh = g_dch + (size_t)b*32*HW;
#pragma unroll
    for (int n = 0; n < 8; n++) {
        int co = n*8 + (lane & 3)*2;
        int cp = n*4 + (lane & 3);
        float b0v = __ldg(bias + co), b1v = __ldg(bias + co + 1);
        float v0 = d[n][0] + b0v, v1 = d[n][1] + b1v;
        float v2 = d[n][2] + b0v, v3 = d[n][3] + b1v;
        v0 = (v0 >= 0.f) ? v0 : 0.2f*v0;
        v1 = (v1 >= 0.f) ? v1 : 0.2f*v1;
        v2 = (v2 >= 0.f) ? v2 : 0.2f*v2;
        v3 = (v3 >= 0.f) ? v3 : 0.2f*v3;
        ob[(size_t)co*HW     + prow]     = v0;
        ob[(size_t)(co+1)*HW + prow]     = v1;
        ob[(size_t)co*HW     + prow + 8] = v2;
        ob[(size_t)(co+1)*HW + prow + 8] = v3;
        oh[(size_t)cp*HW + prow]     = packh2(v0, v1);
        oh[(size_t)cp*HW + prow + 8] = packh2(v2, v3);
    }
}

// ---------------- 5: conv3x3 64->64 via fp16 mma, 2 rows per CTA -----------
template <int FUSE>
__device__ __forceinline__ void conv3tc_f16(
        const unsigned* __restrict__ inh, const unsigned* __restrict__ wth,
        const float* __restrict__ bias, const float* __restrict__ pre,
        float* __restrict__ outp) {
    __shared__ __align__(16) unsigned raw2[8*4*TW];   // [pair8][row4][col132]
    __shared__ __align__(16) unsigned Bs2[9*8*BPAD];  // [k9][pair8][co]
    int tid = threadIdx.x, lane = tid & 31, wid = tid >> 5;
    int h0 = blockIdx.x*2;
    float d[2][8][4];
#pragma unroll
    for (int hr = 0; hr < 2; hr++)
#pragma unroll
        for (int n = 0; n < 8; n++)
#pragma unroll
            for (int r = 0; r < 4; r++) d[hr][n][r] = 0.f;

    for (int cc = 0; cc < 4; cc++) {
        __syncthreads();
        for (int i = tid; i < 8*4*TW; i += 256) {
            int ip = i/(4*TW);
            int r  = (i/TW)&3;
            int t  = i%TW;
            int row = h0 + r - 1, col = t - 1;
            unsigned v = 0u;
            if (t < 130 && row >= 0 && row < H_ && col >= 0 && col < W_)
                v = __ldg(inh + (size_t)(cc*8+ip)*HW + row*W_ + col);
            raw2[i] = v;
        }
        for (int i = tid; i < 9*8*C_; i += 256) {
            int ks = i/(8*C_);
            int ip = (i/C_)%8;
            int co = i & 63;
            Bs2[(ks*8+ip)*BPAD + co] =
                __ldg(wth + (size_t)((cc*8+ip)*KK_ + ks)*C_ + co);
        }
        __syncthreads();
#pragma unroll
        for (int ks = 0; ks < KK_; ks++) {
            int ky = ks/3, kx = ks%3;
            unsigned b0v[8], b1v[8];
#pragma unroll
            for (int n = 0; n < 8; n++) {
                b0v[n] = Bs2[(ks*8 + (lane&3))*BPAD + n*8 + (lane>>2)];
                b1v[n] = Bs2[(ks*8 + (lane&3)+4)*BPAD + n*8 + (lane>>2)];
            }
#pragma unroll
            for (int hr = 0; hr < 2; hr++) {
                int abase = ((lane&3)*4 + hr + ky)*TW + wid*16 + (lane>>2) + kx;
                unsigned a0 = raw2[abase];
                unsigned a1 = raw2[abase + 8];
                unsigned a2 = raw2[abase + 4*4*TW];
                unsigned a3 = raw2[abase + 4*4*TW + 8];
#pragma unroll
                for (int n = 0; n < 8; n++) {
                    asm volatile(
                        "mma.sync.aligned.m16n8k16.row.col.f32.f16.f16.f32 "
                        "{%0,%1,%2,%3}, {%4,%5,%6,%7}, {%8,%9}, {%0,%1,%2,%3};"
                        : "+f"(d[hr][n][0]), "+f"(d[hr][n][1]),
                          "+f"(d[hr][n][2]), "+f"(d[hr][n][3])
                        : "r"(a0), "r"(a1), "r"(a2), "r"(a3),
                          "r"(b0v[n]), "r"(b1v[n]));
                }
            }
        }
    }
#pragma unroll
    for (int hr = 0; hr < 2; hr++) {
        int prow = (h0+hr)*W_ + wid*16 + (lane >> 2);
#pragma unroll
        for (int n = 0; n < 8; n++) {
            int co = n*8 + (lane & 3)*2;
            float b0v = __ldg(bias + co), b1v = __ldg(bias + co + 1);
            float v0 = d[hr][n][0] + b0v, v1 = d[hr][n][1] + b1v;
            float v2 = d[hr][n][2] + b0v, v3 = d[hr][n][3] + b1v;
            if (FUSE) {
                v0 += 2.f*__ldg(pre + (size_t)co*HW     + prow);
                v1 += 2.f*__ldg(pre + (size_t)(co+1)*HW + prow);
                v2 += 2.f*__ldg(pre + (size_t)co*HW     + prow + 8);
                v3 += 2.f*__ldg(pre + (size_t)(co+1)*HW + prow + 8);
            }
            outp[(size_t)co*HW     + prow]     = v0;
            outp[(size_t)(co+1)*HW + prow]     = v1;
            outp[(size_t)co*HW     + prow + 8] = v2;
            outp[(size_t)(co+1)*HW + prow + 8] = v3;
        }
    }
}

__global__ void __launch_bounds__(256, 2) conv_a0tc_k(const float* __restrict__ bias) {
    int b = blockIdx.y;
    conv3tc_f16<0>(g_dch + (size_t)b*32*HW, g_wtah, bias, nullptr,
                   g_x0 + (size_t)b*C_*HW);
}

__global__ void __launch_bounds__(256, 2) conv_fustc_k(
        const float* __restrict__ bias, float* __restrict__ out) {
    int b = blockIdx.y;
    conv3tc_f16<1>(g_outh + (size_t)b*32*HW, g_wtfh, bias,
                   g_dcn + (size_t)b*C_*HW, out + (size_t)b*C_*HW);
}

// ---------------- 6: depthwise 3x3 on g_x0 -> packed g_x1dh ----------------
__global__ void __launch_bounds__(256, 4) dw_k(
        const float* __restrict__ w, const float* __restrict__ bias) {
    int tid = threadIdx.x;
    int cp = blockIdx.y, b = blockIdx.z;
    int p = blockIdx.x*256 + tid;
    int h = p >> 7, wq = p & 127;
    int c0 = 2*cp;
    const float* ic0 = g_x0 + ((size_t)b*C_ + c0)*HW;
    const float* ic1 = ic0 + HW;
    float a0v = __ldg(bias + c0), a1v = __ldg(bias + c0 + 1);
#pragma unroll
    for (int ky = 0; ky < 3; ky++) {
        int hy = h + ky - 1;
        bool oky = (hy >= 0 && hy < H_);
#pragma unroll
        for (int kx = 0; kx < 3; kx++) {
            int wx = wq + kx - 1;
            bool ok = (oky && wx >= 0 && wx < W_);
            float v0 = ok ? __ldg(ic0 + hy*W_ + wx) : 0.f;
            float v1 = ok ? __ldg(ic1 + hy*W_ + wx) : 0.f;
            a0v += __ldg(w + c0*KK_ + ky*3+kx)*v0;
            a1v += __ldg(w + (c0+1)*KK_ + ky*3+kx)*v1;
        }
    }
    g_x1dh[((size_t)b*32 + cp)*HW + p] = packh2(a0v, a1v);
}

// ---------------- 7: per-(b,c) mean of g_x0 --------------------------------
__global__ void mean_k() {
    __shared__ float sd[256];
    int bc = blockIdx.x;
    const float* ic = g_x0 + (size_t)bc*HW;
    float s = 0.f;
    for (int i = threadIdx.x; i < HW; i += 256) s += ic[i];
    sd[threadIdx.x] = s;
    __syncthreads();
    for (int st = 128; st > 0; st >>= 1) {
        if (threadIdx.x < st) sd[threadIdx.x] += sd[threadIdx.x+st];
        __syncthreads();
    }
    if (threadIdx.x == 0) g_s[bc] = sd[0]*(1.f/(float)HW);
}

// ---------------- 8: ECA + fold into a3 effective bias (one kernel) --------
__global__ void ecafuse_k(const float* __restrict__ a3w,
                          const float* __restrict__ a3b,
                          const float* __restrict__ w2,
                          const float* __restrict__ b2) {
    __shared__ float eca_s[C_];
    int b = blockIdx.x;
    int co = threadIdx.x;                // 0..575
    if (co < C_) {
        int i = b*C_ + co;
        float sm1 = (co > 0)  ? g_s[i-1] : 0.f;
        float s0  = g_s[i];
        float sp1 = (co < 63) ? g_s[i+1] : 0.f;
        eca_s[co] = __ldg(w2+0)*sm1 + __ldg(w2+1)*s0 + __ldg(w2+2)*sp1 + __ldg(b2);
    }
    __syncthreads();
    float s = __ldg(a3b + co);
    const float* wr = a3w + (size_t)co*C_;
#pragma unroll 8
    for (int ci = 0; ci < C_; ci++)
        s += __ldg(wr + ci)*eca_s[ci];
    g_beff[b*C9 + co] = s;
}

// ---------------- 9: a3 1x1 (64->576) via fp16 mma + dyn filter + lrelu ----
__global__ void __launch_bounds__(256, 2) a3tc_k() {
    __shared__ __align__(16) float buf[72*TW];   // phase2/3 filt [co72][pxTW]
    unsigned* As2 = (unsigned*)buf;              // phase1: [16][A2PAD]
    unsigned* Bs2 = (unsigned*)buf + 16*A2PAD;   //         [16][BPAD]
    int tid = threadIdx.x, lane = tid & 31, wid = tid >> 5;
    int h = blockIdx.x, b = blockIdx.y;
    int cc = blockIdx.z;
    int co0 = cc*72;
    const unsigned* inb = g_x1dh + (size_t)b*32*HW + h*W_;
    float d[9][4];
#pragma unroll
    for (int n = 0; n < 9; n++)
#pragma unroll
        for (int r = 0; r < 4; r++) d[n][r] = 0.f;

    for (int kc = 0; kc < 2; kc++) {
        __syncthreads();
#pragma unroll
        for (int r = 0; r < 2; r++) {
            int i4 = tid + r*256;                // 0..511
            int row = i4 >> 5, c4 = i4 & 31;
            uint4 v = *(const uint4*)(inb + (size_t)(kc*16+row)*HW + c4*4);
            *(uint4*)(As2 + row*A2PAD + c4*4) = v;
        }
        for (int i = tid; i < 16*72; i += 256) {
            int row = i/72, co = i%72;
            Bs2[row*BPAD + co] = __ldg(g_wt3p + (size_t)(kc*16+row)*C9 + co0 + co);
        }
        __syncthreads();
#pragma unroll
        for (int ks = 0; ks < 2; ks++) {
            int jp0 = ks*8 + (lane & 3);
            int pa = wid*16 + (lane >> 2);
            unsigned a0 = As2[jp0*A2PAD + pa];
            unsigned a1 = As2[jp0*A2PAD + pa + 8];
            unsigned a2 = As2[(jp0+4)*A2PAD + pa];
            unsigned a3 = As2[(jp0+4)*A2PAD + pa + 8];
#pragma unroll
            for (int n = 0; n < 9; n++) {
                unsigned b0 = Bs2[jp0*BPAD + n*8 + (lane >> 2)];
                unsigned b1 = Bs2[(jp0+4)*BPAD + n*8 + (lane >> 2)];
                asm volatile(
                    "mma.sync.aligned.m16n8k16.row.col.f32.f16.f16.f32 "
                    "{%0,%1,%2,%3}, {%4,%5,%6,%7}, {%8,%9}, {%0,%1,%2,%3};"
                    : "+f"(d[n][0]), "+f"(d[n][1]), "+f"(d[n][2]), "+f"(d[n][3])
                    : "r"(a0), "r"(a1), "r"(a2), "r"(a3), "r"(b0), "r"(b1));
            }
        }
    }
    __syncthreads();
    float* filt = buf;
    int px = wid*16 + (lane >> 2);
#pragma unroll
    for (int n = 0; n < 9; n++) {
        int co = n*8 + (lane & 3)*2;
        float b0v = __ldg(g_beff + b*C9 + co0 + co);
        float b1v = __ldg(g_beff + b*C9 + co0 + co + 1);
        filt[co*TW     + px]     = d[n][0] + b0v;
        filt[(co+1)*TW + px]     = d[n][1] + b1v;
        filt[co*TW     + px + 8] = d[n][2] + b0v;
        filt[(co+1)*TW + px + 8] = d[n][3] + b1v;
    }
    __syncthreads();
    // phase 3: apply dyn filter; each thread handles 2 channel PAIRS
    int p  = tid & 127;
    int half = tid >> 7;
    const float* x0b = g_x0 + (size_t)b*C_*HW;
    unsigned* oh = g_outh + (size_t)b*32*HW + h*W_;
#pragma unroll
    for (int cq = 0; cq < 2; cq++) {
        int q = half*2 + cq;
        float o2[2];
#pragma unroll
        for (int e = 0; e < 2; e++) {
            int c8 = q*2 + e;
            int c = cc*8 + c8;
            const float* ic = x0b + (size_t)c*HW;
            float o = 0.f;
#pragma unroll
            for (int ky = 0; ky < 3; ky++) {
                int hy = h + ky - 1;
                bool oy = (hy >= 0 && hy < H_);
                const float* icr = ic + hy*W_;
#pragma unroll
                for (int kx = 0; kx < 3; kx++) {
                    int wx = p + kx - 1;
                    float v = (oy && wx >= 0 && wx < W_) ? __ldg(icr + wx) : 0.f;
                    o += filt[(c8*KK_ + ky*3+kx)*TW + p]*v;
                }
            }
            o2[e] = (o >= 0.f) ? o : 0.2f*o;
        }
        oh[(size_t)(cc*4 + q)*HW + p] = packh2(o2[0], o2[1]);
    }
}

// ---------------- launch ----------------------------------------------------
extern "C" void kernel_launch(void* const* d_in, const int* in_sizes, int n_in,
                              void* d_out, int out_size) {
    const float* x       = (const float*)d_in[0];
    const float* offset  = (const float*)d_in[1];
    const float* conv0_w = (const float*)d_in[2];
    const float* conv0_b = (const float*)d_in[3];
    const float* offm_w  = (const float*)d_in[4];
    const float* offm_b  = (const float*)d_in[5];
    const float* dcn_w   = (const float*)d_in[6];
    const float* dcn_b   = (const float*)d_in[7];
    const float* a0_w    = (const float*)d_in[8];
    const float* a0_b    = (const float*)d_in[9];
    const float* a1_w    = (const float*)d_in[10];
    const float* a1_b    = (const float*)d_in[11];
    const float* a2_w    = (const float*)d_in[12];
    const float* a2_b    = (const float*)d_in[13];
    const float* a3_w    = (const float*)d_in[14];
    const float* a3_b    = (const float*)d_in[15];
    const float* fus_w   = (const float*)d_in[16];
    const float* fus_b   = (const float*)d_in[17];
    float* out = (float*)d_out;

    dim3 gp(HW/256, B_);
    wtrall_k <<<(104832 + 255)/256, 256>>>(dcn_w, a0_w, fus_w, a3_w, offm_w);
    conv0_k  <<<gp, 256>>>(x, conv0_w, conv0_b);
    offmtc_k <<<dim3(H_, B_, 3), 256>>>(offset, offm_b);
    col_k    <<<dim3(HW/256, DG_*KK_, B_), 256>>>();
    dcntc_k  <<<dim3(HW/128, B_), 256>>>(dcn_b);
    conv_a0tc_k<<<dim3(H_/2, B_), 256>>>(a0_b);
    dw_k     <<<dim3(HW/256, 32, B_), 256>>>(a1_w, a1_b);
    mean_k   <<<B_*C_, 256>>>();
    ecafuse_k<<<B_, C9>>>(a3_w, a3_b, a2_w, a2_b);
    a3tc_k   <<<dim3(H_, B_, 8), 256>>>();
    conv_fustc_k<<<dim3(H_/2, B_), 256>>>(fus_b, out);
}

// round 16
// speedup vs baseline: 2.8318x; 1.0108x over previous
#include <cuda_runtime.h>
#include <cuda_bf16.h>
#include <cuda_fp16.h>
#include <math.h>

// Problem constants
#define B_   4
#define CIN  32
#define C_   64
#define H_   128
#define W_   128
#define HW   16384
#define DG_  8
#define CPG  8
#define KK_  9
#define OCM  216   // DG*3*K*K
#define C9   576   // C*9
#define C9P  288   // C9/2 packed rows

// ---------------- scratch (device globals; no allocation allowed) ----------
__device__ float g_x1 [B_*C_ *HW];     // conv0 out (planar)
__device__ float g_om [B_*OCM*HW];     // offset/mask conv out
__device__ float g_dcn[B_*C_ *HW];     // lrelu(deform conv) fp32 (residual use)
__device__ unsigned g_dch[B_*32*HW];   // same, packed half2 channel pairs
__device__ unsigned g_outh[B_*32*HW];  // dynamic-filter out, packed half2 pairs
__device__ unsigned g_colp[B_*C9P*HW]; // packed half2 im2col [b][jp][p]
__device__ unsigned g_x1dh[B_*32*HW];  // depthwise out, packed half2 pairs
__device__ unsigned g_wtp [C9P*C_];    // dcn weights packed half2 [jp][co]
__device__ unsigned g_wtah[32*KK_*C_]; // a0 weights packed [cipair*9+k][co]
__device__ unsigned g_wtfh[32*KK_*C_]; // fus weights packed [cipair*9+k][co]
__device__ unsigned g_wt3p[32*C9];     // a3 weights packed [cipair][co576]
__device__ unsigned g_wtoh[16*KK_*OCM];// offm weights packed [cipair*9+k][co216]
__device__ float g_beff[B_*C9];        // a3 bias + a3_w . eca
__device__ float g_x0 [B_*C_ *HW];     // a0 conv out
__device__ float g_s  [B_*C_];         // channel SUMS of x0 (zeroed per launch)

__device__ __forceinline__ unsigned packh2(float a, float b) {
    __half2 h = __floats2half2_rn(a, b);
    return *(unsigned*)&h;
}

#define APAD 136
#define BPAD 72
#define TW 132
#define A2PAD 136
#define A3PAD 264

// ---------------- 1: conv0 1x1, 32->64 : 4px x 16co (planar out) -----------
__global__ void __launch_bounds__(256, 2) conv0_k(
        const float* __restrict__ x, const float* __restrict__ w,
        const float* __restrict__ bias) {
    __shared__ __align__(16) float ws[CIN*C_];   // [ci][co]
    int tid = threadIdx.x;
    int quad = tid & 63, cg = tid >> 6;
    for (int i = tid; i < C_*CIN; i += 256) {
        int ci = i >> 6, co = i & 63;
        ws[ci*C_ + co] = w[co*CIN + ci];
    }
    __syncthreads();
    int b = blockIdx.y;
    int p0 = blockIdx.x*256 + quad*4;
    const float* xb = x + (size_t)b*CIN*HW + p0;
    float acc[64];
#pragma unroll
    for (int c = 0; c < 16; c++) {
        float bv = __ldg(bias + cg*16 + c);
        acc[c*4+0] = bv; acc[c*4+1] = bv; acc[c*4+2] = bv; acc[c*4+3] = bv;
    }
    for (int ci = 0; ci < CIN; ci++) {
        float4 v = *(const float4*)(xb + (size_t)ci*HW);
        const float4* w4 = (const float4*)(ws + ci*C_ + cg*16);
#pragma unroll
        for (int q = 0; q < 4; q++) {
            float4 wv = w4[q];
            float wr[4] = {wv.x, wv.y, wv.z, wv.w};
#pragma unroll
            for (int r = 0; r < 4; r++) {
                float wc = wr[r];
                float* a = acc + (q*4+r)*4;
                a[0] += wc*v.x; a[1] += wc*v.y; a[2] += wc*v.z; a[3] += wc*v.w;
            }
        }
    }
    float* ob = g_x1 + (size_t)b*C_*HW + p0;
#pragma unroll
    for (int c = 0; c < 16; c++)
        *(float4*)(ob + (size_t)(cg*16+c)*HW) =
            make_float4(acc[c*4+0], acc[c*4+1], acc[c*4+2], acc[c*4+3]);
}

// ---------------- all weight transposes/packs + g_s zero in ONE launch -----
__global__ void wtrall_k(const float* __restrict__ dcn_w,
                         const float* __restrict__ a0_w,
                         const float* __restrict__ fus_w,
                         const float* __restrict__ a3_w,
                         const float* __restrict__ offm_w) {
    int i = blockIdx.x*256 + threadIdx.x;
    if (i < B_*C_) g_s[i] = 0.f;        // zero mean accumulators each launch
    if (i < 18432) {
        int jp = i >> 6, co = i & 63;
        int g = jp/36, r = jp%36, k = r/4, ip = r%4;
        int c0 = ip*2;
        g_wtp[i] = packh2(dcn_w[co*C9 + g*72 + c0*9 + k],
                          dcn_w[co*C9 + g*72 + (c0+1)*9 + k]);
    } else if (i < 36864) {
        int t = i - 18432;              // [cp*9+k][co]
        int co = t & 63, j = t >> 6;
        int cp = j/9, k = j%9;
        g_wtah[t] = packh2(a0_w[co*C9 + (2*cp)*KK_ + k],
                           a0_w[co*C9 + (2*cp+1)*KK_ + k]);
    } else if (i < 55296) {
        int t = i - 36864;
        int co = t & 63, j = t >> 6;
        int cp = j/9, k = j%9;
        g_wtfh[t] = packh2(fus_w[co*C9 + (2*cp)*KK_ + k],
                           fus_w[co*C9 + (2*cp+1)*KK_ + k]);
    } else if (i < 73728) {
        int t = i - 55296;              // [cp][co576]
        int co = t % C9, cp = t / C9;
        g_wt3p[t] = packh2(a3_w[co*C_ + 2*cp], a3_w[co*C_ + 2*cp+1]);
    } else if (i < 104832) {
        int t = i - 73728;              // [cp*9+k][co216]
        int co = t % OCM, j = t / OCM;
        int cp = j/9, k = j%9;
        g_wtoh[t] = packh2(offm_w[(co*CIN + 2*cp)*KK_ + k],
                           offm_w[(co*CIN + 2*cp+1)*KK_ + k]);
    }
}

// ---------------- 2: offm conv 3x3 32->216 via fp16 m16n8k16 ---------------
__global__ void __launch_bounds__(256, 2) offmtc_k(
        const float* __restrict__ in, const float* __restrict__ bias) {
    __shared__ __align__(16) unsigned raw2[8*3*TW];   // [cipair8][row3][col132]
    __shared__ __align__(16) unsigned Bs2[9*8*BPAD];  // [k9][cipair8][co72]
    int tid = threadIdx.x, lane = tid & 31, wid = tid >> 5;
    int h = blockIdx.x, b = blockIdx.y;
    int co0 = blockIdx.z*72;
    const float* ib = in + (size_t)b*CIN*HW;
    float d[9][4];
#pragma unroll
    for (int n = 0; n < 9; n++)
#pragma unroll
        for (int r = 0; r < 4; r++) d[n][r] = 0.f;

    for (int cc = 0; cc < 2; cc++) {
        __syncthreads();
        for (int i = tid; i < 8*3*TW; i += 256) {
            int ip = i/(3*TW);
            int r  = (i/TW)%3;
            int t  = i%TW;
            int row = h + r - 1, col = t - 1;
            unsigned v = 0u;
            if (t < 130 && row >= 0 && row < H_ && col >= 0 && col < W_) {
                const float* p0 = ib + (size_t)(2*(cc*8+ip))*HW + row*W_ + col;
                v = packh2(__ldg(p0), __ldg(p0 + HW));
            }
            raw2[i] = v;
        }
        for (int i = tid; i < 9*8*72; i += 256) {
            int ks = i/(8*72);
            int ip = (i/72)%8;
            int co = i%72;
            Bs2[(ks*8+ip)*BPAD + co] =
                __ldg(g_wtoh + (size_t)((cc*8+ip)*KK_ + ks)*OCM + co0 + co);
        }
        __syncthreads();
#pragma unroll
        for (int ks = 0; ks < KK_; ks++) {
            int ky = ks/3, kx = ks%3;
            int abase = ((lane&3)*3 + ky)*TW + wid*16 + (lane>>2) + kx;
            unsigned a0 = raw2[abase];
            unsigned a1 = raw2[abase + 8];
            unsigned a2 = raw2[abase + 4*3*TW];
            unsigned a3 = raw2[abase + 4*3*TW + 8];
#pragma unroll
            for (int n = 0; n < 9; n++) {
                unsigned b0 = Bs2[(ks*8 + (lane&3))*BPAD + n*8 + (lane>>2)];
                unsigned b1 = Bs2[(ks*8 + (lane&3)+4)*BPAD + n*8 + (lane>>2)];
                asm volatile(
                    "mma.sync.aligned.m16n8k16.row.col.f32.f16.f16.f32 "
                    "{%0,%1,%2,%3}, {%4,%5,%6,%7}, {%8,%9}, {%0,%1,%2,%3};"
                    : "+f"(d[n][0]), "+f"(d[n][1]), "+f"(d[n][2]), "+f"(d[n][3])
                    : "r"(a0), "r"(a1), "r"(a2), "r"(a3), "r"(b0), "r"(b1));
            }
        }
    }
    int prow = h*W_ + wid*16 + (lane >> 2);
    float* ob = g_om + (size_t)b*OCM*HW;
#pragma unroll
    for (int n = 0; n < 9; n++) {
        int co = co0 + n*8 + (lane & 3)*2;
        float b0v = __ldg(bias + co), b1v = __ldg(bias + co + 1);
        ob[(size_t)co*HW     + prow]     = d[n][0] + b0v;
        ob[(size_t)(co+1)*HW + prow]     = d[n][1] + b1v;
        ob[(size_t)co*HW     + prow + 8] = d[n][2] + b0v;
        ob[(size_t)(co+1)*HW + prow + 8] = d[n][3] + b1v;
    }
}

// ---------------- 3: deform im2col (planar gather) -> packed half2 ---------
__global__ void __launch_bounds__(256, 2) col_k() {
    int tid = threadIdx.x;
    int p = blockIdx.x*256 + tid;
    int gk = blockIdx.y;                 // g*9+k, 0..71
    int g = gk/9, k = gk%9;
    int b = blockIdx.z;
    int h = p >> 7, wq = p & 127;
    const float* omb = g_om + (size_t)b*OCM*HW;
    float dy = omb[(       g*9+k)*HW + p];
    float dx = omb[( 72 +  g*9+k)*HW + p];
    float mk = omb[(144 +  g*9+k)*HW + p];
    mk = 1.f/(1.f + expf(-mk));
    float py = dy + (float)(k/3) + (float)h - 1.f;
    float px = dx + (float)(k%3) + (float)wq - 1.f;
    float fy = floorf(py), fx = floorf(px);
    int y0 = (int)fy, x0 = (int)fx;
    float wy = py - fy, wx = px - fx;
    float w00 = (1.f-wy)*(1.f-wx)*mk;
    float w01 = (1.f-wy)*wx*mk;
    float w10 = wy*(1.f-wx)*mk;
    float w11 = wy*wx*mk;
    bool iy0 = (y0 >= 0 && y0 < H_);
    bool iy1 = (y0+1 >= 0 && y0+1 < H_);
    bool ix0 = (x0 >= 0 && x0 < W_);
    bool ix1 = (x0+1 >= 0 && x0+1 < W_);
    bool v00 = iy0 && ix0, v01 = iy0 && ix1, v10 = iy1 && ix0, v11 = iy1 && ix1;
    int i00 = y0*W_ + x0;
    const float* xb = g_x1 + (size_t)b*C_*HW + (size_t)g*CPG*HW;
    float s[CPG];
#pragma unroll
    for (int c = 0; c < CPG; c++) {
        const float* xc = xb + c*HW;
        float sv = 0.f;
        if (v00) sv += w00*__ldg(xc + i00);
        if (v01) sv += w01*__ldg(xc + i00 + 1);
        if (v10) sv += w10*__ldg(xc + i00 + W_);
        if (v11) sv += w11*__ldg(xc + i00 + W_ + 1);
        s[c] = sv;
    }
    unsigned* cb = g_colp + (size_t)b*C9P*HW + (size_t)(g*36 + k*4)*HW + p;
#pragma unroll
    for (int i = 0; i < 4; i++)
        cb[(size_t)i*HW] = packh2(s[2*i], s[2*i+1]);
}

// ---------------- 4: dcn GEMM fp16 m16n8k16, 256 px per CTA ----------------
__global__ void __launch_bounds__(256, 2) dcntc_k(const float* __restrict__ bias) {
    __shared__ __align__(16) unsigned As2[16*A3PAD];  // [jp][px256]
    __shared__ __align__(16) unsigned Bs2[16*BPAD];   // [jp][co]
    int tid = threadIdx.x, lane = tid & 31, wid = tid >> 5;
    int b = blockIdx.y;
    int p0 = blockIdx.x*256;
    const unsigned* cb = g_colp + (size_t)b*C9P*HW + p0;
    float d[2][8][4];
#pragma unroll
    for (int s = 0; s < 2; s++)
#pragma unroll
        for (int n = 0; n < 8; n++)
#pragma unroll
            for (int r = 0; r < 4; r++) d[s][n][r] = 0.f;

    for (int kc = 0; kc < 18; kc++) {
        __syncthreads();
#pragma unroll
        for (int r = 0; r < 4; r++) {
            int i4 = tid + r*256;               // 0..1023
            int row = i4 >> 6, c4 = i4 & 63;
            uint4 v = *(const uint4*)(cb + (size_t)(kc*16+row)*HW + c4*4);
            *(uint4*)(As2 + row*A3PAD + c4*4) = v;
        }
        {
            int row = tid >> 4, c4 = tid & 15;
            uint4 v = *(const uint4*)(g_wtp + (size_t)(kc*16+row)*C_ + c4*4);
            *(uint4*)(Bs2 + row*BPAD + c4*4) = v;
        }
        __syncthreads();
#pragma unroll
        for (int ks = 0; ks < 2; ks++) {
            int jp0 = ks*8 + (lane & 3);
            unsigned af[2][4];
#pragma unroll
            for (int s = 0; s < 2; s++) {
                int pa = wid*32 + s*16 + (lane >> 2);
                af[s][0] = As2[jp0*A3PAD + pa];
                af[s][1] = As2[jp0*A3PAD + pa + 8];
                af[s][2] = As2[(jp0+4)*A3PAD + pa];
                af[s][3] = As2[(jp0+4)*A3PAD + pa + 8];
            }
#pragma unroll
            for (int n = 0; n < 8; n++) {
                unsigned b0 = Bs2[jp0*BPAD + n*8 + (lane >> 2)];
                unsigned b1 = Bs2[(jp0+4)*BPAD + n*8 + (lane >> 2)];
#pragma unroll
                for (int s = 0; s < 2; s++) {
                    asm volatile(
                        "mma.sync.aligned.m16n8k16.row.col.f32.f16.f16.f32 "
                        "{%0,%1,%2,%3}, {%4,%5,%6,%7}, {%8,%9}, {%0,%1,%2,%3};"
                        : "+f"(d[s][n][0]), "+f"(d[s][n][1]),
                          "+f"(d[s][n][2]), "+f"(d[s][n][3])
                        : "r"(af[s][0]), "r"(af[s][1]), "r"(af[s][2]), "r"(af[s][3]),
                          "r"(b0), "r"(b1));
                }
            }
        }
    }
    float* ob = g_dcn + (size_t)b*C_*HW;
    unsigned* oh = g_dch + (size_t)b*32*HW;
#pragma unroll
    for (int s = 0; s < 2; s++) {
        int prow = p0 + wid*32 + s*16 + (lane >> 2);
#pragma unroll
        for (int n = 0; n < 8; n++) {
            int co = n*8 + (lane & 3)*2;
            int cp = n*4 + (lane & 3);
            float b0v = __ldg(bias + co), b1v = __ldg(bias + co + 1);
            float v0 = d[s][n][0] + b0v, v1 = d[s][n][1] + b1v;
            float v2 = d[s][n][2] + b0v, v3 = d[s][n][3] + b1v;
            v0 = (v0 >= 0.f) ? v0 : 0.2f*v0;
            v1 = (v1 >= 0.f) ? v1 : 0.2f*v1;
            v2 = (v2 >= 0.f) ? v2 : 0.2f*v2;
            v3 = (v3 >= 0.f) ? v3 : 0.2f*v3;
            ob[(size_t)co*HW     + prow]     = v0;
            ob[(size_t)(co+1)*HW + prow]     = v1;
            ob[(size_t)co*HW     + prow + 8] = v2;
            ob[(size_t)(co+1)*HW + prow + 8] = v3;
            oh[(size_t)cp*HW + prow]     = packh2(v0, v1);
            oh[(size_t)cp*HW + prow + 8] = packh2(v2, v3);
        }
    }
}

// ---------------- 5: conv3x3 64->64 fp16 mma, 2 rows/CTA (+opt mean) -------
template <int FUSE, int MEAN>
__device__ __forceinline__ void conv3tc_f16(
        const unsigned* __restrict__ inh, const unsigned* __restrict__ wth,
        const float* __restrict__ bias, const float* __restrict__ pre,
        float* __restrict__ outp, int b) {
    __shared__ __align__(16) unsigned raw2[8*4*TW];   // [pair8][row4][col132]
    __shared__ __align__(16) unsigned Bs2[9*8*BPAD];  // [k9][pair8][co]
    __shared__ float red[C_];
    int tid = threadIdx.x, lane = tid & 31, wid = tid >> 5;
    int h0 = blockIdx.x*2;
    if (MEAN && tid < C_) red[tid] = 0.f;
    float d[2][8][4];
#pragma unroll
    for (int hr = 0; hr < 2; hr++)
#pragma unroll
        for (int n = 0; n < 8; n++)
#pragma unroll
            for (int r = 0; r < 4; r++) d[hr][n][r] = 0.f;

    for (int cc = 0; cc < 4; cc++) {
        __syncthreads();
        for (int i = tid; i < 8*4*TW; i += 256) {
            int ip = i/(4*TW);
            int r  = (i/TW)&3;
            int t  = i%TW;
            int row = h0 + r - 1, col = t - 1;
            unsigned v = 0u;
            if (t < 130 && row >= 0 && row < H_ && col >= 0 && col < W_)
                v = __ldg(inh + (size_t)(cc*8+ip)*HW + row*W_ + col);
            raw2[i] = v;
        }
        for (int i = tid; i < 9*8*C_; i += 256) {
            int ks = i/(8*C_);
            int ip = (i/C_)%8;
            int co = i & 63;
            Bs2[(ks*8+ip)*BPAD + co] =
                __ldg(wth + (size_t)((cc*8+ip)*KK_ + ks)*C_ + co);
        }
        __syncthreads();
#pragma unroll
        for (int ks = 0; ks < KK_; ks++) {
            int ky = ks/3, kx = ks%3;
            unsigned b0v[8], b1v[8];
#pragma unroll
            for (int n = 0; n < 8; n++) {
                b0v[n] = Bs2[(ks*8 + (lane&3))*BPAD + n*8 + (lane>>2)];
                b1v[n] = Bs2[(ks*8 + (lane&3)+4)*BPAD + n*8 + (lane>>2)];
            }
#pragma unroll
            for (int hr = 0; hr < 2; hr++) {
                int abase = ((lane&3)*4 + hr + ky)*TW + wid*16 + (lane>>2) + kx;
                unsigned a0 = raw2[abase];
                unsigned a1 = raw2[abase + 8];
                unsigned a2 = raw2[abase + 4*4*TW];
                unsigned a3 = raw2[abase + 4*4*TW + 8];
#pragma unroll
                for (int n = 0; n < 8; n++) {
                    asm volatile(
                        "mma.sync.aligned.m16n8k16.row.col.f32.f16.f16.f32 "
                        "{%0,%1,%2,%3}, {%4,%5,%6,%7}, {%8,%9}, {%0,%1,%2,%3};"
                        : "+f"(d[hr][n][0]), "+f"(d[hr][n][1]),
                          "+f"(d[hr][n][2]), "+f"(d[hr][n][3])
                        : "r"(a0), "r"(a1), "r"(a2), "r"(a3),
                          "r"(b0v[n]), "r"(b1v[n]));
                }
            }
        }
    }
#pragma unroll
    for (int hr = 0; hr < 2; hr++) {
        int prow = (h0+hr)*W_ + wid*16 + (lane >> 2);
#pragma unroll
        for (int n = 0; n < 8; n++) {
            int co = n*8 + (lane & 3)*2;
            float b0v = __ldg(bias + co), b1v = __ldg(bias + co + 1);
            float v0 = d[hr][n][0] + b0v, v1 = d[hr][n][1] + b1v;
            float v2 = d[hr][n][2] + b0v, v3 = d[hr][n][3] + b1v;
            if (FUSE) {
                v0 += 2.f*__ldg(pre + (size_t)co*HW     + prow);
                v1 += 2.f*__ldg(pre + (size_t)(co+1)*HW + prow);
                v2 += 2.f*__ldg(pre + (size_t)co*HW     + prow + 8);
                v3 += 2.f*__ldg(pre + (size_t)(co+1)*HW + prow + 8);
            }
            outp[(size_t)co*HW     + prow]     = v0;
            outp[(size_t)(co+1)*HW + prow]     = v1;
            outp[(size_t)co*HW     + prow + 8] = v2;
            outp[(size_t)(co+1)*HW + prow + 8] = v3;
            if (MEAN) {
                atomicAdd(&red[co],   v0 + v2);
                atomicAdd(&red[co+1], v1 + v3);
            }
        }
    }
    if (MEAN) {
        __syncthreads();
        if (tid < C_) atomicAdd(&g_s[b*C_ + tid], red[tid]);
    }
}

__global__ void __launch_bounds__(256, 2) conv_a0tc_k(const float* __restrict__ bias) {
    int b = blockIdx.y;
    conv3tc_f16<0,1>(g_dch + (size_t)b*32*HW, g_wtah, bias, nullptr,
                     g_x0 + (size_t)b*C_*HW, b);
}

__global__ void __launch_bounds__(256, 2) conv_fustc_k(
        const float* __restrict__ bias, float* __restrict__ out) {
    int b = blockIdx.y;
    conv3tc_f16<1,0>(g_outh + (size_t)b*32*HW, g_wtfh, bias,
                     g_dcn + (size_t)b*C_*HW, out + (size_t)b*C_*HW, b);
}

// ---------------- 6: depthwise 3x3 on g_x0 -> packed g_x1dh ----------------
__global__ void __launch_bounds__(256, 4) dw_k(
        const float* __restrict__ w, const float* __restrict__ bias) {
    int tid = threadIdx.x;
    int cp = blockIdx.y, b = blockIdx.z;
    int p = blockIdx.x*256 + tid;
    int h = p >> 7, wq = p & 127;
    int c0 = 2*cp;
    const float* ic0 = g_x0 + ((size_t)b*C_ + c0)*HW;
    const float* ic1 = ic0 + HW;
    float a0v = __ldg(bias + c0), a1v = __ldg(bias + c0 + 1);
#pragma unroll
    for (int ky = 0; ky < 3; ky++) {
        int hy = h + ky - 1;
        bool oky = (hy >= 0 && hy < H_);
#pragma unroll
        for (int kx = 0; kx < 3; kx++) {
            int wx = wq + kx - 1;
            bool ok = (oky && wx >= 0 && wx < W_);
            float v0 = ok ? __ldg(ic0 + hy*W_ + wx) : 0.f;
            float v1 = ok ? __ldg(ic1 + hy*W_ + wx) : 0.f;
            a0v += __ldg(w + c0*KK_ + ky*3+kx)*v0;
            a1v += __ldg(w + (c0+1)*KK_ + ky*3+kx)*v1;
        }
    }
    g_x1dh[((size_t)b*32 + cp)*HW + p] = packh2(a0v, a1v);
}

// ---------------- 8: ECA + fold into a3 effective bias ---------------------
__global__ void ecafuse_k(const float* __restrict__ a3w,
                          const float* __restrict__ a3b,
                          const float* __restrict__ w2,
                          const float* __restrict__ b2) {
    __shared__ float eca_s[C_];
    int b = blockIdx.x;
    int co = threadIdx.x;                // 0..575
    if (co < C_) {
        int i = b*C_ + co;
        float sm1 = (co > 0)  ? g_s[i-1] : 0.f;
        float s0  = g_s[i];
        float sp1 = (co < 63) ? g_s[i+1] : 0.f;
        eca_s[co] = (__ldg(w2+0)*sm1 + __ldg(w2+1)*s0 + __ldg(w2+2)*sp1)
                    *(1.f/(float)HW) + __ldg(b2);
    }
    __syncthreads();
    float s = __ldg(a3b + co);
    const float* wr = a3w + (size_t)co*C_;
#pragma unroll 8
    for (int ci = 0; ci < C_; ci++)
        s += __ldg(wr + ci)*eca_s[ci];
    g_beff[b*C9 + co] = s;
}

// ---------------- 9: a3 1x1 (64->576) via fp16 mma + dyn filter + lrelu ----
__global__ void __launch_bounds__(256, 2) a3tc_k() {
    __shared__ __align__(16) float buf[72*TW];   // phase2/3 filt [co72][pxTW]
    unsigned* As2 = (unsigned*)buf;              // phase1: [16][A2PAD]
    unsigned* Bs2 = (unsigned*)buf + 16*A2PAD;   //         [16][BPAD]
    int tid = threadIdx.x, lane = tid & 31, wid = tid >> 5;
    int h = blockIdx.x, b = blockIdx.y;
    int cc = blockIdx.z;
    int co0 = cc*72;
    const unsigned* inb = g_x1dh + (size_t)b*32*HW + h*W_;
    float d[9][4];
#pragma unroll
    for (int n = 0; n < 9; n++)
#pragma unroll
        for (int r = 0; r < 4; r++) d[n][r] = 0.f;

    for (int kc = 0; kc < 2; kc++) {
        __syncthreads();
#pragma unroll
        for (int r = 0; r < 2; r++) {
            int i4 = tid + r*256;                // 0..511
            int row = i4 >> 5, c4 = i4 & 31;
            uint4 v = *(const uint4*)(inb + (size_t)(kc*16+row)*HW + c4*4);
            *(uint4*)(As2 + row*A2PAD + c4*4) = v;
        }
        for (int i = tid; i < 16*72; i += 256) {
            int row = i/72, co = i%72;
            Bs2[row*BPAD + co] = __ldg(g_wt3p + (size_t)(kc*16+row)*C9 + co0 + co);
        }
        __syncthreads();
#pragma unroll
        for (int ks = 0; ks < 2; ks++) {
            int jp0 = ks*8 + (lane & 3);
            int pa = wid*16 + (lane >> 2);
            unsigned a0 = As2[jp0*A2PAD + pa];
            unsigned a1 = As2[jp0*A2PAD + pa + 8];
            unsigned a2 = As2[(jp0+4)*A2PAD + pa];
            unsigned a3 = As2[(jp0+4)*A2PAD + pa + 8];
#pragma unroll
            for (int n = 0; n < 9; n++) {
                unsigned b0 = Bs2[jp0*BPAD + n*8 + (lane >> 2)];
                unsigned b1 = Bs2[(jp0+4)*BPAD + n*8 + (lane >> 2)];
                asm volatile(
                    "mma.sync.aligned.m16n8k16.row.col.f32.f16.f16.f32 "
                    "{%0,%1,%2,%3}, {%4,%5,%6,%7}, {%8,%9}, {%0,%1,%2,%3};"
                    : "+f"(d[n][0]), "+f"(d[n][1]), "+f"(d[n][2]), "+f"(d[n][3])
                    : "r"(a0), "r"(a1), "r"(a2), "r"(a3), "r"(b0), "r"(b1));
            }
        }
    }
    __syncthreads();
    float* filt = buf;
    int px = wid*16 + (lane >> 2);
#pragma unroll
    for (int n = 0; n < 9; n++) {
        int co = n*8 + (lane & 3)*2;
        float b0v = __ldg(g_beff + b*C9 + co0 + co);
        float b1v = __ldg(g_beff + b*C9 + co0 + co + 1);
        filt[co*TW     + px]     = d[n][0] + b0v;
        filt[(co+1)*TW + px]     = d[n][1] + b1v;
        filt[co*TW     + px + 8] = d[n][2] + b0v;
        filt[(co+1)*TW + px + 8] = d[n][3] + b1v;
    }
    __syncthreads();
    // phase 3: apply dyn filter; each thread handles 2 channel PAIRS
    int p  = tid & 127;
    int half = tid >> 7;
    const float* x0b = g_x0 + (size_t)b*C_*HW;
    unsigned* oh = g_outh + (size_t)b*32*HW + h*W_;
#pragma unroll
    for (int cq = 0; cq < 2; cq++) {
        int q = half*2 + cq;
        float o2[2];
#pragma unroll
        for (int e = 0; e < 2; e++) {
            int c8 = q*2 + e;
            int c = cc*8 + c8;
            const float* ic = x0b + (size_t)c*HW;
            float o = 0.f;
#pragma unroll
            for (int ky = 0; ky < 3; ky++) {
                int hy = h + ky - 1;
                bool oy = (hy >= 0 && hy < H_);
                const float* icr = ic + hy*W_;
#pragma unroll
                for (int kx = 0; kx < 3; kx++) {
                    int wx = p + kx - 1;
                    float v = (oy && wx >= 0 && wx < W_) ? __ldg(icr + wx) : 0.f;
                    o += filt[(c8*KK_ + ky*3+kx)*TW + p]*v;
                }
            }
            o2[e] = (o >= 0.f) ? o : 0.2f*o;
        }
        oh[(size_t)(cc*4 + q)*HW + p] = packh2(o2[0], o2[1]);
    }
}

// ---------------- launch ----------------------------------------------------
extern "C" void kernel_launch(void* const* d_in, const int* in_sizes, int n_in,
                              void* d_out, int out_size) {
    const float* x       = (const float*)d_in[0];
    const float* offset  = (const float*)d_in[1];
    const float* conv0_w = (const float*)d_in[2];
    const float* conv0_b = (const float*)d_in[3];
    const float* offm_w  = (const float*)d_in[4];
    const float* offm_b  = (const float*)d_in[5];
    const float* dcn_w   = (const float*)d_in[6];
    const float* dcn_b   = (const float*)d_in[7];
    const float* a0_w    = (const float*)d_in[8];
    const float* a0_b    = (const float*)d_in[9];
    const float* a1_w    = (const float*)d_in[10];
    const float* a1_b    = (const float*)d_in[11];
    const float* a2_w    = (const float*)d_in[12];
    const float* a2_b    = (const float*)d_in[13];
    const float* a3_w    = (const float*)d_in[14];
    const float* a3_b    = (const float*)d_in[15];
    const float* fus_w   = (const float*)d_in[16];
    const float* fus_b   = (const float*)d_in[17];
    float* out = (float*)d_out;

    dim3 gp(HW/256, B_);
    wtrall_k <<<(104832 + 255)/256, 256>>>(dcn_w, a0_w, fus_w, a3_w, offm_w);
    conv0_k  <<<gp, 256>>>(x, conv0_w, conv0_b);
    offmtc_k <<<dim3(H_, B_, 3), 256>>>(offset, offm_b);
    col_k    <<<dim3(HW/256, DG_*KK_, B_), 256>>>();
    dcntc_k  <<<dim3(HW/256, B_), 256>>>(dcn_b);
    conv_a0tc_k<<<dim3(H_/2, B_), 256>>>(a0_b);
    dw_k     <<<dim3(HW/256, 32, B_), 256>>>(a1_w, a1_b);
    ecafuse_k<<<B_, C9>>>(a3_w, a3_b, a2_w, a2_b);
    a3tc_k   <<<dim3(H_, B_, 8), 256>>>();
    conv_fustc_k<<<dim3(H_/2, B_), 256>>>(fus_b, out);
}

// round 17
// speedup vs baseline: 2.9523x; 1.0426x over previous
#include <cuda_runtime.h>
#include <cuda_bf16.h>
#include <cuda_fp16.h>
#include <math.h>

// Problem constants
#define B_   4
#define CIN  32
#define C_   64
#define H_   128
#define W_   128
#define HW   16384
#define DG_  8
#define CPG  8
#define KK_  9
#define OCM  216   // DG*3*K*K
#define C9   576   // C*9
#define C9P  288   // C9/2 packed rows

// ---------------- scratch (device globals; no allocation allowed) ----------
__device__ unsigned g_x1h[B_*32*HW];   // conv0 out, planar half2 pairs [b][g*4+i][p]
__device__ float g_om [B_*OCM*HW];     // offset/mask conv out
__device__ float g_dcn[B_*C_ *HW];     // lrelu(deform conv) fp32 (residual use)
__device__ unsigned g_dch[B_*32*HW];   // same, packed half2 channel pairs
__device__ unsigned g_outh[B_*32*HW];  // dynamic-filter out, packed half2 pairs
__device__ unsigned g_colp[B_*C9P*HW]; // packed half2 im2col [b][jp][p]
__device__ unsigned g_x1dh[B_*32*HW];  // depthwise out, packed half2 pairs
__device__ unsigned g_wtp [C9P*C_];    // dcn weights packed half2 [jp][co]
__device__ unsigned g_wtah[32*KK_*C_]; // a0 weights packed [cipair*9+k][co]
__device__ unsigned g_wtfh[32*KK_*C_]; // fus weights packed [cipair*9+k][co]
__device__ unsigned g_wt3p[32*C9];     // a3 weights packed [cipair][co576]
__device__ unsigned g_wtoh[16*KK_*OCM];// offm weights packed [cipair*9+k][co216]
__device__ float g_beff[B_*C9];        // a3 bias + a3_w . eca
__device__ float g_x0 [B_*C_ *HW];     // a0 conv out
__device__ float g_s  [B_*C_];         // channel SUMS of x0 (zeroed per launch)

__device__ __forceinline__ unsigned packh2(float a, float b) {
    __half2 h = __floats2half2_rn(a, b);
    return *(unsigned*)&h;
}
__device__ __forceinline__ float2 unpackh2(unsigned u) {
    __half2 h = *(__half2*)&u;
    return __half22float2(h);
}

#define APAD 136
#define BPAD 72
#define TW 132
#define A2PAD 136
#define A3PAD 264

// ---------------- 1: conv0 1x1, 32->64 : 4px x 16co, half2-pair out --------
__global__ void __launch_bounds__(256, 2) conv0_k(
        const float* __restrict__ x, const float* __restrict__ w,
        const float* __restrict__ bias) {
    __shared__ __align__(16) float ws[CIN*C_];   // [ci][co]
    int tid = threadIdx.x;
    int quad = tid & 63, cg = tid >> 6;
    for (int i = tid; i < C_*CIN; i += 256) {
        int ci = i >> 6, co = i & 63;
        ws[ci*C_ + co] = w[co*CIN + ci];
    }
    __syncthreads();
    int b = blockIdx.y;
    int p0 = blockIdx.x*256 + quad*4;
    const float* xb = x + (size_t)b*CIN*HW + p0;
    float acc[64];
#pragma unroll
    for (int c = 0; c < 16; c++) {
        float bv = __ldg(bias + cg*16 + c);
        acc[c*4+0] = bv; acc[c*4+1] = bv; acc[c*4+2] = bv; acc[c*4+3] = bv;
    }
    for (int ci = 0; ci < CIN; ci++) {
        float4 v = *(const float4*)(xb + (size_t)ci*HW);
        const float4* w4 = (const float4*)(ws + ci*C_ + cg*16);
#pragma unroll
        for (int q = 0; q < 4; q++) {
            float4 wv = w4[q];
            float wr[4] = {wv.x, wv.y, wv.z, wv.w};
#pragma unroll
            for (int r = 0; r < 4; r++) {
                float wc = wr[r];
                float* a = acc + (q*4+r)*4;
                a[0] += wc*v.x; a[1] += wc*v.y; a[2] += wc*v.z; a[3] += wc*v.w;
            }
        }
    }
    // write half2 pair-planes: plane = g*4+i packs channels (2i, 2i+1) of group g
    // this thread's 16 channels = groups 2cg (local ch 0..7), 2cg+1 (8..15)
#pragma unroll
    for (int gg = 0; gg < 2; gg++) {
        int g = 2*cg + gg;
        unsigned* og = g_x1h + ((size_t)(b*DG_+g)*4)*HW + p0;
#pragma unroll
        for (int i = 0; i < 4; i++) {
            uint4 pk;
            pk.x = packh2(acc[(gg*8+2*i)*4+0], acc[(gg*8+2*i+1)*4+0]);
            pk.y = packh2(acc[(gg*8+2*i)*4+1], acc[(gg*8+2*i+1)*4+1]);
            pk.z = packh2(acc[(gg*8+2*i)*4+2], acc[(gg*8+2*i+1)*4+2]);
            pk.w = packh2(acc[(gg*8+2*i)*4+3], acc[(gg*8+2*i+1)*4+3]);
            *(uint4*)(og + (size_t)i*HW) = pk;
        }
    }
}

// ---------------- all weight transposes/packs + g_s zero in ONE launch -----
__global__ void wtrall_k(const float* __restrict__ dcn_w,
                         const float* __restrict__ a0_w,
                         const float* __restrict__ fus_w,
                         const float* __restrict__ a3_w,
                         const float* __restrict__ offm_w) {
    int i = blockIdx.x*256 + threadIdx.x;
    if (i < B_*C_) g_s[i] = 0.f;        // zero mean accumulators each launch
    if (i < 18432) {
        int jp = i >> 6, co = i & 63;
        int g = jp/36, r = jp%36, k = r/4, ip = r%4;
        int c0 = ip*2;
        g_wtp[i] = packh2(dcn_w[co*C9 + g*72 + c0*9 + k],
                          dcn_w[co*C9 + g*72 + (c0+1)*9 + k]);
    } else if (i < 36864) {
        int t = i - 18432;              // [cp*9+k][co]
        int co = t & 63, j = t >> 6;
        int cp = j/9, k = j%9;
        g_wtah[t] = packh2(a0_w[co*C9 + (2*cp)*KK_ + k],
                           a0_w[co*C9 + (2*cp+1)*KK_ + k]);
    } else if (i < 55296) {
        int t = i - 36864;
        int co = t & 63, j = t >> 6;
        int cp = j/9, k = j%9;
        g_wtfh[t] = packh2(fus_w[co*C9 + (2*cp)*KK_ + k],
                           fus_w[co*C9 + (2*cp+1)*KK_ + k]);
    } else if (i < 73728) {
        int t = i - 55296;              // [cp][co576]
        int co = t % C9, cp = t / C9;
        g_wt3p[t] = packh2(a3_w[co*C_ + 2*cp], a3_w[co*C_ + 2*cp+1]);
    } else if (i < 104832) {
        int t = i - 73728;              // [cp*9+k][co216]
        int co = t % OCM, j = t / OCM;
        int cp = j/9, k = j%9;
        g_wtoh[t] = packh2(offm_w[(co*CIN + 2*cp)*KK_ + k],
                           offm_w[(co*CIN + 2*cp+1)*KK_ + k]);
    }
}

// ---------------- 2: offm conv 3x3 32->216 via fp16 m16n8k16 ---------------
__global__ void __launch_bounds__(256, 2) offmtc_k(
        const float* __restrict__ in, const float* __restrict__ bias) {
    __shared__ __align__(16) unsigned raw2[8*3*TW];   // [cipair8][row3][col132]
    __shared__ __align__(16) unsigned Bs2[9*8*BPAD];  // [k9][cipair8][co72]
    int tid = threadIdx.x, lane = tid & 31, wid = tid >> 5;
    int h = blockIdx.x, b = blockIdx.y;
    int co0 = blockIdx.z*72;
    const float* ib = in + (size_t)b*CIN*HW;
    float d[9][4];
#pragma unroll
    for (int n = 0; n < 9; n++)
#pragma unroll
        for (int r = 0; r < 4; r++) d[n][r] = 0.f;

    for (int cc = 0; cc < 2; cc++) {
        __syncthreads();
        for (int i = tid; i < 8*3*TW; i += 256) {
            int ip = i/(3*TW);
            int r  = (i/TW)%3;
            int t  = i%TW;
            int row = h + r - 1, col = t - 1;
            unsigned v = 0u;
            if (t < 130 && row >= 0 && row < H_ && col >= 0 && col < W_) {
                const float* p0 = ib + (size_t)(2*(cc*8+ip))*HW + row*W_ + col;
                v = packh2(__ldg(p0), __ldg(p0 + HW));
            }
            raw2[i] = v;
        }
        for (int i = tid; i < 9*8*72; i += 256) {
            int ks = i/(8*72);
            int ip = (i/72)%8;
            int co = i%72;
            Bs2[(ks*8+ip)*BPAD + co] =
                __ldg(g_wtoh + (size_t)((cc*8+ip)*KK_ + ks)*OCM + co0 + co);
        }
        __syncthreads();
#pragma unroll
        for (int ks = 0; ks < KK_; ks++) {
            int ky = ks/3, kx = ks%3;
            int abase = ((lane&3)*3 + ky)*TW + wid*16 + (lane>>2) + kx;
            unsigned a0 = raw2[abase];
            unsigned a1 = raw2[abase + 8];
            unsigned a2 = raw2[abase + 4*3*TW];
            unsigned a3 = raw2[abase + 4*3*TW + 8];
#pragma unroll
            for (int n = 0; n < 9; n++) {
                unsigned b0 = Bs2[(ks*8 + (lane&3))*BPAD + n*8 + (lane>>2)];
                unsigned b1 = Bs2[(ks*8 + (lane&3)+4)*BPAD + n*8 + (lane>>2)];
                asm volatile(
                    "mma.sync.aligned.m16n8k16.row.col.f32.f16.f16.f32 "
                    "{%0,%1,%2,%3}, {%4,%5,%6,%7}, {%8,%9}, {%0,%1,%2,%3};"
                    : "+f"(d[n][0]), "+f"(d[n][1]), "+f"(d[n][2]), "+f"(d[n][3])
                    : "r"(a0), "r"(a1), "r"(a2), "r"(a3), "r"(b0), "r"(b1));
            }
        }
    }
    int prow = h*W_ + wid*16 + (lane >> 2);
    float* ob = g_om + (size_t)b*OCM*HW;
#pragma unroll
    for (int n = 0; n < 9; n++) {
        int co = co0 + n*8 + (lane & 3)*2;
        float b0v = __ldg(bias + co), b1v = __ldg(bias + co + 1);
        ob[(size_t)co*HW     + prow]     = d[n][0] + b0v;
        ob[(size_t)(co+1)*HW + prow]     = d[n][1] + b1v;
        ob[(size_t)co*HW     + prow + 8] = d[n][2] + b0v;
        ob[(size_t)(co+1)*HW + prow + 8] = d[n][3] + b1v;
    }
}

// ---------------- 3: deform im2col (half2-pair gather) -> packed half2 -----
__global__ void __launch_bounds__(256, 2) col_k() {
    int tid = threadIdx.x;
    int p = blockIdx.x*256 + tid;
    int gk = blockIdx.y;                 // g*9+k, 0..71
    int g = gk/9, k = gk%9;
    int b = blockIdx.z;
    int h = p >> 7, wq = p & 127;
    const float* omb = g_om + (size_t)b*OCM*HW;
    float dy = omb[(       g*9+k)*HW + p];
    float dx = omb[( 72 +  g*9+k)*HW + p];
    float mk = omb[(144 +  g*9+k)*HW + p];
    mk = 1.f/(1.f + expf(-mk));
    float py = dy + (float)(k/3) + (float)h - 1.f;
    float px = dx + (float)(k%3) + (float)wq - 1.f;
    float fy = floorf(py), fx = floorf(px);
    int y0 = (int)fy, x0 = (int)fx;
    float wy = py - fy, wx = px - fx;
    float w00 = (1.f-wy)*(1.f-wx)*mk;
    float w01 = (1.f-wy)*wx*mk;
    float w10 = wy*(1.f-wx)*mk;
    float w11 = wy*wx*mk;
    bool iy0 = (y0 >= 0 && y0 < H_);
    bool iy1 = (y0+1 >= 0 && y0+1 < H_);
    bool ix0 = (x0 >= 0 && x0 < W_);
    bool ix1 = (x0+1 >= 0 && x0+1 < W_);
    int i00 = y0*W_ + x0;
    const unsigned* xg = g_x1h + (size_t)(b*DG_+g)*4*HW;
    float s[CPG] = {0.f,0.f,0.f,0.f,0.f,0.f,0.f,0.f};
#define GATHER(idx, wgt) { \
        _Pragma("unroll") \
        for (int i = 0; i < 4; i++) { \
            float2 f = unpackh2(__ldg(xg + (size_t)i*HW + (idx))); \
            s[2*i]   += (wgt)*f.x; \
            s[2*i+1] += (wgt)*f.y; \
        } }
    if (iy0 && ix0) GATHER(i00,      w00);
    if (iy0 && ix1) GATHER(i00+1,    w01);
    if (iy1 && ix0) GATHER(i00+W_,   w10);
    if (iy1 && ix1) GATHER(i00+W_+1, w11);
#undef GATHER
    unsigned* cb = g_colp + (size_t)b*C9P*HW + (size_t)(g*36 + k*4)*HW + p;
#pragma unroll
    for (int i = 0; i < 4; i++)
        cb[(size_t)i*HW] = packh2(s[2*i], s[2*i+1]);
}

// ---------------- 4: dcn GEMM fp16 m16n8k16, 256 px per CTA ----------------
__global__ void __launch_bounds__(256, 2) dcntc_k(const float* __restrict__ bias) {
    __shared__ __align__(16) unsigned As2[16*A3PAD];  // [jp][px256]
    __shared__ __align__(16) unsigned Bs2[16*BPAD];   // [jp][co]
    int tid = threadIdx.x, lane = tid & 31, wid = tid >> 5;
    int b = blockIdx.y;
    int p0 = blockIdx.x*256;
    const unsigned* cb = g_colp + (size_t)b*C9P*HW + p0;
    float d[2][8][4];
#pragma unroll
    for (int s = 0; s < 2; s++)
#pragma unroll
        for (int n = 0; n < 8; n++)
#pragma unroll
            for (int r = 0; r < 4; r++) d[s][n][r] = 0.f;

    for (int kc = 0; kc < 18; kc++) {
        __syncthreads();
#pragma unroll
        for (int r = 0; r < 4; r++) {
            int i4 = tid + r*256;               // 0..1023
            int row = i4 >> 6, c4 = i4 & 63;
            uint4 v = *(const uint4*)(cb + (size_t)(kc*16+row)*HW + c4*4);
            *(uint4*)(As2 + row*A3PAD + c4*4) = v;
        }
        {
            int row = tid >> 4, c4 = tid & 15;
            uint4 v = *(const uint4*)(g_wtp + (size_t)(kc*16+row)*C_ + c4*4);
            *(uint4*)(Bs2 + row*BPAD + c4*4) = v;
        }
        __syncthreads();
#pragma unroll
        for (int ks = 0; ks < 2; ks++) {
            int jp0 = ks*8 + (lane & 3);
            unsigned af[2][4];
#pragma unroll
            for (int s = 0; s < 2; s++) {
                int pa = wid*32 + s*16 + (lane >> 2);
                af[s][0] = As2[jp0*A3PAD + pa];
                af[s][1] = As2[jp0*A3PAD + pa + 8];
                af[s][2] = As2[(jp0+4)*A3PAD + pa];
                af[s][3] = As2[(jp0+4)*A3PAD + pa + 8];
            }
#pragma unroll
            for (int n = 0; n < 8; n++) {
                unsigned b0 = Bs2[jp0*BPAD + n*8 + (lane >> 2)];
                unsigned b1 = Bs2[(jp0+4)*BPAD + n*8 + (lane >> 2)];
#pragma unroll
                for (int s = 0; s < 2; s++) {
                    asm volatile(
                        "mma.sync.aligned.m16n8k16.row.col.f32.f16.f16.f32 "
                        "{%0,%1,%2,%3}, {%4,%5,%6,%7}, {%8,%9}, {%0,%1,%2,%3};"
                        : "+f"(d[s][n][0]), "+f"(d[s][n][1]),
                          "+f"(d[s][n][2]), "+f"(d[s][n][3])
                        : "r"(af[s][0]), "r"(af[s][1]), "r"(af[s][2]), "r"(af[s][3]),
                          "r"(b0), "r"(b1));
                }
            }
        }
    }
    float* ob = g_dcn + (size_t)b*C_*HW;
    unsigned* oh = g_dch + (size_t)b*32*HW;
#pragma unroll
    for (int s = 0; s < 2; s++) {
        int prow = p0 + wid*32 + s*16 + (lane >> 2);
#pragma unroll
        for (int n = 0; n < 8; n++) {
            int co = n*8 + (lane & 3)*2;
            int cp = n*4 + (lane & 3);
            float b0v = __ldg(bias + co), b1v = __ldg(bias + co + 1);
            float v0 = d[s][n][0] + b0v, v1 = d[s][n][1] + b1v;
            float v2 = d[s][n][2] + b0v, v3 = d[s][n][3] + b1v;
            v0 = (v0 >= 0.f) ? v0 : 0.2f*v0;
            v1 = (v1 >= 0.f) ? v1 : 0.2f*v1;
            v2 = (v2 >= 0.f) ? v2 : 0.2f*v2;
            v3 = (v3 >= 0.f) ? v3 : 0.2f*v3;
            ob[(size_t)co*HW     + prow]     = v0;
            ob[(size_t)(co+1)*HW + prow]     = v1;
            ob[(size_t)co*HW     + prow + 8] = v2;
            ob[(size_t)(co+1)*HW + prow + 8] = v3;
            oh[(size_t)cp*HW + prow]     = packh2(v0, v1);
            oh[(size_t)cp*HW + prow + 8] = packh2(v2, v3);
        }
    }
}

// ---------------- 5: conv3x3 64->64 fp16 mma, 2 rows/CTA (+opt mean) -------
template <int FUSE, int MEAN>
__device__ __forceinline__ void conv3tc_f16(
        const unsigned* __restrict__ inh, const unsigned* __restrict__ wth,
        const float* __restrict__ bias, const float* __restrict__ pre,
        float* __restrict__ outp, int b) {
    __shared__ __align__(16) unsigned raw2[8*4*TW];   // [pair8][row4][col132]
    __shared__ __align__(16) unsigned Bs2[9*8*BPAD];  // [k9][pair8][co]
    __shared__ float red[C_];
    int tid = threadIdx.x, lane = tid & 31, wid = tid >> 5;
    int h0 = blockIdx.x*2;
    if (MEAN && tid < C_) red[tid] = 0.f;
    float d[2][8][4];
#pragma unroll
    for (int hr = 0; hr < 2; hr++)
#pragma unroll
        for (int n = 0; n < 8; n++)
#pragma unroll
            for (int r = 0; r < 4; r++) d[hr][n][r] = 0.f;

    for (int cc = 0; cc < 4; cc++) {
        __syncthreads();
        for (int i = tid; i < 8*4*TW; i += 256) {
            int ip = i/(4*TW);
            int r  = (i/TW)&3;
            int t  = i%TW;
            int row = h0 + r - 1, col = t - 1;
            unsigned v = 0u;
            if (t < 130 && row >= 0 && row < H_ && col >= 0 && col < W_)
                v = __ldg(inh + (size_t)(cc*8+ip)*HW + row*W_ + col);
            raw2[i] = v;
        }
        for (int i = tid; i < 9*8*C_; i += 256) {
            int ks = i/(8*C_);
            int ip = (i/C_)%8;
            int co = i & 63;
            Bs2[(ks*8+ip)*BPAD + co] =
                __ldg(wth + (size_t)((cc*8+ip)*KK_ + ks)*C_ + co);
        }
        __syncthreads();
#pragma unroll
        for (int ks = 0; ks < KK_; ks++) {
            int ky = ks/3, kx = ks%3;
            unsigned b0v[8], b1v[8];
#pragma unroll
            for (int n = 0; n < 8; n++) {
                b0v[n] = Bs2[(ks*8 + (lane&3))*BPAD + n*8 + (lane>>2)];
                b1v[n] = Bs2[(ks*8 + (lane&3)+4)*BPAD + n*8 + (lane>>2)];
            }
#pragma unroll
            for (int hr = 0; hr < 2; hr++) {
                int abase = ((lane&3)*4 + hr + ky)*TW + wid*16 + (lane>>2) + kx;
                unsigned a0 = raw2[abase];
                unsigned a1 = raw2[abase + 8];
                unsigned a2 = raw2[abase + 4*4*TW];
                unsigned a3 = raw2[abase + 4*4*TW + 8];
#pragma unroll
                for (int n = 0; n < 8; n++) {
                    asm volatile(
                        "mma.sync.aligned.m16n8k16.row.col.f32.f16.f16.f32 "
                        "{%0,%1,%2,%3}, {%4,%5,%6,%7}, {%8,%9}, {%0,%1,%2,%3};"
                        : "+f"(d[hr][n][0]), "+f"(d[hr][n][1]),
                          "+f"(d[hr][n][2]), "+f"(d[hr][n][3])
                        : "r"(a0), "r"(a1), "r"(a2), "r"(a3),
                          "r"(b0v[n]), "r"(b1v[n]));
                }
            }
        }
    }
#pragma unroll
    for (int hr = 0; hr < 2; hr++) {
        int prow = (h0+hr)*W_ + wid*16 + (lane >> 2);
#pragma unroll
        for (int n = 0; n < 8; n++) {
            int co = n*8 + (lane & 3)*2;
            float b0v = __ldg(bias + co), b1v = __ldg(bias + co + 1);
            float v0 = d[hr][n][0] + b0v, v1 = d[hr][n][1] + b1v;
            float v2 = d[hr][n][2] + b0v, v3 = d[hr][n][3] + b1v;
            if (FUSE) {
                v0 += 2.f*__ldg(pre + (size_t)co*HW     + prow);
                v1 += 2.f*__ldg(pre + (size_t)(co+1)*HW + prow);
                v2 += 2.f*__ldg(pre + (size_t)co*HW     + prow + 8);
                v3 += 2.f*__ldg(pre + (size_t)(co+1)*HW + prow + 8);
            }
            outp[(size_t)co*HW     + prow]     = v0;
            outp[(size_t)(co+1)*HW + prow]     = v1;
            outp[(size_t)co*HW     + prow + 8] = v2;
            outp[(size_t)(co+1)*HW + prow + 8] = v3;
            if (MEAN) {
                atomicAdd(&red[co],   v0 + v2);
                atomicAdd(&red[co+1], v1 + v3);
            }
        }
    }
    if (MEAN) {
        __syncthreads();
        if (tid < C_) atomicAdd(&g_s[b*C_ + tid], red[tid]);
    }
}

__global__ void __launch_bounds__(256, 2) conv_a0tc_k(const float* __restrict__ bias) {
    int b = blockIdx.y;
    conv3tc_f16<0,1>(g_dch + (size_t)b*32*HW, g_wtah, bias, nullptr,
                     g_x0 + (size_t)b*C_*HW, b);
}

__global__ void __launch_bounds__(256, 2) conv_fustc_k(
        const float* __restrict__ bias, float* __restrict__ out) {
    int b = blockIdx.y;
    conv3tc_f16<1,0>(g_outh + (size_t)b*32*HW, g_wtfh, bias,
                     g_dcn + (size_t)b*C_*HW, out + (size_t)b*C_*HW, b);
}

// ---------------- 6: depthwise 3x3 on g_x0 -> packed g_x1dh ----------------
__global__ void __launch_bounds__(256, 4) dw_k(
        const float* __restrict__ w, const float* __restrict__ bias) {
    int tid = threadIdx.x;
    int cp = blockIdx.y, b = blockIdx.z;
    int p = blockIdx.x*256 + tid;
    int h = p >> 7, wq = p & 127;
    int c0 = 2*cp;
    const float* ic0 = g_x0 + ((size_t)b*C_ + c0)*HW;
    const float* ic1 = ic0 + HW;
    float a0v = __ldg(bias + c0), a1v = __ldg(bias + c0 + 1);
#pragma unroll
    for (int ky = 0; ky < 3; ky++) {
        int hy = h + ky - 1;
        bool oky = (hy >= 0 && hy < H_);
#pragma unroll
        for (int kx = 0; kx < 3; kx++) {
            int wx = wq + kx - 1;
            bool ok = (oky && wx >= 0 && wx < W_);
            float v0 = ok ? __ldg(ic0 + hy*W_ + wx) : 0.f;
            float v1 = ok ? __ldg(ic1 + hy*W_ + wx) : 0.f;
            a0v += __ldg(w + c0*KK_ + ky*3+kx)*v0;
            a1v += __ldg(w + (c0+1)*KK_ + ky*3+kx)*v1;
        }
    }
    g_x1dh[((size_t)b*32 + cp)*HW + p] = packh2(a0v, a1v);
}

// ---------------- 8: ECA + fold into a3 effective bias ---------------------
__global__ void ecafuse_k(const float* __restrict__ a3w,
                          const float* __restrict__ a3b,
                          const float* __restrict__ w2,
                          const float* __restrict__ b2) {
    __shared__ float eca_s[C_];
    int b = blockIdx.x;
    int co = threadIdx.x;                // 0..575
    if (co < C_) {
        int i = b*C_ + co;
        float sm1 = (co > 0)  ? g_s[i-1] : 0.f;
        float s0  = g_s[i];
        float sp1 = (co < 63) ? g_s[i+1] : 0.f;
        eca_s[co] = (__ldg(w2+0)*sm1 + __ldg(w2+1)*s0 + __ldg(w2+2)*sp1)
                    *(1.f/(float)HW) + __ldg(b2);
    }
    __syncthreads();
    float s = __ldg(a3b + co);
    const float* wr = a3w + (size_t)co*C_;
#pragma unroll 8
    for (int ci = 0; ci < C_; ci++)
        s += __ldg(wr + ci)*eca_s[ci];
    g_beff[b*C9 + co] = s;
}

// ---------------- 9: a3 1x1 (64->576) via fp16 mma + dyn filter + lrelu ----
__global__ void __launch_bounds__(256, 2) a3tc_k() {
    __shared__ __align__(16) float buf[72*TW];   // phase2/3 filt [co72][pxTW]
    unsigned* As2 = (unsigned*)buf;              // phase1: [16][A2PAD]
    unsigned* Bs2 = (unsigned*)buf + 16*A2PAD;   //         [16][BPAD]
    int tid = threadIdx.x, lane = tid & 31, wid = tid >> 5;
    int h = blockIdx.x, b = blockIdx.y;
    int cc = blockIdx.z;
    int co0 = cc*72;
    const unsigned* inb = g_x1dh + (size_t)b*32*HW + h*W_;
    float d[9][4];
#pragma unroll
    for (int n = 0; n < 9; n++)
#pragma unroll
        for (int r = 0; r < 4; r++) d[n][r] = 0.f;

    for (int kc = 0; kc < 2; kc++) {
        __syncthreads();
#pragma unroll
        for (int r = 0; r < 2; r++) {
            int i4 = tid + r*256;                // 0..511
            int row = i4 >> 5, c4 = i4 & 31;
            uint4 v = *(const uint4*)(inb + (size_t)(kc*16+row)*HW + c4*4);
            *(uint4*)(As2 + row*A2PAD + c4*4) = v;
        }
        for (int i = tid; i < 16*72; i += 256) {
            int row = i/72, co = i%72;
            Bs2[row*BPAD + co] = __ldg(g_wt3p + (size_t)(kc*16+row)*C9 + co0 + co);
        }
        __syncthreads();
#pragma unroll
        for (int ks = 0; ks < 2; ks++) {
            int jp0 = ks*8 + (lane & 3);
            int pa = wid*16 + (lane >> 2);
            unsigned a0 = As2[jp0*A2PAD + pa];
            unsigned a1 = As2[jp0*A2PAD + pa + 8];
            unsigned a2 = As2[(jp0+4)*A2PAD + pa];
            unsigned a3 = As2[(jp0+4)*A2PAD + pa + 8];
#pragma unroll
            for (int n = 0; n < 9; n++) {
                unsigned b0 = Bs2[jp0*BPAD + n*8 + (lane >> 2)];
                unsigned b1 = Bs2[(jp0+4)*BPAD + n*8 + (lane >> 2)];
                asm volatile(
                    "mma.sync.aligned.m16n8k16.row.col.f32.f16.f16.f32 "
                    "{%0,%1,%2,%3}, {%4,%5,%6,%7}, {%8,%9}, {%0,%1,%2,%3};"
                    : "+f"(d[n][0]), "+f"(d[n][1]), "+f"(d[n][2]), "+f"(d[n][3])
                    : "r"(a0), "r"(a1), "r"(a2), "r"(a3), "r"(b0), "r"(b1));
            }
        }
    }
    __syncthreads();
    float* filt = buf;
    int px = wid*16 + (lane >> 2);
#pragma unroll
    for (int n = 0; n < 9; n++) {
        int co = n*8 + (lane & 3)*2;
        float b0v = __ldg(g_beff + b*C9 + co0 + co);
        float b1v = __ldg(g_beff + b*C9 + co0 + co + 1);
        filt[co*TW     + px]     = d[n][0] + b0v;
        filt[(co+1)*TW + px]     = d[n][1] + b1v;
        filt[co*TW     + px + 8] = d[n][2] + b0v;
        filt[(co+1)*TW + px + 8] = d[n][3] + b1v;
    }
    __syncthreads();
    // phase 3: apply dyn filter; each thread handles 2 channel PAIRS
    int p  = tid & 127;
    int half = tid >> 7;
    const float* x0b = g_x0 + (size_t)b*C_*HW;
    unsigned* oh = g_outh + (size_t)b*32*HW + h*W_;
#pragma unroll
    for (int cq = 0; cq < 2; cq++) {
        int q = half*2 + cq;
        float o2[2];
#pragma unroll
        for (int e = 0; e < 2; e++) {
            int c8 = q*2 + e;
            int c = cc*8 + c8;
            const float* ic = x0b + (size_t)c*HW;
            float o = 0.f;
#pragma unroll
            for (int ky = 0; ky < 3; ky++) {
                int hy = h + ky - 1;
                bool oy = (hy >= 0 && hy < H_);
                const float* icr = ic + hy*W_;
#pragma unroll
                for (int kx = 0; kx < 3; kx++) {
                    int wx = p + kx - 1;
                    float v = (oy && wx >= 0 && wx < W_) ? __ldg(icr + wx) : 0.f;
                    o += filt[(c8*KK_ + ky*3+kx)*TW + p]*v;
                }
            }
            o2[e] = (o >= 0.f) ? o : 0.2f*o;
        }
        oh[(size_t)(cc*4 + q)*HW + p] = packh2(o2[0], o2[1]);
    }
}

// ---------------- launch ----------------------------------------------------
extern "C" void kernel_launch(void* const* d_in, const int* in_sizes, int n_in,
                              void* d_out, int out_size) {
    const float* x       = (const float*)d_in[0];
    const float* offset  = (const float*)d_in[1];
    const float* conv0_w = (const float*)d_in[2];
    const float* conv0_b = (const float*)d_in[3];
    const float* offm_w  = (const float*)d_in[4];
    const float* offm_b  = (const float*)d_in[5];
    const float* dcn_w   = (const float*)d_in[6];
    const float* dcn_b   = (const float*)d_in[7];
    const float* a0_w    = (const float*)d_in[8];
    const float* a0_b    = (const float*)d_in[9];
    const float* a1_w    = (const float*)d_in[10];
    const float* a1_b    = (const float*)d_in[11];
    const float* a2_w    = (const float*)d_in[12];
    const float* a2_b    = (const float*)d_in[13];
    const float* a3_w    = (const float*)d_in[14];
    const float* a3_b    = (const float*)d_in[15];
    const float* fus_w   = (const float*)d_in[16];
    const float* fus_b   = (const float*)d_in[17];
    float* out = (float*)d_out;

    dim3 gp(HW/256, B_);
    wtrall_k <<<(104832 + 255)/256, 256>>>(dcn_w, a0_w, fus_w, a3_w, offm_w);
    conv0_k  <<<gp, 256>>>(x, conv0_w, conv0_b);
    offmtc_k <<<dim3(H_, B_, 3), 256>>>(offset, offm_b);
    col_k    <<<dim3(HW/256, DG_*KK_, B_), 256>>>();
    dcntc_k  <<<dim3(HW/256, B_), 256>>>(dcn_b);
    conv_a0tc_k<<<dim3(H_/2, B_), 256>>>(a0_b);
    dw_k     <<<dim3(HW/256, 32, B_), 256>>>(a1_w, a1_b);
    ecafuse_k<<<B_, C9>>>(a3_w, a3_b, a2_w, a2_b);
    a3tc_k   <<<dim3(H_, B_, 8), 256>>>();
    conv_fustc_k<<<dim3(H_/2, B_), 256>>>(fus_b, out);
}